// round 1
// baseline (speedup 1.0000x reference)
#include <cuda_runtime.h>
#include <math.h>

#define EPS 1e-5f
#define NPATCH 64
#define CCH 256
#define HS 44
#define NB (NPATCH*HS)          // 2816 blocks per axial
#define PLANE (HS*HS)           // 1936
#define IMGSZ (CCH*PLANE)       // 495616 floats per patch

// ---------------- static device scratch (no runtime alloc allowed) ----------------
__device__ float g_p [NPATCH*IMGSZ];   // patchified input (also the residual)
__device__ float g_t1[NPATCH*IMGSZ];   // after height axial
__device__ float g_t2[NPATCH*IMGSZ];   // after width axial
__device__ float g_WT[2][CCH*512];     // folded qkv weights, [ax][c*512+o]
__device__ float g_qkvb[2][512];       // folded qkv bias
__device__ float g_simA[2][12];        // sim scales: [qk g0..3, qr, kr] (0.1 folded)
__device__ float g_simBsum[2][4];      // summed sim shifts per group
__device__ float g_outA_sv[2][256];
__device__ float g_outA_sve[2][256];   // 0.1 folded
__device__ float g_outB[2][256];
__device__ float g_convWT[CCH*9*CCH];  // [((ci*3+ky)*3+kx)*256 + co]

// ---------------- prep: fold all BNs, transpose weights ----------------
__global__ void prep_kernel(const float* __restrict__ h_qkv_w, const float* __restrict__ h_bn_qkv,
                            const float* __restrict__ h_bn_sim, const float* __restrict__ h_bn_out,
                            const float* __restrict__ w_qkv_w, const float* __restrict__ w_bn_qkv,
                            const float* __restrict__ w_bn_sim, const float* __restrict__ w_bn_out,
                            const float* __restrict__ conv_w)
{
    int idx = blockIdx.x * blockDim.x + threadIdx.x;

    // conv weight transpose: [co][ci][ky][kx] -> [ci,ky,kx][co]
    if (idx < 256*256*9) {
        int co  = idx / 2304;
        int rem = idx - co*2304;     // ci*9 + tap
        g_convWT[rem*256 + co] = conv_w[idx];
    }
    // qkv fold: 2 axials * 256c * 512o
    if (idx < 2*131072) {
        int ax = idx >> 17;
        int r  = idx & 131071;
        int o  = r & 511;
        int c  = r >> 9;
        const float* bn = ax ? w_bn_qkv : h_bn_qkv;   // (4,512): g,b,m,v
        const float* W  = ax ? w_qkv_w : h_qkv_w;     // (512,256)
        float s = bn[o] * rsqrtf(bn[1536+o] + EPS);
        g_WT[ax][c*512 + o] = W[o*256 + c] * s;
        if (c == 0) g_qkvb[ax][o] = bn[512+o] - bn[1024+o]*s;
    }
    // sim coefficients: 2 axials * 4 groups
    if (idx < 8) {
        int ax = idx >> 2, g = idx & 3;
        const float* bs = ax ? w_bn_sim : h_bn_sim;   // (4,12)
        float shsum = 0.f;
        #pragma unroll
        for (int p = 0; p < 3; p++) {
            int ch = p*4 + g;
            float s = bs[ch] * rsqrtf(bs[36+ch] + EPS);
            g_simA[ax][p*4+g] = (p == 0 ? 1.f : 0.1f) * s;
            shsum += bs[12+ch] - bs[24+ch]*s;
        }
        g_simBsum[ax][g] = shsum;
    }
    // out coefficients: 2 axials * 256 channels
    if (idx < 512) {
        int ax = idx >> 8, cc = idx & 255;
        const float* bo = ax ? w_bn_out : h_bn_out;   // (4,512)
        int o1 = 2*cc, o2 = 2*cc + 1;
        float s1 = bo[o1] * rsqrtf(bo[1536+o1] + EPS);
        float s2 = bo[o2] * rsqrtf(bo[1536+o2] + EPS);
        g_outA_sv[ax][cc]  = s1;
        g_outA_sve[ax][cc] = 0.1f * s2;
        g_outB[ax][cc] = (bo[512+o1] - bo[1024+o1]*s1) + (bo[512+o2] - bo[1024+o2]*s2);
    }
}

// ---------------- patchify ----------------
__global__ void patchify_kernel(const float* __restrict__ x)
{
    int idx = blockIdx.x * blockDim.x + threadIdx.x;
    if (idx >= NPATCH*IMGSZ) return;
    int xq = idx % 44;
    int y  = (idx / 44) % 44;
    int c  = (idx / 1936) % 256;
    int np = idx / IMGSZ;
    int b  = np >> 2, i2 = (np >> 1) & 1, j2 = np & 1;
    g_p[idx] = x[(((size_t)(b*256 + c))*88 + (i2*44 + y))*88 + (j2*44 + xq)];
}

// ---------------- fused axial attention ----------------
// smem: xs[256*44] | qkv[512*44] | rel[128*87] | sim[4*44*44]  = 210688 bytes
#define AX_SMEM ((11264 + 22528 + 11136 + 7744) * 4)

template<bool WIDTH>
__global__ void __launch_bounds__(256, 1) axial_kernel(const float* __restrict__ rel, int ax)
{
    const float* in  = ax ? g_t1 : g_p;
    float*       out = ax ? g_t2 : g_t1;

    extern __shared__ float sm[];
    float* xs   = sm;                // [256][44]
    float* qkvS = sm + 11264;        // [512][44]
    float* relS = sm + 11264 + 22528;// [128][87]
    float* simS = relS + 11136;      // [4][44][44]

    const int t  = threadIdx.x;
    const int bb = blockIdx.x;
    const int n  = bb / 44;
    const int s  = bb - n*44;
    const float* base = in + (size_t)n * IMGSZ;

    // load x slice: thread t = channel t
    {
        float* dst = xs + t*44;
        if (WIDTH) {
            const float* src = base + (t*44 + s)*44;
            #pragma unroll
            for (int i = 0; i < 44; i++) dst[i] = src[i];
        } else {
            const float* src = base + t*1936 + s;
            #pragma unroll
            for (int i = 0; i < 44; i++) dst[i] = src[i*44];
        }
    }
    for (int i = t; i < 11136; i += 256) relS[i] = rel[i];
    __syncthreads();

    // qkv GEMM: thread computes outputs o0=2t, o0+1 for all 44 positions
    {
        float acc0[44], acc1[44];
        #pragma unroll
        for (int i = 0; i < 44; i++) { acc0[i] = 0.f; acc1[i] = 0.f; }
        const float* WT = g_WT[ax];
        const int o0 = 2*t;
        for (int c = 0; c < 256; c++) {
            float2 w = *(const float2*)(WT + c*512 + o0);
            const float4* xr = (const float4*)(xs + c*44);
            #pragma unroll
            for (int q = 0; q < 11; q++) {
                float4 xv = xr[q];
                acc0[4*q+0] = fmaf(w.x, xv.x, acc0[4*q+0]); acc1[4*q+0] = fmaf(w.y, xv.x, acc1[4*q+0]);
                acc0[4*q+1] = fmaf(w.x, xv.y, acc0[4*q+1]); acc1[4*q+1] = fmaf(w.y, xv.y, acc1[4*q+1]);
                acc0[4*q+2] = fmaf(w.x, xv.z, acc0[4*q+2]); acc1[4*q+2] = fmaf(w.y, xv.z, acc1[4*q+2]);
                acc0[4*q+3] = fmaf(w.x, xv.w, acc0[4*q+3]); acc1[4*q+3] = fmaf(w.y, xv.w, acc1[4*q+3]);
            }
        }
        float b0 = g_qkvb[ax][o0], b1 = g_qkvb[ax][o0+1];
        float* d0 = qkvS + o0*44;
        float* d1 = d0 + 44;
        #pragma unroll
        for (int i = 0; i < 44; i++) { d0[i] = acc0[i] + b0; d1[i] = acc1[i] + b1; }
    }
    __syncthreads();

    // sim = bnfold(qk) + bnfold(0.1*qr) + bnfold(0.1*kr)
    {
        for (int e = t; e < 7744; e += 256) {
            int g = e / 1936;
            int r = e - g*1936;
            int i = r / 44;
            int j = r - i*44;
            const float* qp = qkvS + (g*128)*44 + i;
            const float* kp = qkvS + (g*128 + 32)*44 + j;
            const float* rq = relS + (i - j + 43);
            const float* rk = relS + 32*87 + (j - i + 43);
            float qk = 0.f, qr = 0.f, kr = 0.f;
            #pragma unroll
            for (int c = 0; c < 32; c++) {
                float qv = qp[c*44];
                float kv = kp[c*44];
                qk = fmaf(qv, kv, qk);
                qr = fmaf(qv, rq[c*87], qr);
                kr = fmaf(kv, rk[c*87], kr);
            }
            simS[e] = g_simA[ax][g]*qk + g_simA[ax][4+g]*qr + g_simA[ax][8+g]*kr + g_simBsum[ax][g];
        }
    }
    __syncthreads();

    // softmax over j for each (g,i)
    if (t < 176) {
        int g = t / 44, i = t - g*44;
        float* row = simS + g*1936 + i*44;
        float mx = -1e30f;
        #pragma unroll
        for (int j = 0; j < 44; j++) mx = fmaxf(mx, row[j]);
        float sum = 0.f;
        #pragma unroll
        for (int j = 0; j < 44; j++) { float e = __expf(row[j] - mx); row[j] = e; sum += e; }
        float inv = 1.f / sum;
        #pragma unroll
        for (int j = 0; j < 44; j++) row[j] *= inv;
    }
    __syncthreads();

    // output: thread t = global channel cc; v row cached in registers
    {
        const int g = t >> 6, c = t & 63;
        float vreg[44];
        const float4* vp = (const float4*)(qkvS + (g*128 + 64 + c)*44);
        #pragma unroll
        for (int q = 0; q < 11; q++) {
            float4 v4 = vp[q];
            vreg[4*q+0] = v4.x; vreg[4*q+1] = v4.y; vreg[4*q+2] = v4.z; vreg[4*q+3] = v4.w;
        }
        const float* rv = relS + (64 + c)*87;
        const float aSV  = g_outA_sv[ax][t];
        const float aSVE = g_outA_sve[ax][t];
        const float bO   = g_outB[ax][t];
        const size_t obase = (size_t)(n*256 + t) * 1936;
        for (int i = 0; i < 44; i++) {
            const float* sr  = simS + g*1936 + i*44;
            const float* rvi = rv + (i + 43);
            float sv = 0.f, sve = 0.f;
            #pragma unroll
            for (int j = 0; j < 44; j++) {
                float sj = sr[j];
                sv  = fmaf(sj, vreg[j], sv);
                sve = fmaf(sj, rvi[-j], sve);
            }
            float val = fmaf(aSV, sv, fmaf(aSVE, sve, bO));
            if (WIDTH) out[obase + s*44 + i] = val;
            else       out[obase + i*44 + s] = val;
        }
    }
}

// ---------------- conv3x3 + residual + unpatchify ----------------
#define CONV_SMEM (3*256*46*4)   // 141312 bytes

__global__ void __launch_bounds__(512, 1) conv_kernel(const float* __restrict__ conv_b,
                                                      float* __restrict__ out)
{
    extern __shared__ float sin_[];   // [3][256][46], zero-padded columns 0/45
    const int bb = blockIdx.x;
    const int n = bb / 44, y = bb - n*44;
    const int t = threadIdx.x;
    const size_t nbase = (size_t)n * IMGSZ;

    for (int idx = t; idx < 768; idx += 512) {
        int r  = idx >> 8;
        int ci = idx & 255;
        int yy = y + r - 1;
        float* dst = sin_ + (r*256 + ci)*46;
        if (yy < 0 || yy >= 44) {
            #pragma unroll
            for (int k = 0; k < 46; k++) dst[k] = 0.f;
        } else {
            dst[0] = 0.f; dst[45] = 0.f;
            const float* s1 = g_t2 + nbase + (ci*44 + yy)*44;
            const float* s2 = g_p  + nbase + (ci*44 + yy)*44;
            #pragma unroll
            for (int xq = 0; xq < 44; xq++) dst[1 + xq] = s1[xq] + s2[xq];
        }
    }
    __syncthreads();

    const int co = t & 255;
    const int x0 = (t >> 8) * 22;
    float acc[22];
    #pragma unroll
    for (int xi = 0; xi < 22; xi++) acc[xi] = 0.f;

    for (int ci = 0; ci < 256; ci++) {
        float w[9];
        const float* wp = g_convWT + ci*9*256 + co;
        #pragma unroll
        for (int tap = 0; tap < 9; tap++) w[tap] = wp[tap*256];
        #pragma unroll
        for (int ky = 0; ky < 3; ky++) {
            const float* rb = sin_ + (ky*256 + ci)*46 + x0;
            float a = rb[0], b = rb[1];
            #pragma unroll
            for (int xi = 0; xi < 22; xi++) {
                float cv = rb[xi + 2];
                acc[xi] = fmaf(w[ky*3+0], a,  acc[xi]);
                acc[xi] = fmaf(w[ky*3+1], b,  acc[xi]);
                acc[xi] = fmaf(w[ky*3+2], cv, acc[xi]);
                a = b; b = cv;
            }
        }
    }
    const float bias = conv_b[co];

    __syncthreads();           // done reading input tile
    float* st = sin_;          // reuse smem for coalesced store staging [256][44]
    #pragma unroll
    for (int xi = 0; xi < 22; xi++) st[co*44 + x0 + xi] = acc[xi] + bias;
    __syncthreads();

    const int b_ = n >> 2, i2 = (n >> 1) & 1, j2 = n & 1;
    const size_t orow0 = ((size_t)(b_*256) * 88 + (i2*44 + y)) * 88 + j2*44;
    for (int idx = t; idx < 11264; idx += 512) {
        int cc = idx / 44;
        int xq = idx - cc*44;
        out[orow0 + (size_t)cc*7744 + xq] = st[idx];
    }
}

// ---------------- launch ----------------
extern "C" void kernel_launch(void* const* d_in, const int* in_sizes, int n_in,
                              void* d_out, int out_size)
{
    const float* x        = (const float*)d_in[0];
    const float* h_qkv_w  = (const float*)d_in[1];
    const float* h_bn_qkv = (const float*)d_in[2];
    const float* h_bn_sim = (const float*)d_in[3];
    const float* h_bn_out = (const float*)d_in[4];
    const float* h_rel    = (const float*)d_in[5];
    const float* w_qkv_w  = (const float*)d_in[6];
    const float* w_bn_qkv = (const float*)d_in[7];
    const float* w_bn_sim = (const float*)d_in[8];
    const float* w_bn_out = (const float*)d_in[9];
    const float* w_rel    = (const float*)d_in[10];
    const float* conv_w   = (const float*)d_in[11];
    const float* conv_b   = (const float*)d_in[12];
    float* out = (float*)d_out;

    cudaFuncSetAttribute(axial_kernel<false>, cudaFuncAttributeMaxDynamicSharedMemorySize, AX_SMEM);
    cudaFuncSetAttribute(axial_kernel<true>,  cudaFuncAttributeMaxDynamicSharedMemorySize, AX_SMEM);
    cudaFuncSetAttribute(conv_kernel,         cudaFuncAttributeMaxDynamicSharedMemorySize, CONV_SMEM);

    prep_kernel<<<(256*256*9 + 255)/256, 256>>>(h_qkv_w, h_bn_qkv, h_bn_sim, h_bn_out,
                                                w_qkv_w, w_bn_qkv, w_bn_sim, w_bn_out, conv_w);
    patchify_kernel<<<(NPATCH*IMGSZ + 255)/256, 256>>>(x);
    axial_kernel<false><<<NB, 256, AX_SMEM>>>(h_rel, 0);
    axial_kernel<true><<<NB, 256, AX_SMEM>>>(w_rel, 1);
    conv_kernel<<<NB, 512, CONV_SMEM>>>(conv_b, out);
}

// round 2
// speedup vs baseline: 1.2282x; 1.2282x over previous
#include <cuda_runtime.h>
#include <math.h>

#define EPS 1e-5f
#define NPATCH 64
#define HS 44
#define NB (NPATCH*HS)          // 2816
#define PLANE 1936
#define IMGSZ (256*1936)

typedef unsigned long long ull;
__device__ __forceinline__ void fma2(float2 &d, float2 a, float2 b) {
    asm("fma.rn.f32x2 %0, %1, %2, %0;"
        : "+l"(reinterpret_cast<ull&>(d))
        : "l"(reinterpret_cast<ull&>(a)), "l"(reinterpret_cast<ull&>(b)));
}

// ---------------- static device scratch ----------------
__device__ float g_p [NPATCH*IMGSZ];   // patchified input [c][y][x] (residual + conv)
__device__ float g_pT[NPATCH*IMGSZ];   // [c][x][y] height-axial input; reused as width input after transpose
__device__ float g_t1[NPATCH*IMGSZ];   // height-axial out, [c][x][y]
__device__ float g_t2[NPATCH*IMGSZ];   // width-axial out, [c][y][x]
__device__ float g_WT[2][256*512];     // folded qkv weights [ax][c*512+o]
__device__ float g_qkvb[2][512];
__device__ float g_simA[2][12];
__device__ float g_simBsum[2][4];
__device__ float g_outA_sv[2][256];
__device__ float g_outA_sve[2][256];
__device__ float g_outB[2][256];
__device__ float g_relT[2][87*68];     // transposed q/k rel: relT[d*68+c] = rel[c*87+d], c<64
__device__ float g_convWT[256*9*256];  // [(ci*9+tap)*256 + co]

// ---------------- prep ----------------
__global__ void prep_kernel(const float* __restrict__ h_qkv_w, const float* __restrict__ h_bn_qkv,
                            const float* __restrict__ h_bn_sim, const float* __restrict__ h_bn_out,
                            const float* __restrict__ w_qkv_w, const float* __restrict__ w_bn_qkv,
                            const float* __restrict__ w_bn_sim, const float* __restrict__ w_bn_out,
                            const float* __restrict__ conv_w,
                            const float* __restrict__ h_rel, const float* __restrict__ w_rel)
{
    int idx = blockIdx.x * blockDim.x + threadIdx.x;

    if (idx < 256*256*9) {
        int co  = idx / 2304;
        int rem = idx - co*2304;
        g_convWT[rem*256 + co] = conv_w[idx];
    }
    if (idx < 2*131072) {
        int ax = idx >> 17;
        int r  = idx & 131071;
        int o  = r & 511;
        int c  = r >> 9;
        const float* bn = ax ? w_bn_qkv : h_bn_qkv;
        const float* W  = ax ? w_qkv_w : h_qkv_w;
        float s = bn[o] * rsqrtf(bn[1536+o] + EPS);
        g_WT[ax][c*512 + o] = W[o*256 + c] * s;
        if (c == 0) g_qkvb[ax][o] = bn[512+o] - bn[1024+o]*s;
    }
    if (idx < 8) {
        int ax = idx >> 2, g = idx & 3;
        const float* bs = ax ? w_bn_sim : h_bn_sim;
        float shsum = 0.f;
        #pragma unroll
        for (int p = 0; p < 3; p++) {
            int ch = p*4 + g;
            float s = bs[ch] * rsqrtf(bs[36+ch] + EPS);
            g_simA[ax][p*4+g] = (p == 0 ? 1.f : 0.1f) * s;
            shsum += bs[12+ch] - bs[24+ch]*s;
        }
        g_simBsum[ax][g] = shsum;
    }
    if (idx < 512) {
        int ax = idx >> 8, cc = idx & 255;
        const float* bo = ax ? w_bn_out : h_bn_out;
        int o1 = 2*cc, o2 = 2*cc + 1;
        float s1 = bo[o1] * rsqrtf(bo[1536+o1] + EPS);
        float s2 = bo[o2] * rsqrtf(bo[1536+o2] + EPS);
        g_outA_sv[ax][cc]  = s1;
        g_outA_sve[ax][cc] = 0.1f * s2;
        g_outB[ax][cc] = (bo[512+o1] - bo[1024+o1]*s1) + (bo[512+o2] - bo[1024+o2]*s2);
    }
    if (idx < 2*5568) {
        int ax = idx / 5568, r = idx - ax*5568;
        int d = r >> 6, c = r & 63;
        const float* rl = ax ? w_rel : h_rel;
        g_relT[ax][d*68 + c] = rl[c*87 + d];
    }
}

// ---------------- patchify: write g_p [c][y][x] and g_pT [c][x][y] ----------------
__global__ void __launch_bounds__(256,1) patchify_kernel(const float* __restrict__ x)
{
    __shared__ float tile[44*45];
    const int b = blockIdx.x;            // np*256 + c
    const int np = b >> 8, c = b & 255;
    const int bb_ = np >> 2, i2 = (np >> 1) & 1, j2 = np & 1;
    const float* src = x + ((size_t)(bb_*256 + c)*88 + i2*44)*88 + j2*44;
    float* dp  = g_p  + (size_t)b*1936;
    float* dpt = g_pT + (size_t)b*1936;
    const int t = threadIdx.x;
    for (int idx = t; idx < 1936; idx += 256) {
        int y = idx / 44, xq = idx - y*44;
        float v = src[y*88 + xq];
        dp[idx] = v;
        tile[xq*45 + y] = v;
    }
    __syncthreads();
    for (int idx = t; idx < 1936; idx += 256) {
        int r = idx / 44, col = idx - r*44;
        dpt[idx] = tile[r*45 + col];
    }
}

// ---------------- transpose g_t1 [c][x][y] -> g_pT [c][y][x] ----------------
__global__ void __launch_bounds__(256,1) transpose_kernel()
{
    __shared__ float tile[44*45];
    const int b = blockIdx.x;
    const float* src = g_t1 + (size_t)b*1936;
    float* dst = g_pT + (size_t)b*1936;
    const int t = threadIdx.x;
    for (int idx = t; idx < 1936; idx += 256) {
        int r = idx / 44, col = idx - r*44;
        tile[col*45 + r] = src[idx];
    }
    __syncthreads();
    for (int idx = t; idx < 1936; idx += 256) {
        int r = idx / 44, col = idx - r*44;
        dst[idx] = tile[r*45 + col];
    }
}

// ---------------- fused axial attention ----------------
// smem (floats): qkvS[512*44]@0 | qkT[44*260]@22528 | relV[64*87]@33968 |
//                R4@39536 = union{ xs[256*44] , relT[87*68]@39536 + simS[7744]@45452 }
#define OFF_QKT  22528
#define OFF_RELV 33968
#define OFF_XS   39536
#define OFF_RELT 39536
#define OFF_SIM  45452
#define AX_SMEM  (53196*4)

__global__ void __launch_bounds__(512,1) axial_kernel(const float* __restrict__ rel, int ax)
{
    const float* in = g_pT;
    float* out = ax ? g_t2 : g_t1;

    extern __shared__ float sm[];
    float* qkvS = sm;
    float* qkT  = sm + OFF_QKT;
    float* relV = sm + OFF_RELV;
    float* xs   = sm + OFF_XS;
    float* relT = sm + OFF_RELT;
    float* simS = sm + OFF_SIM;

    const int t  = threadIdx.x;
    const int bb = blockIdx.x;
    const int n  = bb / 44;
    const int s  = bb - n*44;

    // load x slice (contiguous rows) + relV (v_emb rows 64..127)
    {
        const float4* src4 = (const float4*)(in + (size_t)n * IMGSZ);
        float4* xs4 = (float4*)xs;
        for (int idx = t; idx < 2816; idx += 512) {
            int c = idx / 11, q = idx - c*11;
            xs4[idx] = src4[c*484 + s*11 + q];
        }
        for (int idx = t; idx < 5568; idx += 512) relV[idx] = rel[64*87 + idx];
    }
    __syncthreads();

    // qkv GEMM: thread = output channel t, all 44 positions, packed pairs
    {
        float2 a[22];
        #pragma unroll
        for (int p = 0; p < 22; p++) a[p] = make_float2(0.f, 0.f);
        const float* WT = g_WT[ax] + t;
        #pragma unroll 4
        for (int c = 0; c < 256; c++) {
            float w = WT[c*512];
            float2 wb = make_float2(w, w);
            const float4* xr = (const float4*)(xs + c*44);
            #pragma unroll
            for (int q = 0; q < 11; q++) {
                float4 xv = xr[q];
                fma2(a[2*q+0], wb, make_float2(xv.x, xv.y));
                fma2(a[2*q+1], wb, make_float2(xv.z, xv.w));
            }
        }
        float b = g_qkvb[ax][t];
        float2* dst = (float2*)(qkvS + t*44);
        #pragma unroll
        for (int p = 0; p < 22; p++) {
            a[p].x += b; a[p].y += b;
            dst[p] = a[p];
        }
        int g = t >> 7, w_ = t & 127;
        if (w_ < 64) {                        // q/k channels -> transposed copy
            int col = g*64 + w_;
            #pragma unroll
            for (int p = 0; p < 22; p++) {
                qkT[(2*p)*260 + col]   = a[p].x;
                qkT[(2*p+1)*260 + col] = a[p].y;
            }
        }
    }
    __syncthreads();

    // load relT (aliases dead xs region)
    for (int idx = t; idx < 5916; idx += 512) relT[idx] = g_relT[ax][idx];
    __syncthreads();

    // sim
    {
        const float a0 = g_simA[ax][0+ (0)], dummy=0.f; (void)a0; (void)dummy;
        for (int e = t; e < 7744; e += 512) {
            int g = e / 1936;
            int r = e - g*1936;
            int i = r / 44;
            int j = r - i*44;
            const float4* qp = (const float4*)(qkT + i*260 + g*64);
            const float4* kp = (const float4*)(qkT + j*260 + g*64 + 32);
            const float4* rq = (const float4*)(relT + (i - j + 43)*68);
            const float4* rk = (const float4*)(relT + (j - i + 43)*68 + 32);
            float2 qk2 = make_float2(0.f,0.f), qr2 = qk2, kr2 = qk2;
            #pragma unroll
            for (int cc = 0; cc < 8; cc++) {
                float4 q4 = qp[cc], k4 = kp[cc], rq4 = rq[cc], rk4 = rk[cc];
                fma2(qk2, make_float2(q4.x,q4.y), make_float2(k4.x,k4.y));
                fma2(qk2, make_float2(q4.z,q4.w), make_float2(k4.z,k4.w));
                fma2(qr2, make_float2(q4.x,q4.y), make_float2(rq4.x,rq4.y));
                fma2(qr2, make_float2(q4.z,q4.w), make_float2(rq4.z,rq4.w));
                fma2(kr2, make_float2(k4.x,k4.y), make_float2(rk4.x,rk4.y));
                fma2(kr2, make_float2(k4.z,k4.w), make_float2(rk4.z,rk4.w));
            }
            float qk = qk2.x + qk2.y, qr = qr2.x + qr2.y, kr = kr2.x + kr2.y;
            simS[e] = g_simA[ax][g]*qk + g_simA[ax][4+g]*qr + g_simA[ax][8+g]*kr + g_simBsum[ax][g];
        }
    }
    __syncthreads();

    // softmax
    if (t < 176) {
        int g = t / 44, i = t - g*44;
        float* row = simS + g*1936 + i*44;
        float mx = -1e30f;
        #pragma unroll
        for (int j = 0; j < 44; j++) mx = fmaxf(mx, row[j]);
        float sum = 0.f;
        #pragma unroll
        for (int j = 0; j < 44; j++) { float e = __expf(row[j] - mx); row[j] = e; sum += e; }
        float inv = 1.f / sum;
        #pragma unroll
        for (int j = 0; j < 44; j++) row[j] *= inv;
    }
    __syncthreads();

    // output: thread = (half, ch); 22 i-rows each
    {
        const int half = t >> 8, ch = t & 255;
        const int g = ch >> 6, c = ch & 63;
        float2 v2[22];
        const float4* vp = (const float4*)(qkvS + (g*128 + 64 + c)*44);
        #pragma unroll
        for (int q = 0; q < 11; q++) {
            float4 v4 = vp[q];
            v2[2*q]   = make_float2(v4.x, v4.y);
            v2[2*q+1] = make_float2(v4.z, v4.w);
        }
        const float* rv = relV + c*87;
        const float aSV  = g_outA_sv[ax][ch];
        const float aSVE = g_outA_sve[ax][ch];
        const float bO   = g_outB[ax][ch];
        float* op = out + ((size_t)(n*256 + ch))*1936 + s*44;
        const int i0 = half*22;
        for (int ii = 0; ii < 22; ii++) {
            int i = i0 + ii;
            const float2* sr2 = (const float2*)(simS + g*1936 + i*44);
            const float* rvi = rv + i + 43;
            float2 sv2 = make_float2(0.f, 0.f);
            float sve = 0.f;
            #pragma unroll
            for (int p = 0; p < 22; p++) {
                float2 s2 = sr2[p];
                fma2(sv2, s2, v2[p]);
                sve = fmaf(s2.x, rvi[-2*p],   sve);
                sve = fmaf(s2.y, rvi[-2*p-1], sve);
            }
            op[i] = fmaf(aSV, sv2.x + sv2.y, fmaf(aSVE, sve, bO));
        }
    }
}

// ---------------- conv3x3 + residual + unpatchify (f32x2) ----------------
#define CONV_SMEM (3*256*46*4)

__global__ void __launch_bounds__(512,1) conv_kernel(const float* __restrict__ conv_b,
                                                     float* __restrict__ out)
{
    extern __shared__ float sin_[];   // [3][256][46]
    const int bb = blockIdx.x;
    const int n = bb / 44, y = bb - n*44;
    const int t = threadIdx.x;
    const size_t nbase = (size_t)n * IMGSZ;

    for (int idx = t; idx < 768; idx += 512) {
        int r  = idx >> 8;
        int ci = idx & 255;
        int yy = y + r - 1;
        float* dst = sin_ + (r*256 + ci)*46;
        if (yy < 0 || yy >= 44) {
            #pragma unroll
            for (int k = 0; k < 46; k++) dst[k] = 0.f;
        } else {
            dst[0] = 0.f; dst[45] = 0.f;
            const float4* s1 = (const float4*)(g_t2 + nbase + (ci*44 + yy)*44);
            const float4* s2 = (const float4*)(g_p  + nbase + (ci*44 + yy)*44);
            #pragma unroll
            for (int q = 0; q < 11; q++) {
                float4 a = s1[q], b = s2[q];
                dst[1+4*q+0] = a.x + b.x;
                dst[1+4*q+1] = a.y + b.y;
                dst[1+4*q+2] = a.z + b.z;
                dst[1+4*q+3] = a.w + b.w;
            }
        }
    }
    __syncthreads();

    const int quarter = t >> 7, copair = t & 127;
    const int co0 = 2*copair;
    const int x0 = quarter*11;
    float2 acc[11];
    #pragma unroll
    for (int p = 0; p < 11; p++) acc[p] = make_float2(0.f, 0.f);

    for (int ci = 0; ci < 256; ci++) {
        const float* wp = g_convWT + ci*2304 + co0;
        float2 w2[9];
        #pragma unroll
        for (int tap = 0; tap < 9; tap++) w2[tap] = *(const float2*)(wp + tap*256);
        #pragma unroll
        for (int ky = 0; ky < 3; ky++) {
            const float* rb = sin_ + (ky*256 + ci)*46 + x0;
            float2 rp[13];
            #pragma unroll
            for (int k = 0; k < 13; k++) { float v = rb[k]; rp[k] = make_float2(v, v); }
            #pragma unroll
            for (int kx = 0; kx < 3; kx++) {
                #pragma unroll
                for (int p = 0; p < 11; p++) fma2(acc[p], w2[ky*3+kx], rp[p+kx]);
            }
        }
    }
    const float b0v = conv_b[co0], b1v = conv_b[co0+1];

    __syncthreads();
    float* st = sin_;                 // staging [256][44]
    #pragma unroll
    for (int p = 0; p < 11; p++) {
        st[co0*44     + x0 + p] = acc[p].x + b0v;
        st[(co0+1)*44 + x0 + p] = acc[p].y + b1v;
    }
    __syncthreads();

    const int b_ = n >> 2, i2 = (n >> 1) & 1, j2 = n & 1;
    const size_t orow0 = ((size_t)(b_*256) * 88 + (i2*44 + y)) * 88 + j2*44;
    const float4* st4 = (const float4*)st;
    for (int idx = t; idx < 2816; idx += 512) {
        int cc = idx / 11, q = idx - cc*11;
        *(float4*)(out + orow0 + (size_t)cc*7744 + q*4) = st4[idx];
    }
}

// ---------------- launch ----------------
extern "C" void kernel_launch(void* const* d_in, const int* in_sizes, int n_in,
                              void* d_out, int out_size)
{
    const float* x        = (const float*)d_in[0];
    const float* h_qkv_w  = (const float*)d_in[1];
    const float* h_bn_qkv = (const float*)d_in[2];
    const float* h_bn_sim = (const float*)d_in[3];
    const float* h_bn_out = (const float*)d_in[4];
    const float* h_rel    = (const float*)d_in[5];
    const float* w_qkv_w  = (const float*)d_in[6];
    const float* w_bn_qkv = (const float*)d_in[7];
    const float* w_bn_sim = (const float*)d_in[8];
    const float* w_bn_out = (const float*)d_in[9];
    const float* w_rel    = (const float*)d_in[10];
    const float* conv_w   = (const float*)d_in[11];
    const float* conv_b   = (const float*)d_in[12];
    float* out = (float*)d_out;

    cudaFuncSetAttribute(axial_kernel, cudaFuncAttributeMaxDynamicSharedMemorySize, AX_SMEM);
    cudaFuncSetAttribute(conv_kernel,  cudaFuncAttributeMaxDynamicSharedMemorySize, CONV_SMEM);

    prep_kernel<<<(256*256*9 + 255)/256, 256>>>(h_qkv_w, h_bn_qkv, h_bn_sim, h_bn_out,
                                                w_qkv_w, w_bn_qkv, w_bn_sim, w_bn_out,
                                                conv_w, h_rel, w_rel);
    patchify_kernel<<<NPATCH*256, 256>>>(x);
    axial_kernel<<<NB, 512, AX_SMEM>>>(h_rel, 0);
    transpose_kernel<<<NPATCH*256, 256>>>();
    axial_kernel<<<NB, 512, AX_SMEM>>>(w_rel, 1);
    conv_kernel<<<NB, 512, CONV_SMEM>>>(conv_b, out);
}

// round 4
// speedup vs baseline: 1.3207x; 1.0754x over previous
#include <cuda_runtime.h>
#include <math.h>

#define EPS 1e-5f
#define NPATCH 64
#define HS 44
#define NB (NPATCH*HS)          // 2816
#define PLANE 1936
#define IMGSZ (256*1936)

typedef unsigned long long ull;
__device__ __forceinline__ void fma2(float2 &d, float2 a, float2 b) {
    asm("fma.rn.f32x2 %0, %1, %2, %0;"
        : "+l"(reinterpret_cast<ull&>(d))
        : "l"(reinterpret_cast<ull&>(a)), "l"(reinterpret_cast<ull&>(b)));
}

// ---------------- static device scratch ----------------
__device__ float g_p [NPATCH*IMGSZ];   // patchified input [c][y][x]
__device__ float g_pT[NPATCH*IMGSZ];   // [c][x][y]; reused as width input after transpose
__device__ float g_t1[NPATCH*IMGSZ];   // height-axial out [c][x][y]
__device__ float g_t2[NPATCH*IMGSZ];   // width-axial out [c][y][x]
__device__ float g_Wint[2][256*512];   // folded qkv weights, [ax][c][pair][slot]: (o, o+256) interleaved
__device__ float g_qkvb[2][512];
__device__ float g_simA[2][12];
__device__ float g_simBsum[2][4];
__device__ float g_outA_sv[2][256];
__device__ float g_outA_sve[2][256];
__device__ float g_outB[2][256];
__device__ float g_relT[2][87*68];     // transposed q/k rel
__device__ float g_convWT[256*9*256];  // [(ci*9+tap)*256 + co]

// ---------------- prep ----------------
__global__ void prep_kernel(const float* __restrict__ h_qkv_w, const float* __restrict__ h_bn_qkv,
                            const float* __restrict__ h_bn_sim, const float* __restrict__ h_bn_out,
                            const float* __restrict__ w_qkv_w, const float* __restrict__ w_bn_qkv,
                            const float* __restrict__ w_bn_sim, const float* __restrict__ w_bn_out,
                            const float* __restrict__ conv_w,
                            const float* __restrict__ h_rel, const float* __restrict__ w_rel)
{
    int idx = blockIdx.x * blockDim.x + threadIdx.x;

    if (idx < 256*256*9) {
        int co  = idx / 2304;
        int rem = idx - co*2304;
        g_convWT[rem*256 + co] = conv_w[idx];
    }
    if (idx < 2*131072) {
        int ax = idx >> 17;
        int r  = idx & 131071;
        int o  = r & 511;
        int c  = r >> 9;
        const float* bn = ax ? w_bn_qkv : h_bn_qkv;
        const float* W  = ax ? w_qkv_w : h_qkv_w;
        float s = bn[o] * rsqrtf(bn[1536+o] + EPS);
        g_Wint[ax][c*512 + (o & 255)*2 + (o >> 8)] = W[o*256 + c] * s;
        if (c == 0) g_qkvb[ax][o] = bn[512+o] - bn[1024+o]*s;
    }
    if (idx < 8) {
        int ax = idx >> 2, g = idx & 3;
        const float* bs = ax ? w_bn_sim : h_bn_sim;
        float shsum = 0.f;
        #pragma unroll
        for (int p = 0; p < 3; p++) {
            int ch = p*4 + g;
            float s = bs[ch] * rsqrtf(bs[36+ch] + EPS);
            g_simA[ax][p*4+g] = (p == 0 ? 1.f : 0.1f) * s;
            shsum += bs[12+ch] - bs[24+ch]*s;
        }
        g_simBsum[ax][g] = shsum;
    }
    if (idx < 512) {
        int ax = idx >> 8, cc = idx & 255;
        const float* bo = ax ? w_bn_out : h_bn_out;
        int o1 = 2*cc, o2 = 2*cc + 1;
        float s1 = bo[o1] * rsqrtf(bo[1536+o1] + EPS);
        float s2 = bo[o2] * rsqrtf(bo[1536+o2] + EPS);
        g_outA_sv[ax][cc]  = s1;
        g_outA_sve[ax][cc] = 0.1f * s2;
        g_outB[ax][cc] = (bo[512+o1] - bo[1024+o1]*s1) + (bo[512+o2] - bo[1024+o2]*s2);
    }
    if (idx < 2*5568) {
        int ax = idx / 5568, r = idx - ax*5568;
        int d = r >> 6, c = r & 63;
        const float* rl = ax ? w_rel : h_rel;
        g_relT[ax][d*68 + c] = rl[c*87 + d];
    }
}

// ---------------- patchify ----------------
__global__ void __launch_bounds__(256,1) patchify_kernel(const float* __restrict__ x)
{
    __shared__ float tile[44*45];
    const int b = blockIdx.x;
    const int np = b >> 8, c = b & 255;
    const int bb_ = np >> 2, i2 = (np >> 1) & 1, j2 = np & 1;
    const float* src = x + ((size_t)(bb_*256 + c)*88 + i2*44)*88 + j2*44;
    float* dp  = g_p  + (size_t)b*1936;
    float* dpt = g_pT + (size_t)b*1936;
    const int t = threadIdx.x;
    for (int idx = t; idx < 1936; idx += 256) {
        int y = idx / 44, xq = idx - y*44;
        float v = src[y*88 + xq];
        dp[idx] = v;
        tile[xq*45 + y] = v;
    }
    __syncthreads();
    for (int idx = t; idx < 1936; idx += 256) {
        int r = idx / 44, col = idx - r*44;
        dpt[idx] = tile[r*45 + col];
    }
}

// ---------------- transpose g_t1 [c][x][y] -> g_pT [c][y][x] ----------------
__global__ void __launch_bounds__(256,1) transpose_kernel()
{
    __shared__ float tile[44*45];
    const int b = blockIdx.x;
    const float* src = g_t1 + (size_t)b*1936;
    float* dst = g_pT + (size_t)b*1936;
    const int t = threadIdx.x;
    for (int idx = t; idx < 1936; idx += 256) {
        int r = idx / 44, col = idx - r*44;
        tile[col*45 + r] = src[idx];
    }
    __syncthreads();
    for (int idx = t; idx < 1936; idx += 256) {
        int r = idx / 44, col = idx - r*44;
        dst[idx] = tile[r*45 + col];
    }
}

// ---------------- fused axial attention v3: 1024 threads ----------------
// smem floats: xs[256][48]@0 | qkT[44][260]@12288 | vS[256][44]@23728 |
//              relV[64][87]@34992 | relT[87][68]@40560 | sim[4][44][44]@46476
#define OFF_QKT  12288
#define OFF_V    23728
#define OFF_RELV 34992
#define OFF_RELT 40560
#define OFF_SIM  46476
#define AX_SMEM  (54220*4)

__global__ void __launch_bounds__(1024,1) axial_kernel(const float* __restrict__ rel, int ax)
{
    const float* in = g_pT;
    float* out = ax ? g_t2 : g_t1;

    extern __shared__ float sm[];
    float* xs   = sm;
    float* qkT  = sm + OFF_QKT;
    float* vS   = sm + OFF_V;
    float* relV = sm + OFF_RELV;
    float* relT = sm + OFF_RELT;
    float* simS = sm + OFF_SIM;

    const int t  = threadIdx.x;
    const int bb = blockIdx.x;
    const int n  = bb / 44;
    const int s  = bb - n*44;

    // load x slice into padded rows [256][48], plus rel tables
    {
        const float4* src4 = (const float4*)(in + (size_t)n * IMGSZ);
        float4* xs4 = (float4*)xs;
        for (int idx = t; idx < 3072; idx += 1024) {
            int c = idx / 12, q = idx - c*12;
            xs4[idx] = (q < 11) ? src4[c*484 + s*11 + q] : make_float4(0.f,0.f,0.f,0.f);
        }
        for (int idx = t; idx < 5568; idx += 1024) relV[idx] = rel[64*87 + idx];
        for (int idx = t; idx < 5916; idx += 1024) relT[idx] = g_relT[ax][idx];
    }
    __syncthreads();

    // qkv GEMM: thread = channel pair (o0, o0+256) x 12 positions
    {
        const int o0  = t & 255;
        const int qtr = t >> 8;         // 0..3
        const int p0  = qtr*12;
        float2 acc[12];
        #pragma unroll
        for (int p = 0; p < 12; p++) acc[p] = make_float2(0.f, 0.f);
        const float2* Wp = ((const float2*)g_Wint[ax]) + o0;
        #pragma unroll 4
        for (int c = 0; c < 256; c++) {
            float2 w = Wp[c*256];
            const float4* xp = (const float4*)(xs + c*48 + p0);
            #pragma unroll
            for (int qq = 0; qq < 3; qq++) {
                float4 xv = xp[qq];
                fma2(acc[qq*4+0], w, make_float2(xv.x, xv.x));
                fma2(acc[qq*4+1], w, make_float2(xv.y, xv.y));
                fma2(acc[qq*4+2], w, make_float2(xv.z, xv.z));
                fma2(acc[qq*4+3], w, make_float2(xv.w, xv.w));
            }
        }
        #pragma unroll
        for (int sl = 0; sl < 2; sl++) {
            const int o = o0 + sl*256;
            const float b = g_qkvb[ax][o];
            const int g = o >> 7, wi = o & 127;
            float* dst;
            int stride;
            if (wi < 64) { dst = qkT + p0*260 + g*64 + wi; stride = 260; }
            else         { dst = vS + (g*64 + wi - 64)*44 + p0; stride = 1; }
            #pragma unroll
            for (int p = 0; p < 12; p++) {
                if (p0 + p < 44) dst[p*stride] = (sl ? acc[p].y : acc[p].x) + b;
            }
        }
    }
    __syncthreads();

    // sim
    for (int e = t; e < 7744; e += 1024) {
        int g = e / 1936;
        int r = e - g*1936;
        int i = r / 44;
        int j = r - i*44;
        const float4* qp = (const float4*)(qkT + i*260 + g*64);
        const float4* kp = (const float4*)(qkT + j*260 + g*64 + 32);
        const float4* rq = (const float4*)(relT + (i - j + 43)*68);
        const float4* rk = (const float4*)(relT + (j - i + 43)*68 + 32);
        float2 qk2 = make_float2(0.f,0.f), qr2 = qk2, kr2 = qk2;
        #pragma unroll
        for (int cc = 0; cc < 8; cc++) {
            float4 q4 = qp[cc], k4 = kp[cc], rq4 = rq[cc], rk4 = rk[cc];
            fma2(qk2, make_float2(q4.x,q4.y), make_float2(k4.x,k4.y));
            fma2(qk2, make_float2(q4.z,q4.w), make_float2(k4.z,k4.w));
            fma2(qr2, make_float2(q4.x,q4.y), make_float2(rq4.x,rq4.y));
            fma2(qr2, make_float2(q4.z,q4.w), make_float2(rq4.z,rq4.w));
            fma2(kr2, make_float2(k4.x,k4.y), make_float2(rk4.x,rk4.y));
            fma2(kr2, make_float2(k4.z,k4.w), make_float2(rk4.z,rk4.w));
        }
        float qk = qk2.x + qk2.y, qr = qr2.x + qr2.y, kr = kr2.x + kr2.y;
        simS[e] = g_simA[ax][g]*qk + g_simA[ax][4+g]*qr + g_simA[ax][8+g]*kr + g_simBsum[ax][g];
    }
    __syncthreads();

    // softmax: warp per row
    {
        const int wid = t >> 5, lane = t & 31;
        #pragma unroll
        for (int k = 0; k < 6; k++) {
            int r = wid + 32*k;
            if (r < 176) {
                float* row = simS + (r/44)*1936 + (r - (r/44)*44)*44;
                float v1 = row[lane];
                float v2 = (lane < 12) ? row[lane+32] : -1e30f;
                float m = fmaxf(v1, v2);
                #pragma unroll
                for (int off = 16; off; off >>= 1) m = fmaxf(m, __shfl_xor_sync(0xffffffffu, m, off));
                float e1 = __expf(v1 - m);
                float e2 = (lane < 12) ? __expf(v2 - m) : 0.f;
                float su = e1 + e2;
                #pragma unroll
                for (int off = 16; off; off >>= 1) su += __shfl_xor_sync(0xffffffffu, su, off);
                float inv = 1.f / su;
                row[lane] = e1 * inv;
                if (lane < 12) row[lane+32] = e2 * inv;
            }
        }
    }
    __syncthreads();

    // output: thread = (quarter, ch); 11 i-rows each; v row in regs
    {
        const int ch = t & 255, qtr = t >> 8;
        const int g = ch >> 6, c = ch & 63;
        float2 v2[22];
        const float4* vp = (const float4*)(vS + ch*44);
        #pragma unroll
        for (int q = 0; q < 11; q++) {
            float4 v4 = vp[q];
            v2[2*q]   = make_float2(v4.x, v4.y);
            v2[2*q+1] = make_float2(v4.z, v4.w);
        }
        const float* rv = relV + c*87;
        const float aSV  = g_outA_sv[ax][ch];
        const float aSVE = g_outA_sve[ax][ch];
        const float bO   = g_outB[ax][ch];
        float* op = out + ((size_t)(n*256 + ch))*1936 + s*44;
        #pragma unroll 1
        for (int ii = 0; ii < 11; ii++) {
            int i = qtr*11 + ii;
            const float2* sr2 = (const float2*)(simS + g*1936 + i*44);
            const float* rvi = rv + i + 43;
            float2 sv2 = make_float2(0.f, 0.f);
            float sve = 0.f;
            #pragma unroll
            for (int p = 0; p < 22; p++) {
                float2 s2 = sr2[p];
                fma2(sv2, s2, v2[p]);
                sve = fmaf(s2.x, rvi[-2*p],   sve);
                sve = fmaf(s2.y, rvi[-2*p-1], sve);
            }
            op[i] = fmaf(aSV, sv2.x + sv2.y, fmaf(aSVE, sve, bO));
        }
    }
}

// ---------------- conv3x3 + residual + unpatchify (f32x2, from R2) ----------------
#define CONV_SMEM (3*256*46*4)

__global__ void __launch_bounds__(512,1) conv_kernel(const float* __restrict__ conv_b,
                                                     float* __restrict__ out)
{
    extern __shared__ float sin_[];   // [3][256][46]
    const int bb = blockIdx.x;
    const int n = bb / 44, y = bb - n*44;
    const int t = threadIdx.x;
    const size_t nbase = (size_t)n * IMGSZ;

    for (int idx = t; idx < 768; idx += 512) {
        int r  = idx >> 8;
        int ci = idx & 255;
        int yy = y + r - 1;
        float* dst = sin_ + (r*256 + ci)*46;
        if (yy < 0 || yy >= 44) {
            #pragma unroll
            for (int k = 0; k < 46; k++) dst[k] = 0.f;
        } else {
            dst[0] = 0.f; dst[45] = 0.f;
            const float4* s1 = (const float4*)(g_t2 + nbase + (ci*44 + yy)*44);
            const float4* s2 = (const float4*)(g_p  + nbase + (ci*44 + yy)*44);
            #pragma unroll
            for (int q = 0; q < 11; q++) {
                float4 a = s1[q], b = s2[q];
                dst[1+4*q+0] = a.x + b.x;
                dst[1+4*q+1] = a.y + b.y;
                dst[1+4*q+2] = a.z + b.z;
                dst[1+4*q+3] = a.w + b.w;
            }
        }
    }
    __syncthreads();

    const int quarter = t >> 7, copair = t & 127;
    const int co0 = 2*copair;
    const int x0 = quarter*11;
    float2 acc[11];
    #pragma unroll
    for (int p = 0; p < 11; p++) acc[p] = make_float2(0.f, 0.f);

    for (int ci = 0; ci < 256; ci++) {
        const float* wp = g_convWT + ci*2304 + co0;
        float2 w2[9];
        #pragma unroll
        for (int tap = 0; tap < 9; tap++) w2[tap] = *(const float2*)(wp + tap*256);
        #pragma unroll
        for (int ky = 0; ky < 3; ky++) {
            const float* rb = sin_ + (ky*256 + ci)*46 + x0;
            float2 rp[13];
            #pragma unroll
            for (int k = 0; k < 13; k++) { float v = rb[k]; rp[k] = make_float2(v, v); }
            #pragma unroll
            for (int kx = 0; kx < 3; kx++) {
                #pragma unroll
                for (int p = 0; p < 11; p++) fma2(acc[p], w2[ky*3+kx], rp[p+kx]);
            }
        }
    }
    const float b0v = conv_b[co0], b1v = conv_b[co0+1];

    __syncthreads();
    float* st = sin_;                 // staging [256][44]
    #pragma unroll
    for (int p = 0; p < 11; p++) {
        st[co0*44     + x0 + p] = acc[p].x + b0v;
        st[(co0+1)*44 + x0 + p] = acc[p].y + b1v;
    }
    __syncthreads();

    const int b_ = n >> 2, i2 = (n >> 1) & 1, j2 = n & 1;
    const size_t orow0 = ((size_t)(b_*256) * 88 + (i2*44 + y)) * 88 + j2*44;
    const float4* st4 = (const float4*)st;
    for (int idx = t; idx < 2816; idx += 512) {
        int cc = idx / 11, q = idx - cc*11;
        *(float4*)(out + orow0 + (size_t)cc*7744 + q*4) = st4[idx];
    }
}

// ---------------- launch ----------------
extern "C" void kernel_launch(void* const* d_in, const int* in_sizes, int n_in,
                              void* d_out, int out_size)
{
    const float* x        = (const float*)d_in[0];
    const float* h_qkv_w  = (const float*)d_in[1];
    const float* h_bn_qkv = (const float*)d_in[2];
    const float* h_bn_sim = (const float*)d_in[3];
    const float* h_bn_out = (const float*)d_in[4];
    const float* h_rel    = (const float*)d_in[5];
    const float* w_qkv_w  = (const float*)d_in[6];
    const float* w_bn_qkv = (const float*)d_in[7];
    const float* w_bn_sim = (const float*)d_in[8];
    const float* w_bn_out = (const float*)d_in[9];
    const float* w_rel    = (const float*)d_in[10];
    const float* conv_w   = (const float*)d_in[11];
    const float* conv_b   = (const float*)d_in[12];
    float* out = (float*)d_out;

    cudaFuncSetAttribute(axial_kernel, cudaFuncAttributeMaxDynamicSharedMemorySize, AX_SMEM);
    cudaFuncSetAttribute(conv_kernel,  cudaFuncAttributeMaxDynamicSharedMemorySize, CONV_SMEM);

    prep_kernel<<<(256*256*9 + 255)/256, 256>>>(h_qkv_w, h_bn_qkv, h_bn_sim, h_bn_out,
                                                w_qkv_w, w_bn_qkv, w_bn_sim, w_bn_out,
                                                conv_w, h_rel, w_rel);
    patchify_kernel<<<NPATCH*256, 256>>>(x);
    axial_kernel<<<NB, 1024, AX_SMEM>>>(h_rel, 0);
    transpose_kernel<<<NPATCH*256, 256>>>();
    axial_kernel<<<NB, 1024, AX_SMEM>>>(w_rel, 1);
    conv_kernel<<<NB, 512, CONV_SMEM>>>(conv_b, out);
}

// round 5
// speedup vs baseline: 1.5731x; 1.1910x over previous
#include <cuda_runtime.h>
#include <cuda_bf16.h>
#include <math.h>
#include <cstdint>

#define EPS 1e-5f
#define NPATCH 64
#define HS 44
#define NB (NPATCH*HS)          // 2816
#define PLANE 1936
#define IMGSZ (256*1936)

// padded conv geometry
#define PPX 2208                // 46*48 padded pixels per patch
#define NWIN 18
#define MARGIN_LO 128
#define XROWS (MARGIN_LO + NPATCH*PPX + 256)

typedef unsigned long long ull;
__device__ __forceinline__ void fma2(float2 &d, float2 a, float2 b) {
    asm("fma.rn.f32x2 %0, %1, %2, %0;"
        : "+l"(reinterpret_cast<ull&>(d))
        : "l"(reinterpret_cast<ull&>(a)), "l"(reinterpret_cast<ull&>(b)));
}

// ---------------- mma / ldmatrix / cp.async helpers (all sm_80 baseline) ----------------
__device__ __forceinline__ uint32_t smem_to_u32(const void* p) {
    uint32_t a;
    asm("{ .reg .u64 t; cvta.to.shared.u64 t, %1; cvt.u32.u64 %0, t; }" : "=r"(a) : "l"(p));
    return a;
}
__device__ __forceinline__ void ldsm_x4(uint32_t a[4], uint32_t addr) {
    asm volatile("ldmatrix.sync.aligned.m8n8.x4.shared.b16 {%0,%1,%2,%3}, [%4];"
        : "=r"(a[0]),"=r"(a[1]),"=r"(a[2]),"=r"(a[3]) : "r"(addr));
}
__device__ __forceinline__ void ldsm_x2_t(uint32_t b[2], uint32_t addr) {
    asm volatile("ldmatrix.sync.aligned.m8n8.x2.trans.shared.b16 {%0,%1}, [%2];"
        : "=r"(b[0]),"=r"(b[1]) : "r"(addr));
}
__device__ __forceinline__ void mma_bf16(float c[4], const uint32_t a[4], const uint32_t b[2]) {
    asm volatile("mma.sync.aligned.m16n8k16.row.col.f32.bf16.bf16.f32 "
        "{%0,%1,%2,%3}, {%4,%5,%6,%7}, {%8,%9}, {%0,%1,%2,%3};"
        : "+f"(c[0]),"+f"(c[1]),"+f"(c[2]),"+f"(c[3])
        : "r"(a[0]),"r"(a[1]),"r"(a[2]),"r"(a[3]), "r"(b[0]),"r"(b[1]));
}
__device__ __forceinline__ void cp16(uint32_t saddr, const void* g) {
    asm volatile("cp.async.cg.shared.global [%0], [%1], 16;" :: "r"(saddr), "l"(g));
}
#define CP_COMMIT() asm volatile("cp.async.commit_group;" ::: "memory")
#define CP_WAIT(n)  asm volatile("cp.async.wait_group %0;" :: "n"(n) : "memory")

// ---------------- static device scratch ----------------
__device__ float g_p [NPATCH*IMGSZ];   // patchified input [c][y][x]
__device__ float g_pT[NPATCH*IMGSZ];   // [c][x][y]; reused after transpose
__device__ float g_t1[NPATCH*IMGSZ];
__device__ float g_t2[NPATCH*IMGSZ];
__device__ float g_Wint[2][256*512];
__device__ float g_qkvb[2][512];
__device__ float g_simA[2][12];
__device__ float g_simBsum[2][4];
__device__ float g_outA_sv[2][256];
__device__ float g_outA_sve[2][256];
__device__ float g_outB[2][256];
__device__ float g_relT[2][87*68];
// conv tensor buffers
__device__ __align__(1024) __nv_bfloat16 g_xh[(size_t)XROWS*256];  // [row][ci] hi
__device__ __align__(1024) __nv_bfloat16 g_xl[(size_t)XROWS*256];  // lo
__device__ __align__(1024) __nv_bfloat16 g_wh[9*256*256];          // [tap][ci][co] hi
__device__ __align__(1024) __nv_bfloat16 g_wl[9*256*256];          // lo

// ---------------- prep ----------------
__global__ void prep_kernel(const float* __restrict__ h_qkv_w, const float* __restrict__ h_bn_qkv,
                            const float* __restrict__ h_bn_sim, const float* __restrict__ h_bn_out,
                            const float* __restrict__ w_qkv_w, const float* __restrict__ w_bn_qkv,
                            const float* __restrict__ w_bn_sim, const float* __restrict__ w_bn_out,
                            const float* __restrict__ conv_w,
                            const float* __restrict__ h_rel, const float* __restrict__ w_rel)
{
    int idx = blockIdx.x * blockDim.x + threadIdx.x;

    if (idx < 256*256*9) {   // conv_w [co][ci][tap] -> [tap][ci][co] hi/lo bf16
        int co  = idx / 2304;
        int rem = idx - co*2304;    // ci*9 + tap
        int ci  = rem / 9;
        int tap = rem - ci*9;
        float w = conv_w[idx];
        __nv_bfloat16 hi = __float2bfloat16(w);
        float lo = w - __bfloat162float(hi);
        g_wh[(tap*256 + ci)*256 + co] = hi;
        g_wl[(tap*256 + ci)*256 + co] = __float2bfloat16(lo);
    }
    // zero activation margins
    if (idx < MARGIN_LO*256) {
        g_xh[idx] = __float2bfloat16(0.f);
        g_xl[idx] = __float2bfloat16(0.f);
    }
    if (idx < 256*256) {
        size_t off = (size_t)(MARGIN_LO + NPATCH*PPX)*256 + idx;
        g_xh[off] = __float2bfloat16(0.f);
        g_xl[off] = __float2bfloat16(0.f);
    }
    if (idx < 2*131072) {
        int ax = idx >> 17;
        int r  = idx & 131071;
        int o  = r & 511;
        int c  = r >> 9;
        const float* bn = ax ? w_bn_qkv : h_bn_qkv;
        const float* W  = ax ? w_qkv_w : h_qkv_w;
        float s = bn[o] * rsqrtf(bn[1536+o] + EPS);
        g_Wint[ax][c*512 + (o & 255)*2 + (o >> 8)] = W[o*256 + c] * s;
        if (c == 0) g_qkvb[ax][o] = bn[512+o] - bn[1024+o]*s;
    }
    if (idx < 8) {
        int ax = idx >> 2, g = idx & 3;
        const float* bs = ax ? w_bn_sim : h_bn_sim;
        float shsum = 0.f;
        #pragma unroll
        for (int p = 0; p < 3; p++) {
            int ch = p*4 + g;
            float s = bs[ch] * rsqrtf(bs[36+ch] + EPS);
            g_simA[ax][p*4+g] = (p == 0 ? 1.f : 0.1f) * s;
            shsum += bs[12+ch] - bs[24+ch]*s;
        }
        g_simBsum[ax][g] = shsum;
    }
    if (idx < 512) {
        int ax = idx >> 8, cc = idx & 255;
        const float* bo = ax ? w_bn_out : h_bn_out;
        int o1 = 2*cc, o2 = 2*cc + 1;
        float s1 = bo[o1] * rsqrtf(bo[1536+o1] + EPS);
        float s2 = bo[o2] * rsqrtf(bo[1536+o2] + EPS);
        g_outA_sv[ax][cc]  = s1;
        g_outA_sve[ax][cc] = 0.1f * s2;
        g_outB[ax][cc] = (bo[512+o1] - bo[1024+o1]*s1) + (bo[512+o2] - bo[1024+o2]*s2);
    }
    if (idx < 2*5568) {
        int ax = idx / 5568, r = idx - ax*5568;
        int d = r >> 6, c = r & 63;
        const float* rl = ax ? w_rel : h_rel;
        g_relT[ax][d*68 + c] = rl[c*87 + d];
    }
}

// ---------------- patchify ----------------
__global__ void __launch_bounds__(256,1) patchify_kernel(const float* __restrict__ x)
{
    __shared__ float tile[44*45];
    const int b = blockIdx.x;
    const int np = b >> 8, c = b & 255;
    const int bb_ = np >> 2, i2 = (np >> 1) & 1, j2 = np & 1;
    const float* src = x + ((size_t)(bb_*256 + c)*88 + i2*44)*88 + j2*44;
    float* dp  = g_p  + (size_t)b*1936;
    float* dpt = g_pT + (size_t)b*1936;
    const int t = threadIdx.x;
    for (int idx = t; idx < 1936; idx += 256) {
        int y = idx / 44, xq = idx - y*44;
        float v = src[y*88 + xq];
        dp[idx] = v;
        tile[xq*45 + y] = v;
    }
    __syncthreads();
    for (int idx = t; idx < 1936; idx += 256) {
        int r = idx / 44, col = idx - r*44;
        dpt[idx] = tile[r*45 + col];
    }
}

// ---------------- transpose ----------------
__global__ void __launch_bounds__(256,1) transpose_kernel()
{
    __shared__ float tile[44*45];
    const int b = blockIdx.x;
    const float* src = g_t1 + (size_t)b*1936;
    float* dst = g_pT + (size_t)b*1936;
    const int t = threadIdx.x;
    for (int idx = t; idx < 1936; idx += 256) {
        int r = idx / 44, col = idx - r*44;
        tile[col*45 + r] = src[idx];
    }
    __syncthreads();
    for (int idx = t; idx < 1936; idx += 256) {
        int r = idx / 44, col = idx - r*44;
        dst[idx] = tile[r*45 + col];
    }
}

// ---------------- fused axial attention (R4 version) ----------------
#define OFF_QKT  12288
#define OFF_V    23728
#define OFF_RELV 34992
#define OFF_RELT 40560
#define OFF_SIM  46476
#define AX_SMEM  (54220*4)

__global__ void __launch_bounds__(1024,1) axial_kernel(const float* __restrict__ rel, int ax)
{
    const float* in = g_pT;
    float* out = ax ? g_t2 : g_t1;

    extern __shared__ float sm[];
    float* xs   = sm;
    float* qkT  = sm + OFF_QKT;
    float* vS   = sm + OFF_V;
    float* relV = sm + OFF_RELV;
    float* relT = sm + OFF_RELT;
    float* simS = sm + OFF_SIM;

    const int t  = threadIdx.x;
    const int bb = blockIdx.x;
    const int n  = bb / 44;
    const int s  = bb - n*44;

    {
        const float4* src4 = (const float4*)(in + (size_t)n * IMGSZ);
        float4* xs4 = (float4*)xs;
        for (int idx = t; idx < 3072; idx += 1024) {
            int c = idx / 12, q = idx - c*12;
            xs4[idx] = (q < 11) ? src4[c*484 + s*11 + q] : make_float4(0.f,0.f,0.f,0.f);
        }
        for (int idx = t; idx < 5568; idx += 1024) relV[idx] = rel[64*87 + idx];
        for (int idx = t; idx < 5916; idx += 1024) relT[idx] = g_relT[ax][idx];
    }
    __syncthreads();

    {
        const int o0  = t & 255;
        const int qtr = t >> 8;
        const int p0  = qtr*12;
        float2 acc[12];
        #pragma unroll
        for (int p = 0; p < 12; p++) acc[p] = make_float2(0.f, 0.f);
        const float2* Wp = ((const float2*)g_Wint[ax]) + o0;
        #pragma unroll 4
        for (int c = 0; c < 256; c++) {
            float2 w = Wp[c*256];
            const float4* xp = (const float4*)(xs + c*48 + p0);
            #pragma unroll
            for (int qq = 0; qq < 3; qq++) {
                float4 xv = xp[qq];
                fma2(acc[qq*4+0], w, make_float2(xv.x, xv.x));
                fma2(acc[qq*4+1], w, make_float2(xv.y, xv.y));
                fma2(acc[qq*4+2], w, make_float2(xv.z, xv.z));
                fma2(acc[qq*4+3], w, make_float2(xv.w, xv.w));
            }
        }
        #pragma unroll
        for (int sl = 0; sl < 2; sl++) {
            const int o = o0 + sl*256;
            const float b = g_qkvb[ax][o];
            const int g = o >> 7, wi = o & 127;
            float* dst;
            int stride;
            if (wi < 64) { dst = qkT + p0*260 + g*64 + wi; stride = 260; }
            else         { dst = vS + (g*64 + wi - 64)*44 + p0; stride = 1; }
            #pragma unroll
            for (int p = 0; p < 12; p++) {
                if (p0 + p < 44) dst[p*stride] = (sl ? acc[p].y : acc[p].x) + b;
            }
        }
    }
    __syncthreads();

    for (int e = t; e < 7744; e += 1024) {
        int g = e / 1936;
        int r = e - g*1936;
        int i = r / 44;
        int j = r - i*44;
        const float4* qp = (const float4*)(qkT + i*260 + g*64);
        const float4* kp = (const float4*)(qkT + j*260 + g*64 + 32);
        const float4* rq = (const float4*)(relT + (i - j + 43)*68);
        const float4* rk = (const float4*)(relT + (j - i + 43)*68 + 32);
        float2 qk2 = make_float2(0.f,0.f), qr2 = qk2, kr2 = qk2;
        #pragma unroll
        for (int cc = 0; cc < 8; cc++) {
            float4 q4 = qp[cc], k4 = kp[cc], rq4 = rq[cc], rk4 = rk[cc];
            fma2(qk2, make_float2(q4.x,q4.y), make_float2(k4.x,k4.y));
            fma2(qk2, make_float2(q4.z,q4.w), make_float2(k4.z,k4.w));
            fma2(qr2, make_float2(q4.x,q4.y), make_float2(rq4.x,rq4.y));
            fma2(qr2, make_float2(q4.z,q4.w), make_float2(rq4.z,rq4.w));
            fma2(kr2, make_float2(k4.x,k4.y), make_float2(rk4.x,rk4.y));
            fma2(kr2, make_float2(k4.z,k4.w), make_float2(rk4.z,rk4.w));
        }
        float qk = qk2.x + qk2.y, qr = qr2.x + qr2.y, kr = kr2.x + kr2.y;
        simS[e] = g_simA[ax][g]*qk + g_simA[ax][4+g]*qr + g_simA[ax][8+g]*kr + g_simBsum[ax][g];
    }
    __syncthreads();

    {
        const int wid = t >> 5, lane = t & 31;
        #pragma unroll
        for (int k = 0; k < 6; k++) {
            int r = wid + 32*k;
            if (r < 176) {
                float* row = simS + (r/44)*1936 + (r - (r/44)*44)*44;
                float v1 = row[lane];
                float v2 = (lane < 12) ? row[lane+32] : -1e30f;
                float m = fmaxf(v1, v2);
                #pragma unroll
                for (int off = 16; off; off >>= 1) m = fmaxf(m, __shfl_xor_sync(0xffffffffu, m, off));
                float e1 = __expf(v1 - m);
                float e2 = (lane < 12) ? __expf(v2 - m) : 0.f;
                float su = e1 + e2;
                #pragma unroll
                for (int off = 16; off; off >>= 1) su += __shfl_xor_sync(0xffffffffu, su, off);
                float inv = 1.f / su;
                row[lane] = e1 * inv;
                if (lane < 12) row[lane+32] = e2 * inv;
            }
        }
    }
    __syncthreads();

    {
        const int ch = t & 255, qtr = t >> 8;
        const int g = ch >> 6, c = ch & 63;
        float2 v2[22];
        const float4* vp = (const float4*)(vS + ch*44);
        #pragma unroll
        for (int q = 0; q < 11; q++) {
            float4 v4 = vp[q];
            v2[2*q]   = make_float2(v4.x, v4.y);
            v2[2*q+1] = make_float2(v4.z, v4.w);
        }
        const float* rv = relV + c*87;
        const float aSV  = g_outA_sv[ax][ch];
        const float aSVE = g_outA_sve[ax][ch];
        const float bO   = g_outB[ax][ch];
        float* op = out + ((size_t)(n*256 + ch))*1936 + s*44;
        #pragma unroll 1
        for (int ii = 0; ii < 11; ii++) {
            int i = qtr*11 + ii;
            const float2* sr2 = (const float2*)(simS + g*1936 + i*44);
            const float* rvi = rv + i + 43;
            float2 sv2 = make_float2(0.f, 0.f);
            float sve = 0.f;
            #pragma unroll
            for (int p = 0; p < 22; p++) {
                float2 s2 = sr2[p];
                fma2(sv2, s2, v2[p]);
                sve = fmaf(s2.x, rvi[-2*p],   sve);
                sve = fmaf(s2.y, rvi[-2*p-1], sve);
            }
            op[i] = fmaf(aSV, sv2.x + sv2.y, fmaf(aSVE, sve, bO));
        }
    }
}

// ---------------- conv input prep: (g_t2 + g_p) -> padded NHWC bf16 hi/lo ----------------
__global__ void __launch_bounds__(256,1) conv_in_prep()
{
    __shared__ float srow[256*44];
    const int blk = blockIdx.x;
    const int n = blk / 46, py = blk - n*46;
    const int t = threadIdx.x;
    const bool interior = (py >= 1 && py <= 44);
    if (interior) {
        const int yy = py - 1;
        const size_t nb = (size_t)n * IMGSZ + yy*44;
        for (int idx = t; idx < 256*44; idx += 256) {
            int ci = idx / 44, xx = idx - ci*44;
            srow[idx] = g_t2[nb + (size_t)ci*1936 + xx] + g_p[nb + (size_t)ci*1936 + xx];
        }
    }
    __syncthreads();
    const size_t base = ((size_t)MARGIN_LO + (size_t)n * PPX + (size_t)py*48) * 256;
    for (int x = 0; x < 48; x++) {
        float val = 0.f;
        if (interior && x >= 1 && x <= 44) val = srow[t*44 + (x-1)];
        __nv_bfloat16 hi = __float2bfloat16(val);
        float lo = val - __bfloat162float(hi);
        g_xh[base + x*256 + t] = hi;
        g_xl[base + x*256 + t] = __float2bfloat16(lo);
    }
}

// ---------------- tensor-core conv3x3 (mma.sync bf16 hi/lo) ----------------
// smem per stage: Ah[128*48B] Al[128*48B] Bh[16*272B] Bl[16*272B] = 20992 B; 2 stages + bias
#define CSTAGE 20992
#define OFF_AH 0
#define OFF_AL 6144
#define OFF_BH 12288
#define OFF_BL 16640
#define CONV_SMEM (2*CSTAGE + 512)

__global__ void __launch_bounds__(256,1) conv_mma_kernel(const float* __restrict__ conv_b,
                                                         float* __restrict__ out)
{
    extern __shared__ char smc[];
    const uint32_t sbase = smem_to_u32(smc);
    const int t = threadIdx.x;
    const int wid = t >> 5, lane = t & 31;
    const int bb = blockIdx.x;
    const int n = bb / 36;
    const int r_ = bb - n*36;
    const int widx = r_ >> 1, cohalf = r_ & 1;
    const int pxw = widx * 128;
    const int wm = wid & 1, wn = wid >> 1;    // warp tile: 64px x 32co

    float* biasS = (float*)(smc + 2*CSTAGE);
    if (t < 128) biasS[t] = conv_b[cohalf*128 + t];

    const long long arow0 = (long long)MARGIN_LO + (long long)n*PPX + pxw;

    // cp.async chunk loader: 1024 x 16B ops, 4 per thread
    auto load_chunk = [&](int kc, int stage) {
        const int tap = kc >> 4, sub = kc & 15;
        const int offr = (tap/3 - 1)*48 + (tap%3 - 1);
        const long long abase = arow0 + offr;
        const uint32_t sA = sbase + stage*CSTAGE;
        const uint32_t sB = sA + OFF_BH;
        #pragma unroll
        for (int i = 0; i < 4; i++) {
            int o = t + 256*i;
            if (o < 512) {
                int hl   = o & 1;
                int half = (o >> 1) & 1;
                int row  = o >> 2;
                const __nv_bfloat16* g = (hl ? g_xl : g_xh) + ((size_t)(abase + row))*256 + sub*16 + half*8;
                uint32_t d = sA + hl*OFF_AL + row*48 + half*16;
                cp16(d, g);
            } else {
                int o2 = o - 512;
                int hl = o2 & 1;
                int rest = o2 >> 1;            // 0..255
                int krow = rest >> 4, unit = rest & 15;
                const __nv_bfloat16* g = (hl ? g_wl : g_wh)
                    + ((size_t)(tap*256 + sub*16 + krow))*256 + cohalf*128 + unit*8;
                uint32_t d = sB + hl*(OFF_BL-OFF_BH) + krow*272 + unit*16;
                cp16(d, g);
            }
        }
    };

    float acc[4][4][4];
    #pragma unroll
    for (int mf = 0; mf < 4; mf++)
        #pragma unroll
        for (int nf = 0; nf < 4; nf++)
            #pragma unroll
            for (int k = 0; k < 4; k++) acc[mf][nf][k] = 0.f;

    load_chunk(0, 0);
    CP_COMMIT();

    for (int kc = 0; kc < 144; kc++) {
        const int stage = kc & 1;
        if (kc < 143) { load_chunk(kc+1, stage ^ 1); CP_COMMIT(); CP_WAIT(1); }
        else          { CP_WAIT(0); }
        __syncthreads();

        const uint32_t sA = sbase + stage*CSTAGE;
        const uint32_t sB = sA + OFF_BH;

        uint32_t Ah[4][4], Al[4][4], Bh[4][2], Bl[4][2];
        #pragma unroll
        for (int mf = 0; mf < 4; mf++) {
            uint32_t a_off = (wm*64 + mf*16 + (lane & 15))*48 + (lane >> 4)*16;
            ldsm_x4(Ah[mf], sA + OFF_AH + a_off);
            ldsm_x4(Al[mf], sA + OFF_AL + a_off);
        }
        #pragma unroll
        for (int nf = 0; nf < 4; nf++) {
            uint32_t b_off = (lane & 15)*272 + (wn*32 + nf*8)*2;
            ldsm_x2_t(Bh[nf], sB + b_off);
            ldsm_x2_t(Bl[nf], sB + (OFF_BL - OFF_BH) + b_off);
        }
        #pragma unroll
        for (int mf = 0; mf < 4; mf++)
            #pragma unroll
            for (int nf = 0; nf < 4; nf++) {
                mma_bf16(acc[mf][nf], Ah[mf], Bh[nf]);
                mma_bf16(acc[mf][nf], Ah[mf], Bl[nf]);
                mma_bf16(acc[mf][nf], Al[mf], Bh[nf]);
            }
        __syncthreads();
    }

    // epilogue: scatter valid pixels to output with bias
    const int b_ = n >> 2, i2 = (n >> 1) & 1, j2 = n & 1;
    #pragma unroll
    for (int mf = 0; mf < 4; mf++) {
        #pragma unroll
        for (int half = 0; half < 2; half++) {
            int px = pxw + wm*64 + mf*16 + (lane >> 2) + half*8;
            int py = px / 48, pxx = px - py*48;
            bool valid = (py >= 1 && py <= 44) && (pxx >= 1 && pxx <= 44);
            if (!valid) continue;
            size_t ob = ((size_t)(b_*256))*7744 + (size_t)(i2*44 + (py-1))*88 + j2*44 + (pxx-1);
            #pragma unroll
            for (int nf = 0; nf < 4; nf++) {
                int col = wn*32 + nf*8 + (lane & 3)*2;   // within 128
                int co = cohalf*128 + col;
                out[ob + (size_t)co*7744]     = acc[mf][nf][half*2+0] + biasS[col];
                out[ob + (size_t)(co+1)*7744] = acc[mf][nf][half*2+1] + biasS[col+1];
            }
        }
    }
}

// ---------------- launch ----------------
extern "C" void kernel_launch(void* const* d_in, const int* in_sizes, int n_in,
                              void* d_out, int out_size)
{
    const float* x        = (const float*)d_in[0];
    const float* h_qkv_w  = (const float*)d_in[1];
    const float* h_bn_qkv = (const float*)d_in[2];
    const float* h_bn_sim = (const float*)d_in[3];
    const float* h_bn_out = (const float*)d_in[4];
    const float* h_rel    = (const float*)d_in[5];
    const float* w_qkv_w  = (const float*)d_in[6];
    const float* w_bn_qkv = (const float*)d_in[7];
    const float* w_bn_sim = (const float*)d_in[8];
    const float* w_bn_out = (const float*)d_in[9];
    const float* w_rel    = (const float*)d_in[10];
    const float* conv_w   = (const float*)d_in[11];
    const float* conv_b   = (const float*)d_in[12];
    float* out = (float*)d_out;

    cudaFuncSetAttribute(axial_kernel,    cudaFuncAttributeMaxDynamicSharedMemorySize, AX_SMEM);
    cudaFuncSetAttribute(conv_mma_kernel, cudaFuncAttributeMaxDynamicSharedMemorySize, CONV_SMEM);

    prep_kernel<<<(256*256*9 + 255)/256, 256>>>(h_qkv_w, h_bn_qkv, h_bn_sim, h_bn_out,
                                                w_qkv_w, w_bn_qkv, w_bn_sim, w_bn_out,
                                                conv_w, h_rel, w_rel);
    patchify_kernel<<<NPATCH*256, 256>>>(x);
    axial_kernel<<<NB, 1024, AX_SMEM>>>(h_rel, 0);
    transpose_kernel<<<NPATCH*256, 256>>>();
    axial_kernel<<<NB, 1024, AX_SMEM>>>(w_rel, 1);
    conv_in_prep<<<NPATCH*46, 256>>>();
    conv_mma_kernel<<<NPATCH*36, 256, CONV_SMEM>>>(conv_b, out);
}

// round 6
// speedup vs baseline: 1.8077x; 1.1492x over previous
#include <cuda_runtime.h>
#include <cuda_bf16.h>
#include <math.h>
#include <cstdint>

#define EPS 1e-5f
#define NPATCH 64
#define HS 44
#define NB (NPATCH*HS)          // 2816
#define PLANE 1936
#define IMGSZ (256*1936)

// padded conv geometry
#define PPX 2208
#define MARGIN_LO 128
#define XROWS (MARGIN_LO + NPATCH*PPX + 256)

typedef unsigned long long ull;
__device__ __forceinline__ void fma2(float2 &d, float2 a, float2 b) {
    asm("fma.rn.f32x2 %0, %1, %2, %0;"
        : "+l"(reinterpret_cast<ull&>(d))
        : "l"(reinterpret_cast<ull&>(a)), "l"(reinterpret_cast<ull&>(b)));
}

// ---------------- mma / ldmatrix / cp.async helpers ----------------
__device__ __forceinline__ uint32_t smem_to_u32(const void* p) {
    uint32_t a;
    asm("{ .reg .u64 t; cvta.to.shared.u64 t, %1; cvt.u32.u64 %0, t; }" : "=r"(a) : "l"(p));
    return a;
}
__device__ __forceinline__ void ldsm_x4(uint32_t a[4], uint32_t addr) {
    asm volatile("ldmatrix.sync.aligned.m8n8.x4.shared.b16 {%0,%1,%2,%3}, [%4];"
        : "=r"(a[0]),"=r"(a[1]),"=r"(a[2]),"=r"(a[3]) : "r"(addr));
}
__device__ __forceinline__ void ldsm_x2_t(uint32_t b[2], uint32_t addr) {
    asm volatile("ldmatrix.sync.aligned.m8n8.x2.trans.shared.b16 {%0,%1}, [%2];"
        : "=r"(b[0]),"=r"(b[1]) : "r"(addr));
}
__device__ __forceinline__ void mma_bf16(float c[4], const uint32_t a[4], const uint32_t b[2]) {
    asm volatile("mma.sync.aligned.m16n8k16.row.col.f32.bf16.bf16.f32 "
        "{%0,%1,%2,%3}, {%4,%5,%6,%7}, {%8,%9}, {%0,%1,%2,%3};"
        : "+f"(c[0]),"+f"(c[1]),"+f"(c[2]),"+f"(c[3])
        : "r"(a[0]),"r"(a[1]),"r"(a[2]),"r"(a[3]), "r"(b[0]),"r"(b[1]));
}
__device__ __forceinline__ void cp16(uint32_t saddr, const void* g) {
    asm volatile("cp.async.cg.shared.global [%0], [%1], 16;" :: "r"(saddr), "l"(g));
}
#define CP_COMMIT() asm volatile("cp.async.commit_group;" ::: "memory")
#define CP_WAIT(n)  asm volatile("cp.async.wait_group %0;" :: "n"(n) : "memory")

// ---------------- static device scratch ----------------
__device__ float g_p [NPATCH*IMGSZ];   // patchified input [c][y][x] (residual)
__device__ float g_t1[NPATCH*IMGSZ];   // height-axial out [c][x][y]
__device__ float g_t2[NPATCH*IMGSZ];   // width-axial out [c][y][x]
__device__ float g_qkv[(size_t)NPATCH*512*PLANE];   // qkv GEMM result [n][o][pos]
__device__ float g_qkvb[2][512];
__device__ float g_simA[2][12];
__device__ float g_simBsum[2][4];
__device__ float g_outA_sv[2][256];
__device__ float g_outA_sve[2][256];
__device__ float g_outB[2][256];
__device__ float g_relT[2][87*68];
// tensor-core operand buffers
__device__ __align__(1024) __nv_bfloat16 g_xbh[(size_t)NPATCH*256*PLANE + 256]; // x for qkv gemm [n][c][pos] hi
__device__ __align__(1024) __nv_bfloat16 g_xbl[(size_t)NPATCH*256*PLANE + 256]; // lo
__device__ __align__(1024) __nv_bfloat16 g_qwh[2][512*256];  // qkv W [ax][o][ci] hi
__device__ __align__(1024) __nv_bfloat16 g_qwl[2][512*256];  // lo
__device__ __align__(1024) __nv_bfloat16 g_xh[(size_t)XROWS*256];  // conv activations hi
__device__ __align__(1024) __nv_bfloat16 g_xl[(size_t)XROWS*256];
__device__ __align__(1024) __nv_bfloat16 g_wh[9*256*256];          // conv W [tap][ci][co]
__device__ __align__(1024) __nv_bfloat16 g_wl[9*256*256];

// ---------------- prep ----------------
__global__ void prep_kernel(const float* __restrict__ h_qkv_w, const float* __restrict__ h_bn_qkv,
                            const float* __restrict__ h_bn_sim, const float* __restrict__ h_bn_out,
                            const float* __restrict__ w_qkv_w, const float* __restrict__ w_bn_qkv,
                            const float* __restrict__ w_bn_sim, const float* __restrict__ w_bn_out,
                            const float* __restrict__ conv_w,
                            const float* __restrict__ h_rel, const float* __restrict__ w_rel)
{
    int idx = blockIdx.x * blockDim.x + threadIdx.x;

    if (idx < 256*256*9) {   // conv_w [co][ci][tap] -> [tap][ci][co] hi/lo
        int co  = idx / 2304;
        int rem = idx - co*2304;
        int ci  = rem / 9;
        int tap = rem - ci*9;
        float w = conv_w[idx];
        __nv_bfloat16 hi = __float2bfloat16(w);
        float lo = w - __bfloat162float(hi);
        g_wh[(tap*256 + ci)*256 + co] = hi;
        g_wl[(tap*256 + ci)*256 + co] = __float2bfloat16(lo);
    }
    if (idx < MARGIN_LO*256) {
        g_xh[idx] = __float2bfloat16(0.f);
        g_xl[idx] = __float2bfloat16(0.f);
    }
    if (idx < 256*256) {
        size_t off = (size_t)(MARGIN_LO + NPATCH*PPX)*256 + idx;
        g_xh[off] = __float2bfloat16(0.f);
        g_xl[off] = __float2bfloat16(0.f);
    }
    if (idx < 2*131072) {    // qkv weights folded, [ax][o][ci] hi/lo
        int ax = idx >> 17;
        int r  = idx & 131071;
        int o  = r & 511;
        int c  = r >> 9;
        const float* bn = ax ? w_bn_qkv : h_bn_qkv;
        const float* W  = ax ? w_qkv_w : h_qkv_w;
        float s = bn[o] * rsqrtf(bn[1536+o] + EPS);
        float wv = W[o*256 + c] * s;
        __nv_bfloat16 hi = __float2bfloat16(wv);
        float lo = wv - __bfloat162float(hi);
        g_qwh[ax][o*256 + c] = hi;
        g_qwl[ax][o*256 + c] = __float2bfloat16(lo);
        if (c == 0) g_qkvb[ax][o] = bn[512+o] - bn[1024+o]*s;
    }
    if (idx < 8) {
        int ax = idx >> 2, g = idx & 3;
        const float* bs = ax ? w_bn_sim : h_bn_sim;
        float shsum = 0.f;
        #pragma unroll
        for (int p = 0; p < 3; p++) {
            int ch = p*4 + g;
            float s = bs[ch] * rsqrtf(bs[36+ch] + EPS);
            g_simA[ax][p*4+g] = (p == 0 ? 1.f : 0.1f) * s;
            shsum += bs[12+ch] - bs[24+ch]*s;
        }
        g_simBsum[ax][g] = shsum;
    }
    if (idx < 512) {
        int ax = idx >> 8, cc = idx & 255;
        const float* bo = ax ? w_bn_out : h_bn_out;
        int o1 = 2*cc, o2 = 2*cc + 1;
        float s1 = bo[o1] * rsqrtf(bo[1536+o1] + EPS);
        float s2 = bo[o2] * rsqrtf(bo[1536+o2] + EPS);
        g_outA_sv[ax][cc]  = s1;
        g_outA_sve[ax][cc] = 0.1f * s2;
        g_outB[ax][cc] = (bo[512+o1] - bo[1024+o1]*s1) + (bo[512+o2] - bo[1024+o2]*s2);
    }
    if (idx < 2*5568) {
        int ax = idx / 5568, r = idx - ax*5568;
        int d = r >> 6, c = r & 63;
        const float* rl = ax ? w_rel : h_rel;
        g_relT[ax][d*68 + c] = rl[c*87 + d];
    }
}

// ---------------- patchify: g_p float + x bf16 hi/lo in [c][x][y] ----------------
__global__ void __launch_bounds__(256,1) patchify_kernel(const float* __restrict__ x)
{
    __shared__ float tile[44*45];
    const int b = blockIdx.x;            // np*256 + c
    const int np = b >> 8, c = b & 255;
    const int bb_ = np >> 2, i2 = (np >> 1) & 1, j2 = np & 1;
    const float* src = x + ((size_t)(bb_*256 + c)*88 + i2*44)*88 + j2*44;
    float* dp = g_p + (size_t)b*1936;
    const int t = threadIdx.x;
    for (int idx = t; idx < 1936; idx += 256) {
        int y = idx / 44, xq = idx - y*44;
        float v = src[y*88 + xq];
        dp[idx] = v;
        tile[xq*45 + y] = v;
    }
    __syncthreads();
    const size_t base = (size_t)b*1936;
    for (int idx = t; idx < 1936; idx += 256) {
        int r = idx / 44, col = idx - r*44;
        float val = tile[r*45 + col];          // [x][y] layout
        __nv_bfloat16 hi = __float2bfloat16(val);
        g_xbh[base + idx] = hi;
        g_xbl[base + idx] = __float2bfloat16(val - __bfloat162float(hi));
    }
}

// ---------------- transpose g_t1 [c][x][y] -> bf16 hi/lo [c][y][x] ----------------
__global__ void __launch_bounds__(256,1) transpose_kernel()
{
    __shared__ float tile[44*45];
    const int b = blockIdx.x;
    const float* src = g_t1 + (size_t)b*1936;
    const int t = threadIdx.x;
    for (int idx = t; idx < 1936; idx += 256) {
        int r = idx / 44, col = idx - r*44;
        tile[col*45 + r] = src[idx];
    }
    __syncthreads();
    const size_t base = (size_t)b*1936;
    for (int idx = t; idx < 1936; idx += 256) {
        int r = idx / 44, col = idx - r*44;
        float val = tile[r*45 + col];          // [y][x] layout
        __nv_bfloat16 hi = __float2bfloat16(val);
        g_xbh[base + idx] = hi;
        g_xbl[base + idx] = __float2bfloat16(val - __bfloat162float(hi));
    }
}

// ---------------- qkv GEMM (mma.sync bf16 hi/lo): QKV[512][1936] = W @ X + b ----------------
#define CSTAGE 20992
#define OFF_AL 6144
#define OFF_BH 12288
#define OFF_BL 16640
#define GEMM_SMEM (2*CSTAGE)

__global__ void __launch_bounds__(256,1) qkv_gemm_kernel(int ax)
{
    extern __shared__ char smc[];
    const uint32_t sbase = smem_to_u32(smc);
    const int t = threadIdx.x;
    const int wid = t >> 5, lane = t & 31;
    const int ntile = blockIdx.x;        // 0..15 (pos tiles of 128; covers 1936)
    const int mtile = blockIdx.y;        // 0..3  (o tiles of 128)
    const int n     = blockIdx.z;        // patch
    const int pxw = ntile * 128;
    const int mrow0 = mtile * 128;
    const int wm = wid & 1, wn = wid >> 1;
    const __nv_bfloat16* qwh = g_qwh[ax];
    const __nv_bfloat16* qwl = g_qwl[ax];

    auto load_chunk = [&](int kc, int stage) {
        const uint32_t sA = sbase + stage*CSTAGE;
        const uint32_t sB = sA + OFF_BH;
        #pragma unroll
        for (int i = 0; i < 4; i++) {
            int o = t + 256*i;
            if (o < 512) {
                int hl   = o & 1;
                int half = (o >> 1) & 1;
                int row  = o >> 2;
                const __nv_bfloat16* g = (hl ? qwl : qwh) + (size_t)(mrow0 + row)*256 + kc*16 + half*8;
                cp16(sA + hl*OFF_AL + row*48 + half*16, g);
            } else {
                int o2 = o - 512;
                int hl = o2 & 1;
                int rest = o2 >> 1;
                int krow = rest >> 4, unit = rest & 15;
                const __nv_bfloat16* g = (hl ? g_xbl : g_xbh)
                    + ((size_t)(n*256 + kc*16 + krow))*1936 + pxw + unit*8;
                cp16(sB + hl*(OFF_BL-OFF_BH) + krow*272 + unit*16, g);
            }
        }
    };

    float acc[4][4][4];
    #pragma unroll
    for (int mf = 0; mf < 4; mf++)
        #pragma unroll
        for (int nf = 0; nf < 4; nf++)
            #pragma unroll
            for (int k = 0; k < 4; k++) acc[mf][nf][k] = 0.f;

    load_chunk(0, 0);
    CP_COMMIT();

    for (int kc = 0; kc < 16; kc++) {
        const int stage = kc & 1;
        if (kc < 15) { load_chunk(kc+1, stage ^ 1); CP_COMMIT(); CP_WAIT(1); }
        else         { CP_WAIT(0); }
        __syncthreads();

        const uint32_t sA = sbase + stage*CSTAGE;
        const uint32_t sB = sA + OFF_BH;

        uint32_t Ah[4][4], Al[4][4], Bh[4][2], Bl[4][2];
        #pragma unroll
        for (int mf = 0; mf < 4; mf++) {
            uint32_t a_off = (wm*64 + mf*16 + (lane & 15))*48 + (lane >> 4)*16;
            ldsm_x4(Ah[mf], sA + a_off);
            ldsm_x4(Al[mf], sA + OFF_AL + a_off);
        }
        #pragma unroll
        for (int nf = 0; nf < 4; nf++) {
            uint32_t b_off = (lane & 15)*272 + (wn*32 + nf*8)*2;
            ldsm_x2_t(Bh[nf], sB + b_off);
            ldsm_x2_t(Bl[nf], sB + (OFF_BL - OFF_BH) + b_off);
        }
        #pragma unroll
        for (int mf = 0; mf < 4; mf++)
            #pragma unroll
            for (int nf = 0; nf < 4; nf++) {
                mma_bf16(acc[mf][nf], Ah[mf], Bh[nf]);
                mma_bf16(acc[mf][nf], Ah[mf], Bl[nf]);
                mma_bf16(acc[mf][nf], Al[mf], Bh[nf]);
            }
        __syncthreads();
    }

    // epilogue: stage 64 rows at a time through smem, coalesced stores + bias
    float* stg = (float*)smc;   // [64][132]
    #pragma unroll
    for (int h = 0; h < 2; h++) {
        __syncthreads();
        if (wm == h) {
            #pragma unroll
            for (int mf = 0; mf < 4; mf++) {
                int r0 = mf*16 + (lane >> 2);
                #pragma unroll
                for (int nf = 0; nf < 4; nf++) {
                    int c0 = wn*32 + nf*8 + (lane & 3)*2;
                    stg[r0*132 + c0]     = acc[mf][nf][0];
                    stg[r0*132 + c0+1]   = acc[mf][nf][1];
                    stg[(r0+8)*132 + c0]   = acc[mf][nf][2];
                    stg[(r0+8)*132 + c0+1] = acc[mf][nf][3];
                }
            }
        }
        __syncthreads();
        for (int idx = t; idx < 64*32; idx += 256) {
            int r = idx >> 5, q4 = idx & 31;
            int pos = pxw + q4*4;
            if (pos + 4 <= 1936) {
                int o = mrow0 + h*64 + r;
                float bias = g_qkvb[ax][o];
                float4 v = *(float4*)(stg + r*132 + q4*4);
                v.x += bias; v.y += bias; v.z += bias; v.w += bias;
                *(float4*)(g_qkv + ((size_t)n*512 + o)*1936 + pos) = v;
            }
        }
    }
}

// ---------------- fused axial attention v4: reads precomputed qkv ----------------
// smem floats: qkT[44][260]@0 | vS[256][44]@11440 | relV[64][87]@22704 |
//              relT[87][68]@28272 | sim[4][44][44]@34188
#define OFF_V    11440
#define OFF_RELV 22704
#define OFF_RELT 28272
#define OFF_SIM  34188
#define AX_SMEM  (41932*4)

__global__ void __launch_bounds__(1024,1) axial_kernel(const float* __restrict__ rel, int ax)
{
    float* out = ax ? g_t2 : g_t1;

    extern __shared__ float sm[];
    float* qkT  = sm;
    float* vS   = sm + OFF_V;
    float* relV = sm + OFF_RELV;
    float* relT = sm + OFF_RELT;
    float* simS = sm + OFF_SIM;

    const int t  = threadIdx.x;
    const int bb = blockIdx.x;
    const int n  = bb / 44;
    const int s  = bb - n*44;

    // load qkv slice + rel tables
    {
        const float* qsrc = g_qkv + (size_t)n*512*1936 + s*44;
        for (int idx = t; idx < 5632; idx += 1024) {
            int o = idx / 11, q = idx - o*11;
            float4 v4 = *(const float4*)(qsrc + (size_t)o*1936 + q*4);
            int g = o >> 7, wi = o & 127;
            if (wi < 64) {
                int col = g*64 + wi;
                qkT[(q*4+0)*260 + col] = v4.x;
                qkT[(q*4+1)*260 + col] = v4.y;
                qkT[(q*4+2)*260 + col] = v4.z;
                qkT[(q*4+3)*260 + col] = v4.w;
            } else {
                *(float4*)(vS + (g*64 + wi - 64)*44 + q*4) = v4;
            }
        }
        for (int idx = t; idx < 5568; idx += 1024) relV[idx] = rel[64*87 + idx];
        for (int idx = t; idx < 5916; idx += 1024) relT[idx] = g_relT[ax][idx];
    }
    __syncthreads();

    // sim
    for (int e = t; e < 7744; e += 1024) {
        int g = e / 1936;
        int r = e - g*1936;
        int i = r / 44;
        int j = r - i*44;
        const float4* qp = (const float4*)(qkT + i*260 + g*64);
        const float4* kp = (const float4*)(qkT + j*260 + g*64 + 32);
        const float4* rq = (const float4*)(relT + (i - j + 43)*68);
        const float4* rk = (const float4*)(relT + (j - i + 43)*68 + 32);
        float2 qk2 = make_float2(0.f,0.f), qr2 = qk2, kr2 = qk2;
        #pragma unroll
        for (int cc = 0; cc < 8; cc++) {
            float4 q4 = qp[cc], k4 = kp[cc], rq4 = rq[cc], rk4 = rk[cc];
            fma2(qk2, make_float2(q4.x,q4.y), make_float2(k4.x,k4.y));
            fma2(qk2, make_float2(q4.z,q4.w), make_float2(k4.z,k4.w));
            fma2(qr2, make_float2(q4.x,q4.y), make_float2(rq4.x,rq4.y));
            fma2(qr2, make_float2(q4.z,q4.w), make_float2(rq4.z,rq4.w));
            fma2(kr2, make_float2(k4.x,k4.y), make_float2(rk4.x,rk4.y));
            fma2(kr2, make_float2(k4.z,k4.w), make_float2(rk4.z,rk4.w));
        }
        float qk = qk2.x + qk2.y, qr = qr2.x + qr2.y, kr = kr2.x + kr2.y;
        simS[e] = g_simA[ax][g]*qk + g_simA[ax][4+g]*qr + g_simA[ax][8+g]*kr + g_simBsum[ax][g];
    }
    __syncthreads();

    // softmax: warp per row
    {
        const int wid = t >> 5, lane = t & 31;
        #pragma unroll
        for (int k = 0; k < 6; k++) {
            int r = wid + 32*k;
            if (r < 176) {
                float* row = simS + (r/44)*1936 + (r - (r/44)*44)*44;
                float v1 = row[lane];
                float v2 = (lane < 12) ? row[lane+32] : -1e30f;
                float m = fmaxf(v1, v2);
                #pragma unroll
                for (int off = 16; off; off >>= 1) m = fmaxf(m, __shfl_xor_sync(0xffffffffu, m, off));
                float e1 = __expf(v1 - m);
                float e2 = (lane < 12) ? __expf(v2 - m) : 0.f;
                float su = e1 + e2;
                #pragma unroll
                for (int off = 16; off; off >>= 1) su += __shfl_xor_sync(0xffffffffu, su, off);
                float inv = 1.f / su;
                row[lane] = e1 * inv;
                if (lane < 12) row[lane+32] = e2 * inv;
            }
        }
    }
    __syncthreads();

    // output
    {
        const int ch = t & 255, qtr = t >> 8;
        const int g = ch >> 6, c = ch & 63;
        float2 v2[22];
        const float4* vp = (const float4*)(vS + ch*44);
        #pragma unroll
        for (int q = 0; q < 11; q++) {
            float4 v4 = vp[q];
            v2[2*q]   = make_float2(v4.x, v4.y);
            v2[2*q+1] = make_float2(v4.z, v4.w);
        }
        const float* rv = relV + c*87;
        const float aSV  = g_outA_sv[ax][ch];
        const float aSVE = g_outA_sve[ax][ch];
        const float bO   = g_outB[ax][ch];
        float* op = out + ((size_t)(n*256 + ch))*1936 + s*44;
        #pragma unroll 1
        for (int ii = 0; ii < 11; ii++) {
            int i = qtr*11 + ii;
            const float2* sr2 = (const float2*)(simS + g*1936 + i*44);
            const float* rvi = rv + i + 43;
            float2 sv2 = make_float2(0.f, 0.f);
            float sve = 0.f;
            #pragma unroll
            for (int p = 0; p < 22; p++) {
                float2 s2 = sr2[p];
                fma2(sv2, s2, v2[p]);
                sve = fmaf(s2.x, rvi[-2*p],   sve);
                sve = fmaf(s2.y, rvi[-2*p-1], sve);
            }
            op[i] = fmaf(aSV, sv2.x + sv2.y, fmaf(aSVE, sve, bO));
        }
    }
}

// ---------------- conv input prep ----------------
__global__ void __launch_bounds__(256,1) conv_in_prep()
{
    __shared__ float srow[256*44];
    const int blk = blockIdx.x;
    const int n = blk / 46, py = blk - n*46;
    const int t = threadIdx.x;
    const bool interior = (py >= 1 && py <= 44);
    if (interior) {
        const int yy = py - 1;
        const size_t nb = (size_t)n * IMGSZ + yy*44;
        for (int idx = t; idx < 256*44; idx += 256) {
            int ci = idx / 44, xx = idx - ci*44;
            srow[idx] = g_t2[nb + (size_t)ci*1936 + xx] + g_p[nb + (size_t)ci*1936 + xx];
        }
    }
    __syncthreads();
    const size_t base = ((size_t)MARGIN_LO + (size_t)n * PPX + (size_t)py*48) * 256;
    for (int x = 0; x < 48; x++) {
        float val = 0.f;
        if (interior && x >= 1 && x <= 44) val = srow[t*44 + (x-1)];
        __nv_bfloat16 hi = __float2bfloat16(val);
        float lo = val - __bfloat162float(hi);
        g_xh[base + x*256 + t] = hi;
        g_xl[base + x*256 + t] = __float2bfloat16(lo);
    }
}

// ---------------- tensor-core conv3x3 (unchanged from R5) ----------------
#define CONV_SMEM (2*CSTAGE + 512)

__global__ void __launch_bounds__(256,1) conv_mma_kernel(const float* __restrict__ conv_b,
                                                         float* __restrict__ out)
{
    extern __shared__ char smc[];
    const uint32_t sbase = smem_to_u32(smc);
    const int t = threadIdx.x;
    const int wid = t >> 5, lane = t & 31;
    const int bb = blockIdx.x;
    const int n = bb / 36;
    const int r_ = bb - n*36;
    const int widx = r_ >> 1, cohalf = r_ & 1;
    const int pxw = widx * 128;
    const int wm = wid & 1, wn = wid >> 1;

    float* biasS = (float*)(smc + 2*CSTAGE);
    if (t < 128) biasS[t] = conv_b[cohalf*128 + t];

    const long long arow0 = (long long)MARGIN_LO + (long long)n*PPX + pxw;

    auto load_chunk = [&](int kc, int stage) {
        const int tap = kc >> 4, sub = kc & 15;
        const int offr = (tap/3 - 1)*48 + (tap%3 - 1);
        const long long abase = arow0 + offr;
        const uint32_t sA = sbase + stage*CSTAGE;
        const uint32_t sB = sA + OFF_BH;
        #pragma unroll
        for (int i = 0; i < 4; i++) {
            int o = t + 256*i;
            if (o < 512) {
                int hl   = o & 1;
                int half = (o >> 1) & 1;
                int row  = o >> 2;
                const __nv_bfloat16* g = (hl ? g_xl : g_xh) + ((size_t)(abase + row))*256 + sub*16 + half*8;
                cp16(sA + hl*OFF_AL + row*48 + half*16, g);
            } else {
                int o2 = o - 512;
                int hl = o2 & 1;
                int rest = o2 >> 1;
                int krow = rest >> 4, unit = rest & 15;
                const __nv_bfloat16* g = (hl ? g_wl : g_wh)
                    + ((size_t)(tap*256 + sub*16 + krow))*256 + cohalf*128 + unit*8;
                cp16(sB + hl*(OFF_BL-OFF_BH) + krow*272 + unit*16, g);
            }
        }
    };

    float acc[4][4][4];
    #pragma unroll
    for (int mf = 0; mf < 4; mf++)
        #pragma unroll
        for (int nf = 0; nf < 4; nf++)
            #pragma unroll
            for (int k = 0; k < 4; k++) acc[mf][nf][k] = 0.f;

    load_chunk(0, 0);
    CP_COMMIT();

    for (int kc = 0; kc < 144; kc++) {
        const int stage = kc & 1;
        if (kc < 143) { load_chunk(kc+1, stage ^ 1); CP_COMMIT(); CP_WAIT(1); }
        else          { CP_WAIT(0); }
        __syncthreads();

        const uint32_t sA = sbase + stage*CSTAGE;
        const uint32_t sB = sA + OFF_BH;

        uint32_t Ah[4][4], Al[4][4], Bh[4][2], Bl[4][2];
        #pragma unroll
        for (int mf = 0; mf < 4; mf++) {
            uint32_t a_off = (wm*64 + mf*16 + (lane & 15))*48 + (lane >> 4)*16;
            ldsm_x4(Ah[mf], sA + a_off);
            ldsm_x4(Al[mf], sA + OFF_AL + a_off);
        }
        #pragma unroll
        for (int nf = 0; nf < 4; nf++) {
            uint32_t b_off = (lane & 15)*272 + (wn*32 + nf*8)*2;
            ldsm_x2_t(Bh[nf], sB + b_off);
            ldsm_x2_t(Bl[nf], sB + (OFF_BL - OFF_BH) + b_off);
        }
        #pragma unroll
        for (int mf = 0; mf < 4; mf++)
            #pragma unroll
            for (int nf = 0; nf < 4; nf++) {
                mma_bf16(acc[mf][nf], Ah[mf], Bh[nf]);
                mma_bf16(acc[mf][nf], Ah[mf], Bl[nf]);
                mma_bf16(acc[mf][nf], Al[mf], Bh[nf]);
            }
        __syncthreads();
    }

    const int b_ = n >> 2, i2 = (n >> 1) & 1, j2 = n & 1;
    #pragma unroll
    for (int mf = 0; mf < 4; mf++) {
        #pragma unroll
        for (int half = 0; half < 2; half++) {
            int px = pxw + wm*64 + mf*16 + (lane >> 2) + half*8;
            int py = px / 48, pxx = px - py*48;
            bool valid = (py >= 1 && py <= 44) && (pxx >= 1 && pxx <= 44);
            if (!valid) continue;
            size_t ob = ((size_t)(b_*256))*7744 + (size_t)(i2*44 + (py-1))*88 + j2*44 + (pxx-1);
            #pragma unroll
            for (int nf = 0; nf < 4; nf++) {
                int col = wn*32 + nf*8 + (lane & 3)*2;
                int co = cohalf*128 + col;
                out[ob + (size_t)co*7744]     = acc[mf][nf][half*2+0] + biasS[col];
                out[ob + (size_t)(co+1)*7744] = acc[mf][nf][half*2+1] + biasS[col+1];
            }
        }
    }
}

// ---------------- launch ----------------
extern "C" void kernel_launch(void* const* d_in, const int* in_sizes, int n_in,
                              void* d_out, int out_size)
{
    const float* x        = (const float*)d_in[0];
    const float* h_qkv_w  = (const float*)d_in[1];
    const float* h_bn_qkv = (const float*)d_in[2];
    const float* h_bn_sim = (const float*)d_in[3];
    const float* h_bn_out = (const float*)d_in[4];
    const float* h_rel    = (const float*)d_in[5];
    const float* w_qkv_w  = (const float*)d_in[6];
    const float* w_bn_qkv = (const float*)d_in[7];
    const float* w_bn_sim = (const float*)d_in[8];
    const float* w_bn_out = (const float*)d_in[9];
    const float* w_rel    = (const float*)d_in[10];
    const float* conv_w   = (const float*)d_in[11];
    const float* conv_b   = (const float*)d_in[12];
    float* out = (float*)d_out;

    cudaFuncSetAttribute(axial_kernel,    cudaFuncAttributeMaxDynamicSharedMemorySize, AX_SMEM);
    cudaFuncSetAttribute(qkv_gemm_kernel, cudaFuncAttributeMaxDynamicSharedMemorySize, GEMM_SMEM);
    cudaFuncSetAttribute(conv_mma_kernel, cudaFuncAttributeMaxDynamicSharedMemorySize, CONV_SMEM);

    prep_kernel<<<(256*256*9 + 255)/256, 256>>>(h_qkv_w, h_bn_qkv, h_bn_sim, h_bn_out,
                                                w_qkv_w, w_bn_qkv, w_bn_sim, w_bn_out,
                                                conv_w, h_rel, w_rel);
    patchify_kernel<<<NPATCH*256, 256>>>(x);
    qkv_gemm_kernel<<<dim3(16,4,NPATCH), 256, GEMM_SMEM>>>(0);
    axial_kernel<<<NB, 1024, AX_SMEM>>>(h_rel, 0);
    transpose_kernel<<<NPATCH*256, 256>>>();
    qkv_gemm_kernel<<<dim3(16,4,NPATCH), 256, GEMM_SMEM>>>(1);
    axial_kernel<<<NB, 1024, AX_SMEM>>>(w_rel, 1);
    conv_in_prep<<<NPATCH*46, 256>>>();
    conv_mma_kernel<<<NPATCH*36, 256, CONV_SMEM>>>(conv_b, out);
}

// round 7
// speedup vs baseline: 1.8101x; 1.0013x over previous
#include <cuda_runtime.h>
#include <cuda_bf16.h>
#include <cuda_fp16.h>
#include <math.h>
#include <cstdint>

#define EPS 1e-5f
#define NPATCH 64
#define HS 44
#define NB (NPATCH*HS)          // 2816
#define PLANE 1936
#define IMGSZ (256*1936)

// padded conv geometry
#define PPX 2208
#define MARGIN_LO 128
#define XROWS (MARGIN_LO + NPATCH*PPX + 256)

typedef unsigned long long ull;
__device__ __forceinline__ void fma2(float2 &d, float2 a, float2 b) {
    asm("fma.rn.f32x2 %0, %1, %2, %0;"
        : "+l"(reinterpret_cast<ull&>(d))
        : "l"(reinterpret_cast<ull&>(a)), "l"(reinterpret_cast<ull&>(b)));
}
__device__ __forceinline__ float2 h2f(uint32_t u) {
    __half2 h = *reinterpret_cast<__half2*>(&u);
    return __half22float2(h);
}

// ---------------- mma / ldmatrix / cp.async helpers ----------------
__device__ __forceinline__ uint32_t smem_to_u32(const void* p) {
    uint32_t a;
    asm("{ .reg .u64 t; cvta.to.shared.u64 t, %1; cvt.u32.u64 %0, t; }" : "=r"(a) : "l"(p));
    return a;
}
__device__ __forceinline__ void ldsm_x4(uint32_t a[4], uint32_t addr) {
    asm volatile("ldmatrix.sync.aligned.m8n8.x4.shared.b16 {%0,%1,%2,%3}, [%4];"
        : "=r"(a[0]),"=r"(a[1]),"=r"(a[2]),"=r"(a[3]) : "r"(addr));
}
__device__ __forceinline__ void ldsm_x2_t(uint32_t b[2], uint32_t addr) {
    asm volatile("ldmatrix.sync.aligned.m8n8.x2.trans.shared.b16 {%0,%1}, [%2];"
        : "=r"(b[0]),"=r"(b[1]) : "r"(addr));
}
__device__ __forceinline__ void mma_bf16(float c[4], const uint32_t a[4], const uint32_t b[2]) {
    asm volatile("mma.sync.aligned.m16n8k16.row.col.f32.bf16.bf16.f32 "
        "{%0,%1,%2,%3}, {%4,%5,%6,%7}, {%8,%9}, {%0,%1,%2,%3};"
        : "+f"(c[0]),"+f"(c[1]),"+f"(c[2]),"+f"(c[3])
        : "r"(a[0]),"r"(a[1]),"r"(a[2]),"r"(a[3]), "r"(b[0]),"r"(b[1]));
}
__device__ __forceinline__ void cp16(uint32_t saddr, const void* g) {
    asm volatile("cp.async.cg.shared.global [%0], [%1], 16;" :: "r"(saddr), "l"(g));
}
#define CP_COMMIT() asm volatile("cp.async.commit_group;" ::: "memory")
#define CP_WAIT(n)  asm volatile("cp.async.wait_group %0;" :: "n"(n) : "memory")

// ---------------- static device scratch ----------------
__device__ float g_p [NPATCH*IMGSZ];   // patchified input [c][y][x] (residual)
__device__ float g_t1[NPATCH*IMGSZ];   // height-axial out [c][x][y]
__device__ float g_t2[NPATCH*IMGSZ];   // width-axial out [c][y][x]
__device__ float g_qkv[(size_t)NPATCH*512*PLANE];   // qkv GEMM result [n][o][pos]
__device__ float g_qkvb[2][512];
__device__ float g_simA[2][12];
__device__ float g_simBsum[2][4];
__device__ float g_outA_sv[2][256];
__device__ float g_outA_sve[2][256];
__device__ float g_outB[2][256];
__device__ __half g_relTh[2][87*72];   // q/k rel fp16 [d][c(72 pad)]
__device__ uint32_t g_rvP[2][5632];    // v rel fp16 reversed, [par][c][44] half2-packed
// tensor-core operand buffers
__device__ __align__(1024) __nv_bfloat16 g_xbh[(size_t)NPATCH*256*PLANE + 256];
__device__ __align__(1024) __nv_bfloat16 g_xbl[(size_t)NPATCH*256*PLANE + 256];
__device__ __align__(1024) __nv_bfloat16 g_qwh[2][512*256];
__device__ __align__(1024) __nv_bfloat16 g_qwl[2][512*256];
__device__ __align__(1024) __nv_bfloat16 g_xh[(size_t)XROWS*256];
__device__ __align__(1024) __nv_bfloat16 g_xl[(size_t)XROWS*256];
__device__ __align__(1024) __nv_bfloat16 g_wh[9*256*256];
__device__ __align__(1024) __nv_bfloat16 g_wl[9*256*256];

// ---------------- prep ----------------
__global__ void prep_kernel(const float* __restrict__ h_qkv_w, const float* __restrict__ h_bn_qkv,
                            const float* __restrict__ h_bn_sim, const float* __restrict__ h_bn_out,
                            const float* __restrict__ w_qkv_w, const float* __restrict__ w_bn_qkv,
                            const float* __restrict__ w_bn_sim, const float* __restrict__ w_bn_out,
                            const float* __restrict__ conv_w,
                            const float* __restrict__ h_rel, const float* __restrict__ w_rel)
{
    int idx = blockIdx.x * blockDim.x + threadIdx.x;

    if (idx < 256*256*9) {
        int co  = idx / 2304;
        int rem = idx - co*2304;
        int ci  = rem / 9;
        int tap = rem - ci*9;
        float w = conv_w[idx];
        __nv_bfloat16 hi = __float2bfloat16(w);
        float lo = w - __bfloat162float(hi);
        g_wh[(tap*256 + ci)*256 + co] = hi;
        g_wl[(tap*256 + ci)*256 + co] = __float2bfloat16(lo);
    }
    if (idx < MARGIN_LO*256) {
        g_xh[idx] = __float2bfloat16(0.f);
        g_xl[idx] = __float2bfloat16(0.f);
    }
    if (idx < 256*256) {
        size_t off = (size_t)(MARGIN_LO + NPATCH*PPX)*256 + idx;
        g_xh[off] = __float2bfloat16(0.f);
        g_xl[off] = __float2bfloat16(0.f);
    }
    if (idx < 2*131072) {
        int ax = idx >> 17;
        int r  = idx & 131071;
        int o  = r & 511;
        int c  = r >> 9;
        const float* bn = ax ? w_bn_qkv : h_bn_qkv;
        const float* W  = ax ? w_qkv_w : h_qkv_w;
        float s = bn[o] * rsqrtf(bn[1536+o] + EPS);
        float wv = W[o*256 + c] * s;
        __nv_bfloat16 hi = __float2bfloat16(wv);
        float lo = wv - __bfloat162float(hi);
        g_qwh[ax][o*256 + c] = hi;
        g_qwl[ax][o*256 + c] = __float2bfloat16(lo);
        if (c == 0) g_qkvb[ax][o] = bn[512+o] - bn[1024+o]*s;
    }
    if (idx < 8) {
        int ax = idx >> 2, g = idx & 3;
        const float* bs = ax ? w_bn_sim : h_bn_sim;
        float shsum = 0.f;
        #pragma unroll
        for (int p = 0; p < 3; p++) {
            int ch = p*4 + g;
            float s = bs[ch] * rsqrtf(bs[36+ch] + EPS);
            g_simA[ax][p*4+g] = (p == 0 ? 1.f : 0.1f) * s;
            shsum += bs[12+ch] - bs[24+ch]*s;
        }
        g_simBsum[ax][g] = shsum;
    }
    if (idx < 512) {
        int ax = idx >> 8, cc = idx & 255;
        const float* bo = ax ? w_bn_out : h_bn_out;
        int o1 = 2*cc, o2 = 2*cc + 1;
        float s1 = bo[o1] * rsqrtf(bo[1536+o1] + EPS);
        float s2 = bo[o2] * rsqrtf(bo[1536+o2] + EPS);
        g_outA_sv[ax][cc]  = s1;
        g_outA_sve[ax][cc] = 0.1f * s2;
        g_outB[ax][cc] = (bo[512+o1] - bo[1024+o1]*s1) + (bo[512+o2] - bo[1024+o2]*s2);
    }
    if (idx < 2*87*72) {   // q/k rel fp16, transposed [d][c], pad c to 72
        int ax = idx / 6264, r = idx - ax*6264;
        int d = r / 72, c = r - d*72;
        const float* rl = ax ? w_rel : h_rel;
        g_relTh[ax][r] = __float2half(c < 64 ? rl[c*87 + d] : 0.f);
    }
    if (idx < 2*5632) {    // v rel fp16 reversed, parity-packed pairs
        int ax = idx / 5632, r = idx - ax*5632;
        int par = r / 2816, r2 = r - par*2816;
        int c = r2 / 44, tt = r2 - c*44;
        const float* rl = ax ? w_rel : h_rel;
        int d0 = 2*tt + par;          // lo half index d'
        float lo = (d0     <= 86) ? rl[(64+c)*87 + 86 - d0]     : 0.f;
        float hi = (d0 + 1 <= 86) ? rl[(64+c)*87 + 86 - d0 - 1] : 0.f;
        __half2 h2v = __halves2half2(__float2half(lo), __float2half(hi));
        g_rvP[ax][par*2816 + c*44 + tt] = *reinterpret_cast<uint32_t*>(&h2v);
    }
}

// ---------------- patchify ----------------
__global__ void __launch_bounds__(256,1) patchify_kernel(const float* __restrict__ x)
{
    __shared__ float tile[44*45];
    const int b = blockIdx.x;
    const int np = b >> 8, c = b & 255;
    const int bb_ = np >> 2, i2 = (np >> 1) & 1, j2 = np & 1;
    const float* src = x + ((size_t)(bb_*256 + c)*88 + i2*44)*88 + j2*44;
    float* dp = g_p + (size_t)b*1936;
    const int t = threadIdx.x;
    for (int idx = t; idx < 1936; idx += 256) {
        int y = idx / 44, xq = idx - y*44;
        float v = src[y*88 + xq];
        dp[idx] = v;
        tile[xq*45 + y] = v;
    }
    __syncthreads();
    const size_t base = (size_t)b*1936;
    for (int idx = t; idx < 1936; idx += 256) {
        int r = idx / 44, col = idx - r*44;
        float val = tile[r*45 + col];
        __nv_bfloat16 hi = __float2bfloat16(val);
        g_xbh[base + idx] = hi;
        g_xbl[base + idx] = __float2bfloat16(val - __bfloat162float(hi));
    }
}

// ---------------- transpose g_t1 [c][x][y] -> bf16 hi/lo [c][y][x] ----------------
__global__ void __launch_bounds__(256,1) transpose_kernel()
{
    __shared__ float tile[44*45];
    const int b = blockIdx.x;
    const float* src = g_t1 + (size_t)b*1936;
    const int t = threadIdx.x;
    for (int idx = t; idx < 1936; idx += 256) {
        int r = idx / 44, col = idx - r*44;
        tile[col*45 + r] = src[idx];
    }
    __syncthreads();
    const size_t base = (size_t)b*1936;
    for (int idx = t; idx < 1936; idx += 256) {
        int r = idx / 44, col = idx - r*44;
        float val = tile[r*45 + col];
        __nv_bfloat16 hi = __float2bfloat16(val);
        g_xbh[base + idx] = hi;
        g_xbl[base + idx] = __float2bfloat16(val - __bfloat162float(hi));
    }
}

// ---------------- qkv GEMM (mma.sync bf16 hi/lo, 3-stage) ----------------
#define CSTAGE 20992
#define OFF_AL 6144
#define OFF_BH 12288
#define OFF_BL 16640
#define GEMM_SMEM (3*CSTAGE)

__global__ void __launch_bounds__(256,1) qkv_gemm_kernel(int ax)
{
    extern __shared__ char smc[];
    const uint32_t sbase = smem_to_u32(smc);
    const int t = threadIdx.x;
    const int wid = t >> 5, lane = t & 31;
    const int ntile = blockIdx.x;
    const int mtile = blockIdx.y;
    const int n     = blockIdx.z;
    const int pxw = ntile * 128;
    const int mrow0 = mtile * 128;
    const int wm = wid & 1, wn = wid >> 1;
    const __nv_bfloat16* qwh = g_qwh[ax];
    const __nv_bfloat16* qwl = g_qwl[ax];

    auto load_chunk = [&](int kc, int stage) {
        const uint32_t sA = sbase + stage*CSTAGE;
        const uint32_t sB = sA + OFF_BH;
        #pragma unroll
        for (int i = 0; i < 4; i++) {
            int o = t + 256*i;
            if (o < 512) {
                int hl   = o & 1;
                int half = (o >> 1) & 1;
                int row  = o >> 2;
                const __nv_bfloat16* g = (hl ? qwl : qwh) + (size_t)(mrow0 + row)*256 + kc*16 + half*8;
                cp16(sA + hl*OFF_AL + row*48 + half*16, g);
            } else {
                int o2 = o - 512;
                int hl = o2 & 1;
                int rest = o2 >> 1;
                int krow = rest >> 4, unit = rest & 15;
                const __nv_bfloat16* g = (hl ? g_xbl : g_xbh)
                    + ((size_t)(n*256 + kc*16 + krow))*1936 + pxw + unit*8;
                cp16(sB + hl*(OFF_BL-OFF_BH) + krow*272 + unit*16, g);
            }
        }
    };

    float acc[4][4][4];
    #pragma unroll
    for (int mf = 0; mf < 4; mf++)
        #pragma unroll
        for (int nf = 0; nf < 4; nf++)
            #pragma unroll
            for (int k = 0; k < 4; k++) acc[mf][nf][k] = 0.f;

    load_chunk(0, 0); CP_COMMIT();
    load_chunk(1, 1); CP_COMMIT();

    for (int kc = 0; kc < 16; kc++) {
        const int stage = kc % 3;
        if (kc + 2 < 16) { load_chunk(kc+2, (kc+2)%3); CP_COMMIT(); CP_WAIT(2); }
        else if (kc + 1 < 16) { CP_WAIT(1); }
        else { CP_WAIT(0); }
        __syncthreads();

        const uint32_t sA = sbase + stage*CSTAGE;
        const uint32_t sB = sA + OFF_BH;

        uint32_t Ah[4][4], Al[4][4], Bh[4][2], Bl[4][2];
        #pragma unroll
        for (int mf = 0; mf < 4; mf++) {
            uint32_t a_off = (wm*64 + mf*16 + (lane & 15))*48 + (lane >> 4)*16;
            ldsm_x4(Ah[mf], sA + a_off);
            ldsm_x4(Al[mf], sA + OFF_AL + a_off);
        }
        #pragma unroll
        for (int nf = 0; nf < 4; nf++) {
            uint32_t b_off = (lane & 15)*272 + (wn*32 + nf*8)*2;
            ldsm_x2_t(Bh[nf], sB + b_off);
            ldsm_x2_t(Bl[nf], sB + (OFF_BL - OFF_BH) + b_off);
        }
        #pragma unroll
        for (int mf = 0; mf < 4; mf++)
            #pragma unroll
            for (int nf = 0; nf < 4; nf++) {
                mma_bf16(acc[mf][nf], Ah[mf], Bh[nf]);
                mma_bf16(acc[mf][nf], Ah[mf], Bl[nf]);
                mma_bf16(acc[mf][nf], Al[mf], Bh[nf]);
            }
        __syncthreads();
    }

    // epilogue
    float* stg = (float*)smc;
    #pragma unroll
    for (int h = 0; h < 2; h++) {
        __syncthreads();
        if (wm == h) {
            #pragma unroll
            for (int mf = 0; mf < 4; mf++) {
                int r0 = mf*16 + (lane >> 2);
                #pragma unroll
                for (int nf = 0; nf < 4; nf++) {
                    int c0 = wn*32 + nf*8 + (lane & 3)*2;
                    stg[r0*132 + c0]       = acc[mf][nf][0];
                    stg[r0*132 + c0+1]     = acc[mf][nf][1];
                    stg[(r0+8)*132 + c0]   = acc[mf][nf][2];
                    stg[(r0+8)*132 + c0+1] = acc[mf][nf][3];
                }
            }
        }
        __syncthreads();
        for (int idx = t; idx < 64*32; idx += 256) {
            int r = idx >> 5, q4 = idx & 31;
            int pos = pxw + q4*4;
            if (pos + 4 <= 1936) {
                int o = mrow0 + h*64 + r;
                float bias = g_qkvb[ax][o];
                float4 v = *(float4*)(stg + r*132 + q4*4);
                v.x += bias; v.y += bias; v.z += bias; v.w += bias;
                *(float4*)(g_qkv + ((size_t)n*512 + o)*1936 + pos) = v;
            }
        }
    }
}

// ---------------- fused axial attention v5: fp16 rel, staged stores ----------------
// floats: qkT[44][260]@0 | vS[256][44]@11440 | sim[4][44][44]@22704 |
//         relTh(3132u)@30448 | rvP(5632u)@33580
#define OFF_V    11440
#define OFF_SIM  22704
#define OFF_RTH  30448
#define OFF_RVP  33580
#define AX_SMEM  (39212*4)

__global__ void __launch_bounds__(1024,1) axial_kernel(int ax)
{
    float* out = ax ? g_t2 : g_t1;

    extern __shared__ float sm[];
    float* qkT  = sm;
    float* vS   = sm + OFF_V;
    float* simS = sm + OFF_SIM;
    const __half* rTh = (const __half*)(sm + OFF_RTH);
    uint32_t* rvS = (uint32_t*)(sm + OFF_RVP);

    const int t  = threadIdx.x;
    const int bb = blockIdx.x;
    const int n  = bb / 44;
    const int s  = bb - n*44;

    // load qkv slice + fp16 rel tables
    {
        const float* qsrc = g_qkv + (size_t)n*512*1936 + s*44;
        for (int idx = t; idx < 5632; idx += 1024) {
            int o = idx / 11, q = idx - o*11;
            float4 v4 = *(const float4*)(qsrc + (size_t)o*1936 + q*4);
            int g = o >> 7, wi = o & 127;
            if (wi < 64) {
                int col = g*64 + wi;
                qkT[(q*4+0)*260 + col] = v4.x;
                qkT[(q*4+1)*260 + col] = v4.y;
                qkT[(q*4+2)*260 + col] = v4.z;
                qkT[(q*4+3)*260 + col] = v4.w;
            } else {
                *(float4*)(vS + (g*64 + wi - 64)*44 + q*4) = v4;
            }
        }
        const uint32_t* rthG = (const uint32_t*)g_relTh[ax];
        uint32_t* rthS = (uint32_t*)(sm + OFF_RTH);
        for (int idx = t; idx < 3132; idx += 1024) rthS[idx] = rthG[idx];
        for (int idx = t; idx < 5632; idx += 1024) rvS[idx] = g_rvP[ax][idx];
    }
    __syncthreads();

    // sim
    for (int e = t; e < 7744; e += 1024) {
        int g = e / 1936;
        int r = e - g*1936;
        int i = r / 44;
        int j = r - i*44;
        const float4* qp = (const float4*)(qkT + i*260 + g*64);
        const float4* kp = (const float4*)(qkT + j*260 + g*64 + 32);
        const uint4* rq = (const uint4*)(rTh + (i - j + 43)*72);
        const uint4* rk = (const uint4*)(rTh + (j - i + 43)*72 + 32);
        float2 qk2 = make_float2(0.f,0.f), qr2 = qk2, kr2 = qk2;
        #pragma unroll
        for (int cc = 0; cc < 4; cc++) {
            float4 q4a = qp[2*cc], q4b = qp[2*cc+1];
            float4 k4a = kp[2*cc], k4b = kp[2*cc+1];
            uint4 rqu = rq[cc], rku = rk[cc];
            fma2(qk2, make_float2(q4a.x,q4a.y), make_float2(k4a.x,k4a.y));
            fma2(qk2, make_float2(q4a.z,q4a.w), make_float2(k4a.z,k4a.w));
            fma2(qk2, make_float2(q4b.x,q4b.y), make_float2(k4b.x,k4b.y));
            fma2(qk2, make_float2(q4b.z,q4b.w), make_float2(k4b.z,k4b.w));
            fma2(qr2, make_float2(q4a.x,q4a.y), h2f(rqu.x));
            fma2(qr2, make_float2(q4a.z,q4a.w), h2f(rqu.y));
            fma2(qr2, make_float2(q4b.x,q4b.y), h2f(rqu.z));
            fma2(qr2, make_float2(q4b.z,q4b.w), h2f(rqu.w));
            fma2(kr2, make_float2(k4a.x,k4a.y), h2f(rku.x));
            fma2(kr2, make_float2(k4a.z,k4a.w), h2f(rku.y));
            fma2(kr2, make_float2(k4b.x,k4b.y), h2f(rku.z));
            fma2(kr2, make_float2(k4b.z,k4b.w), h2f(rku.w));
        }
        float qk = qk2.x + qk2.y, qr = qr2.x + qr2.y, kr = kr2.x + kr2.y;
        simS[e] = g_simA[ax][g]*qk + g_simA[ax][4+g]*qr + g_simA[ax][8+g]*kr + g_simBsum[ax][g];
    }
    __syncthreads();

    // softmax: warp per row
    {
        const int wid = t >> 5, lane = t & 31;
        #pragma unroll
        for (int k = 0; k < 6; k++) {
            int r = wid + 32*k;
            if (r < 176) {
                float* row = simS + (r/44)*1936 + (r - (r/44)*44)*44;
                float v1 = row[lane];
                float v2 = (lane < 12) ? row[lane+32] : -1e30f;
                float m = fmaxf(v1, v2);
                #pragma unroll
                for (int off = 16; off; off >>= 1) m = fmaxf(m, __shfl_xor_sync(0xffffffffu, m, off));
                float e1 = __expf(v1 - m);
                float e2 = (lane < 12) ? __expf(v2 - m) : 0.f;
                float su = e1 + e2;
                #pragma unroll
                for (int off = 16; off; off >>= 1) su += __shfl_xor_sync(0xffffffffu, su, off);
                float inv = 1.f / su;
                row[lane] = e1 * inv;
                if (lane < 12) row[lane+32] = e2 * inv;
            }
        }
    }
    __syncthreads();

    // output: compute, stage into qkT (dead), then coalesced writeback
    {
        const int ch = t & 255, qtr = t >> 8;
        const int g = ch >> 6, c = ch & 63;
        float2 v2[22];
        const float4* vp = (const float4*)(vS + ch*44);
        #pragma unroll
        for (int q = 0; q < 11; q++) {
            float4 v4 = vp[q];
            v2[2*q]   = make_float2(v4.x, v4.y);
            v2[2*q+1] = make_float2(v4.z, v4.w);
        }
        const float aSV  = g_outA_sv[ax][ch];
        const float aSVE = g_outA_sve[ax][ch];
        const float bO   = g_outB[ax][ch];
        #pragma unroll 1
        for (int ii = 0; ii < 11; ii++) {
            int i = qtr*11 + ii;
            const float2* sr2 = (const float2*)(simS + g*1936 + i*44);
            int b0 = 43 - i;
            const uint32_t* wrow = rvS + (b0 & 1)*2816 + c*44 + (b0 >> 1);
            float2 sv2 = make_float2(0.f, 0.f), sve2 = make_float2(0.f, 0.f);
            #pragma unroll
            for (int p = 0; p < 22; p++) {
                float2 s2 = sr2[p];
                fma2(sv2, s2, v2[p]);
                fma2(sve2, s2, h2f(wrow[p]));
            }
            qkT[ch*44 + i] = fmaf(aSV, sv2.x + sv2.y, fmaf(aSVE, sve2.x + sve2.y, bO));
        }
    }
    __syncthreads();
    {
        const float4* st4 = (const float4*)qkT;
        for (int idx = t; idx < 2816; idx += 1024) {
            int ch = idx / 11, q = idx - ch*11;
            *(float4*)(out + ((size_t)(n*256 + ch))*1936 + s*44 + q*4) = st4[idx];
        }
    }
}

// ---------------- conv input prep ----------------
__global__ void __launch_bounds__(256,1) conv_in_prep()
{
    __shared__ float srow[256*44];
    const int blk = blockIdx.x;
    const int n = blk / 46, py = blk - n*46;
    const int t = threadIdx.x;
    const bool interior = (py >= 1 && py <= 44);
    if (interior) {
        const int yy = py - 1;
        const size_t nb = (size_t)n * IMGSZ + yy*44;
        for (int idx = t; idx < 256*44; idx += 256) {
            int ci = idx / 44, xx = idx - ci*44;
            srow[idx] = g_t2[nb + (size_t)ci*1936 + xx] + g_p[nb + (size_t)ci*1936 + xx];
        }
    }
    __syncthreads();
    const size_t base = ((size_t)MARGIN_LO + (size_t)n * PPX + (size_t)py*48) * 256;
    for (int x = 0; x < 48; x++) {
        float val = 0.f;
        if (interior && x >= 1 && x <= 44) val = srow[t*44 + (x-1)];
        __nv_bfloat16 hi = __float2bfloat16(val);
        float lo = val - __bfloat162float(hi);
        g_xh[base + x*256 + t] = hi;
        g_xl[base + x*256 + t] = __float2bfloat16(lo);
    }
}

// ---------------- tensor-core conv3x3 (3-stage) ----------------
#define CONV_SMEM (3*CSTAGE + 512)

__global__ void __launch_bounds__(256,1) conv_mma_kernel(const float* __restrict__ conv_b,
                                                         float* __restrict__ out)
{
    extern __shared__ char smc[];
    const uint32_t sbase = smem_to_u32(smc);
    const int t = threadIdx.x;
    const int wid = t >> 5, lane = t & 31;
    const int bb = blockIdx.x;
    const int n = bb / 36;
    const int r_ = bb - n*36;
    const int widx = r_ >> 1, cohalf = r_ & 1;
    const int pxw = widx * 128;
    const int wm = wid & 1, wn = wid >> 1;

    float* biasS = (float*)(smc + 3*CSTAGE);
    if (t < 128) biasS[t] = conv_b[cohalf*128 + t];

    const long long arow0 = (long long)MARGIN_LO + (long long)n*PPX + pxw;

    auto load_chunk = [&](int kc, int stage) {
        const int tap = kc >> 4, sub = kc & 15;
        const int offr = (tap/3 - 1)*48 + (tap%3 - 1);
        const long long abase = arow0 + offr;
        const uint32_t sA = sbase + stage*CSTAGE;
        const uint32_t sB = sA + OFF_BH;
        #pragma unroll
        for (int i = 0; i < 4; i++) {
            int o = t + 256*i;
            if (o < 512) {
                int hl   = o & 1;
                int half = (o >> 1) & 1;
                int row  = o >> 2;
                const __nv_bfloat16* g = (hl ? g_xl : g_xh) + ((size_t)(abase + row))*256 + sub*16 + half*8;
                cp16(sA + hl*OFF_AL + row*48 + half*16, g);
            } else {
                int o2 = o - 512;
                int hl = o2 & 1;
                int rest = o2 >> 1;
                int krow = rest >> 4, unit = rest & 15;
                const __nv_bfloat16* g = (hl ? g_wl : g_wh)
                    + ((size_t)(tap*256 + sub*16 + krow))*256 + cohalf*128 + unit*8;
                cp16(sB + hl*(OFF_BL-OFF_BH) + krow*272 + unit*16, g);
            }
        }
    };

    float acc[4][4][4];
    #pragma unroll
    for (int mf = 0; mf < 4; mf++)
        #pragma unroll
        for (int nf = 0; nf < 4; nf++)
            #pragma unroll
            for (int k = 0; k < 4; k++) acc[mf][nf][k] = 0.f;

    load_chunk(0, 0); CP_COMMIT();
    load_chunk(1, 1); CP_COMMIT();

    for (int kc = 0; kc < 144; kc++) {
        const int stage = kc % 3;
        if (kc + 2 < 144) { load_chunk(kc+2, (kc+2)%3); CP_COMMIT(); CP_WAIT(2); }
        else if (kc + 1 < 144) { CP_WAIT(1); }
        else { CP_WAIT(0); }
        __syncthreads();

        const uint32_t sA = sbase + stage*CSTAGE;
        const uint32_t sB = sA + OFF_BH;

        uint32_t Ah[4][4], Al[4][4], Bh[4][2], Bl[4][2];
        #pragma unroll
        for (int mf = 0; mf < 4; mf++) {
            uint32_t a_off = (wm*64 + mf*16 + (lane & 15))*48 + (lane >> 4)*16;
            ldsm_x4(Ah[mf], sA + a_off);
            ldsm_x4(Al[mf], sA + OFF_AL + a_off);
        }
        #pragma unroll
        for (int nf = 0; nf < 4; nf++) {
            uint32_t b_off = (lane & 15)*272 + (wn*32 + nf*8)*2;
            ldsm_x2_t(Bh[nf], sB + b_off);
            ldsm_x2_t(Bl[nf], sB + (OFF_BL - OFF_BH) + b_off);
        }
        #pragma unroll
        for (int mf = 0; mf < 4; mf++)
            #pragma unroll
            for (int nf = 0; nf < 4; nf++) {
                mma_bf16(acc[mf][nf], Ah[mf], Bh[nf]);
                mma_bf16(acc[mf][nf], Ah[mf], Bl[nf]);
                mma_bf16(acc[mf][nf], Al[mf], Bh[nf]);
            }
        __syncthreads();
    }

    const int b_ = n >> 2, i2 = (n >> 1) & 1, j2 = n & 1;
    #pragma unroll
    for (int mf = 0; mf < 4; mf++) {
        #pragma unroll
        for (int half = 0; half < 2; half++) {
            int px = pxw + wm*64 + mf*16 + (lane >> 2) + half*8;
            int py = px / 48, pxx = px - py*48;
            bool valid = (py >= 1 && py <= 44) && (pxx >= 1 && pxx <= 44);
            if (!valid) continue;
            size_t ob = ((size_t)(b_*256))*7744 + (size_t)(i2*44 + (py-1))*88 + j2*44 + (pxx-1);
            #pragma unroll
            for (int nf = 0; nf < 4; nf++) {
                int col = wn*32 + nf*8 + (lane & 3)*2;
                int co = cohalf*128 + col;
                out[ob + (size_t)co*7744]     = acc[mf][nf][half*2+0] + biasS[col];
                out[ob + (size_t)(co+1)*7744] = acc[mf][nf][half*2+1] + biasS[col+1];
            }
        }
    }
}

// ---------------- launch ----------------
extern "C" void kernel_launch(void* const* d_in, const int* in_sizes, int n_in,
                              void* d_out, int out_size)
{
    const float* x        = (const float*)d_in[0];
    const float* h_qkv_w  = (const float*)d_in[1];
    const float* h_bn_qkv = (const float*)d_in[2];
    const float* h_bn_sim = (const float*)d_in[3];
    const float* h_bn_out = (const float*)d_in[4];
    const float* h_rel    = (const float*)d_in[5];
    const float* w_qkv_w  = (const float*)d_in[6];
    const float* w_bn_qkv = (const float*)d_in[7];
    const float* w_bn_sim = (const float*)d_in[8];
    const float* w_bn_out = (const float*)d_in[9];
    const float* w_rel    = (const float*)d_in[10];
    const float* conv_w   = (const float*)d_in[11];
    const float* conv_b   = (const float*)d_in[12];
    float* out = (float*)d_out;

    cudaFuncSetAttribute(axial_kernel,    cudaFuncAttributeMaxDynamicSharedMemorySize, AX_SMEM);
    cudaFuncSetAttribute(qkv_gemm_kernel, cudaFuncAttributeMaxDynamicSharedMemorySize, GEMM_SMEM);
    cudaFuncSetAttribute(conv_mma_kernel, cudaFuncAttributeMaxDynamicSharedMemorySize, CONV_SMEM);

    prep_kernel<<<(256*256*9 + 255)/256, 256>>>(h_qkv_w, h_bn_qkv, h_bn_sim, h_bn_out,
                                                w_qkv_w, w_bn_qkv, w_bn_sim, w_bn_out,
                                                conv_w, h_rel, w_rel);
    patchify_kernel<<<NPATCH*256, 256>>>(x);
    qkv_gemm_kernel<<<dim3(16,4,NPATCH), 256, GEMM_SMEM>>>(0);
    axial_kernel<<<NB, 1024, AX_SMEM>>>(0);
    transpose_kernel<<<NPATCH*256, 256>>>();
    qkv_gemm_kernel<<<dim3(16,4,NPATCH), 256, GEMM_SMEM>>>(1);
    axial_kernel<<<NB, 1024, AX_SMEM>>>(1);
    conv_in_prep<<<NPATCH*46, 256>>>();
    conv_mma_kernel<<<NPATCH*36, 256, CONV_SMEM>>>(conv_b, out);
}

// round 8
// speedup vs baseline: 1.9576x; 1.0815x over previous
#include <cuda_runtime.h>
#include <cuda_bf16.h>
#include <cuda_fp16.h>
#include <math.h>
#include <cstdint>

#define EPS 1e-5f
#define NPATCH 64
#define HS 44
#define NB (NPATCH*HS)          // 2816
#define PLANE 1936
#define IMGSZ (256*1936)

// padded conv geometry
#define PPX 2208
#define MARGIN_LO 128
#define XROWS (MARGIN_LO + NPATCH*PPX + 256)

typedef unsigned long long ull;
__device__ __forceinline__ void fma2(float2 &d, float2 a, float2 b) {
    asm("fma.rn.f32x2 %0, %1, %2, %0;"
        : "+l"(reinterpret_cast<ull&>(d))
        : "l"(reinterpret_cast<ull&>(a)), "l"(reinterpret_cast<ull&>(b)));
}
__device__ __forceinline__ float2 h2f(uint32_t u) {
    __half2 h = *reinterpret_cast<__half2*>(&u);
    return __half22float2(h);
}

// ---------------- mma / ldmatrix / cp.async helpers ----------------
__device__ __forceinline__ uint32_t smem_to_u32(const void* p) {
    uint32_t a;
    asm("{ .reg .u64 t; cvta.to.shared.u64 t, %1; cvt.u32.u64 %0, t; }" : "=r"(a) : "l"(p));
    return a;
}
__device__ __forceinline__ void ldsm_x4(uint32_t a[4], uint32_t addr) {
    asm volatile("ldmatrix.sync.aligned.m8n8.x4.shared.b16 {%0,%1,%2,%3}, [%4];"
        : "=r"(a[0]),"=r"(a[1]),"=r"(a[2]),"=r"(a[3]) : "r"(addr));
}
__device__ __forceinline__ void ldsm_x2_t(uint32_t b[2], uint32_t addr) {
    asm volatile("ldmatrix.sync.aligned.m8n8.x2.trans.shared.b16 {%0,%1}, [%2];"
        : "=r"(b[0]),"=r"(b[1]) : "r"(addr));
}
__device__ __forceinline__ void mma_bf16(float c[4], const uint32_t a[4], const uint32_t b[2]) {
    asm volatile("mma.sync.aligned.m16n8k16.row.col.f32.bf16.bf16.f32 "
        "{%0,%1,%2,%3}, {%4,%5,%6,%7}, {%8,%9}, {%0,%1,%2,%3};"
        : "+f"(c[0]),"+f"(c[1]),"+f"(c[2]),"+f"(c[3])
        : "r"(a[0]),"r"(a[1]),"r"(a[2]),"r"(a[3]), "r"(b[0]),"r"(b[1]));
}
__device__ __forceinline__ void cp16(uint32_t saddr, const void* g) {
    asm volatile("cp.async.cg.shared.global [%0], [%1], 16;" :: "r"(saddr), "l"(g));
}
#define CP_COMMIT() asm volatile("cp.async.commit_group;" ::: "memory")
#define CP_WAIT(n)  asm volatile("cp.async.wait_group %0;" :: "n"(n) : "memory")

// ---------------- static device scratch ----------------
__device__ float g_p [NPATCH*IMGSZ];
__device__ float g_t1[NPATCH*IMGSZ];
__device__ float g_t2[NPATCH*IMGSZ];
__device__ float g_qkv[(size_t)NPATCH*512*PLANE];
__device__ float g_qkvb[2][512];
__device__ float g_simA[2][12];
__device__ float g_simBsum[2][4];
__device__ float g_outA_sv[2][256];
__device__ float g_outA_sve[2][256];
__device__ float g_outB[2][256];
__device__ __half g_relTh[2][87*72];   // q/k rel fp16 [d][c(72 pad)]
__device__ uint32_t g_rvP[2][5632];    // v rel fp16 reversed: [par][dhalf(44)][c(64)]
// tensor-core operand buffers
__device__ __align__(1024) __nv_bfloat16 g_xbh[(size_t)NPATCH*256*PLANE + 256];
__device__ __align__(1024) __nv_bfloat16 g_xbl[(size_t)NPATCH*256*PLANE + 256];
__device__ __align__(1024) __nv_bfloat16 g_qwh[2][512*256];
__device__ __align__(1024) __nv_bfloat16 g_qwl[2][512*256];
__device__ __align__(1024) __nv_bfloat16 g_xh[(size_t)XROWS*256];
__device__ __align__(1024) __nv_bfloat16 g_xl[(size_t)XROWS*256];
__device__ __align__(1024) __nv_bfloat16 g_wh[9*256*256];
__device__ __align__(1024) __nv_bfloat16 g_wl[9*256*256];

// ---------------- prep ----------------
__global__ void prep_kernel(const float* __restrict__ h_qkv_w, const float* __restrict__ h_bn_qkv,
                            const float* __restrict__ h_bn_sim, const float* __restrict__ h_bn_out,
                            const float* __restrict__ w_qkv_w, const float* __restrict__ w_bn_qkv,
                            const float* __restrict__ w_bn_sim, const float* __restrict__ w_bn_out,
                            const float* __restrict__ conv_w,
                            const float* __restrict__ h_rel, const float* __restrict__ w_rel)
{
    int idx = blockIdx.x * blockDim.x + threadIdx.x;

    if (idx < 256*256*9) {
        int co  = idx / 2304;
        int rem = idx - co*2304;
        int ci  = rem / 9;
        int tap = rem - ci*9;
        float w = conv_w[idx];
        __nv_bfloat16 hi = __float2bfloat16(w);
        float lo = w - __bfloat162float(hi);
        g_wh[(tap*256 + ci)*256 + co] = hi;
        g_wl[(tap*256 + ci)*256 + co] = __float2bfloat16(lo);
    }
    if (idx < MARGIN_LO*256) {
        g_xh[idx] = __float2bfloat16(0.f);
        g_xl[idx] = __float2bfloat16(0.f);
    }
    if (idx < 256*256) {
        size_t off = (size_t)(MARGIN_LO + NPATCH*PPX)*256 + idx;
        g_xh[off] = __float2bfloat16(0.f);
        g_xl[off] = __float2bfloat16(0.f);
    }
    if (idx < 2*131072) {
        int ax = idx >> 17;
        int r  = idx & 131071;
        int o  = r & 511;
        int c  = r >> 9;
        const float* bn = ax ? w_bn_qkv : h_bn_qkv;
        const float* W  = ax ? w_qkv_w : h_qkv_w;
        float s = bn[o] * rsqrtf(bn[1536+o] + EPS);
        float wv = W[o*256 + c] * s;
        __nv_bfloat16 hi = __float2bfloat16(wv);
        float lo = wv - __bfloat162float(hi);
        g_qwh[ax][o*256 + c] = hi;
        g_qwl[ax][o*256 + c] = __float2bfloat16(lo);
        if (c == 0) g_qkvb[ax][o] = bn[512+o] - bn[1024+o]*s;
    }
    if (idx < 8) {
        int ax = idx >> 2, g = idx & 3;
        const float* bs = ax ? w_bn_sim : h_bn_sim;
        float shsum = 0.f;
        #pragma unroll
        for (int p = 0; p < 3; p++) {
            int ch = p*4 + g;
            float s = bs[ch] * rsqrtf(bs[36+ch] + EPS);
            g_simA[ax][p*4+g] = (p == 0 ? 1.f : 0.1f) * s;
            shsum += bs[12+ch] - bs[24+ch]*s;
        }
        g_simBsum[ax][g] = shsum;
    }
    if (idx < 512) {
        int ax = idx >> 8, cc = idx & 255;
        const float* bo = ax ? w_bn_out : h_bn_out;
        int o1 = 2*cc, o2 = 2*cc + 1;
        float s1 = bo[o1] * rsqrtf(bo[1536+o1] + EPS);
        float s2 = bo[o2] * rsqrtf(bo[1536+o2] + EPS);
        g_outA_sv[ax][cc]  = s1;
        g_outA_sve[ax][cc] = 0.1f * s2;
        g_outB[ax][cc] = (bo[512+o1] - bo[1024+o1]*s1) + (bo[512+o2] - bo[1024+o2]*s2);
    }
    if (idx < 2*87*72) {
        int ax = idx / 6264, r = idx - ax*6264;
        int d = r / 72, c = r - d*72;
        const float* rl = ax ? w_rel : h_rel;
        g_relTh[ax][r] = __float2half(c < 64 ? rl[c*87 + d] : 0.f);
    }
    if (idx < 2*5632) {    // v rel fp16 reversed: [par][dhalf][c], c contiguous
        int ax = idx / 5632, r = idx - ax*5632;
        int par = r / 2816, r2 = r - par*2816;
        int dhalf = r2 >> 6, c = r2 & 63;
        const float* rl = ax ? w_rel : h_rel;
        int d0 = 2*dhalf + par;
        float lo = (d0     <= 86) ? rl[(64+c)*87 + 86 - d0]     : 0.f;
        float hi = (d0 + 1 <= 86) ? rl[(64+c)*87 + 86 - d0 - 1] : 0.f;
        __half2 h2v = __halves2half2(__float2half(lo), __float2half(hi));
        g_rvP[ax][par*2816 + dhalf*64 + c] = *reinterpret_cast<uint32_t*>(&h2v);
    }
}

// ---------------- patchify ----------------
__global__ void __launch_bounds__(256,1) patchify_kernel(const float* __restrict__ x)
{
    __shared__ float tile[44*45];
    const int b = blockIdx.x;
    const int np = b >> 8, c = b & 255;
    const int bb_ = np >> 2, i2 = (np >> 1) & 1, j2 = np & 1;
    const float* src = x + ((size_t)(bb_*256 + c)*88 + i2*44)*88 + j2*44;
    float* dp = g_p + (size_t)b*1936;
    const int t = threadIdx.x;
    for (int idx = t; idx < 1936; idx += 256) {
        int y = idx / 44, xq = idx - y*44;
        float v = src[y*88 + xq];
        dp[idx] = v;
        tile[xq*45 + y] = v;
    }
    __syncthreads();
    const size_t base = (size_t)b*1936;
    for (int idx = t; idx < 1936; idx += 256) {
        int r = idx / 44, col = idx - r*44;
        float val = tile[r*45 + col];
        __nv_bfloat16 hi = __float2bfloat16(val);
        g_xbh[base + idx] = hi;
        g_xbl[base + idx] = __float2bfloat16(val - __bfloat162float(hi));
    }
}

// ---------------- transpose g_t1 [c][x][y] -> bf16 hi/lo [c][y][x] ----------------
__global__ void __launch_bounds__(256,1) transpose_kernel()
{
    __shared__ float tile[44*45];
    const int b = blockIdx.x;
    const float* src = g_t1 + (size_t)b*1936;
    const int t = threadIdx.x;
    for (int idx = t; idx < 1936; idx += 256) {
        int r = idx / 44, col = idx - r*44;
        tile[col*45 + r] = src[idx];
    }
    __syncthreads();
    const size_t base = (size_t)b*1936;
    for (int idx = t; idx < 1936; idx += 256) {
        int r = idx / 44, col = idx - r*44;
        float val = tile[r*45 + col];
        __nv_bfloat16 hi = __float2bfloat16(val);
        g_xbh[base + idx] = hi;
        g_xbl[base + idx] = __float2bfloat16(val - __bfloat162float(hi));
    }
}

// ---------------- qkv GEMM (mma.sync bf16 hi/lo, 3-stage) ----------------
#define CSTAGE 20992
#define OFF_AL 6144
#define OFF_BH 12288
#define OFF_BL 16640
#define GEMM_SMEM (3*CSTAGE)

__global__ void __launch_bounds__(256,1) qkv_gemm_kernel(int ax)
{
    extern __shared__ char smc[];
    const uint32_t sbase = smem_to_u32(smc);
    const int t = threadIdx.x;
    const int wid = t >> 5, lane = t & 31;
    const int ntile = blockIdx.x;
    const int mtile = blockIdx.y;
    const int n     = blockIdx.z;
    const int pxw = ntile * 128;
    const int mrow0 = mtile * 128;
    const int wm = wid & 1, wn = wid >> 1;
    const __nv_bfloat16* qwh = g_qwh[ax];
    const __nv_bfloat16* qwl = g_qwl[ax];

    auto load_chunk = [&](int kc, int stage) {
        const uint32_t sA = sbase + stage*CSTAGE;
        const uint32_t sB = sA + OFF_BH;
        #pragma unroll
        for (int i = 0; i < 4; i++) {
            int o = t + 256*i;
            if (o < 512) {
                int hl   = o & 1;
                int half = (o >> 1) & 1;
                int row  = o >> 2;
                const __nv_bfloat16* g = (hl ? qwl : qwh) + (size_t)(mrow0 + row)*256 + kc*16 + half*8;
                cp16(sA + hl*OFF_AL + row*48 + half*16, g);
            } else {
                int o2 = o - 512;
                int hl = o2 & 1;
                int rest = o2 >> 1;
                int krow = rest >> 4, unit = rest & 15;
                const __nv_bfloat16* g = (hl ? g_xbl : g_xbh)
                    + ((size_t)(n*256 + kc*16 + krow))*1936 + pxw + unit*8;
                cp16(sB + hl*(OFF_BL-OFF_BH) + krow*272 + unit*16, g);
            }
        }
    };

    float acc[4][4][4];
    #pragma unroll
    for (int mf = 0; mf < 4; mf++)
        #pragma unroll
        for (int nf = 0; nf < 4; nf++)
            #pragma unroll
            for (int k = 0; k < 4; k++) acc[mf][nf][k] = 0.f;

    load_chunk(0, 0); CP_COMMIT();
    load_chunk(1, 1); CP_COMMIT();

    for (int kc = 0; kc < 16; kc++) {
        const int stage = kc % 3;
        if (kc + 2 < 16) { load_chunk(kc+2, (kc+2)%3); CP_COMMIT(); CP_WAIT(2); }
        else if (kc + 1 < 16) { CP_WAIT(1); }
        else { CP_WAIT(0); }
        __syncthreads();

        const uint32_t sA = sbase + stage*CSTAGE;
        const uint32_t sB = sA + OFF_BH;

        uint32_t Ah[4][4], Al[4][4], Bh[4][2], Bl[4][2];
        #pragma unroll
        for (int mf = 0; mf < 4; mf++) {
            uint32_t a_off = (wm*64 + mf*16 + (lane & 15))*48 + (lane >> 4)*16;
            ldsm_x4(Ah[mf], sA + a_off);
            ldsm_x4(Al[mf], sA + OFF_AL + a_off);
        }
        #pragma unroll
        for (int nf = 0; nf < 4; nf++) {
            uint32_t b_off = (lane & 15)*272 + (wn*32 + nf*8)*2;
            ldsm_x2_t(Bh[nf], sB + b_off);
            ldsm_x2_t(Bl[nf], sB + (OFF_BL - OFF_BH) + b_off);
        }
        #pragma unroll
        for (int mf = 0; mf < 4; mf++)
            #pragma unroll
            for (int nf = 0; nf < 4; nf++) {
                mma_bf16(acc[mf][nf], Ah[mf], Bh[nf]);
                mma_bf16(acc[mf][nf], Ah[mf], Bl[nf]);
                mma_bf16(acc[mf][nf], Al[mf], Bh[nf]);
            }
        __syncthreads();
    }

    // epilogue
    float* stg = (float*)smc;
    #pragma unroll
    for (int h = 0; h < 2; h++) {
        __syncthreads();
        if (wm == h) {
            #pragma unroll
            for (int mf = 0; mf < 4; mf++) {
                int r0 = mf*16 + (lane >> 2);
                #pragma unroll
                for (int nf = 0; nf < 4; nf++) {
                    int c0 = wn*32 + nf*8 + (lane & 3)*2;
                    stg[r0*132 + c0]       = acc[mf][nf][0];
                    stg[r0*132 + c0+1]     = acc[mf][nf][1];
                    stg[(r0+8)*132 + c0]   = acc[mf][nf][2];
                    stg[(r0+8)*132 + c0+1] = acc[mf][nf][3];
                }
            }
        }
        __syncthreads();
        for (int idx = t; idx < 64*32; idx += 256) {
            int r = idx >> 5, q4 = idx & 31;
            int pos = pxw + q4*4;
            if (pos + 4 <= 1936) {
                int o = mrow0 + h*64 + r;
                float bias = g_qkvb[ax][o];
                float4 v = *(float4*)(stg + r*132 + q4*4);
                v.x += bias; v.y += bias; v.z += bias; v.w += bias;
                *(float4*)(g_qkv + ((size_t)n*512 + o)*1936 + pos) = v;
            }
        }
    }
}

// ---------------- fused axial attention v6: conflict-free rel layout ----------------
#define OFF_V    11440
#define OFF_SIM  22704
#define OFF_RTH  30448
#define OFF_RVP  33580
#define AX_SMEM  (39212*4)

__global__ void __launch_bounds__(1024,1) axial_kernel(int ax)
{
    float* out = ax ? g_t2 : g_t1;

    extern __shared__ float sm[];
    float* qkT  = sm;
    float* vS   = sm + OFF_V;
    float* simS = sm + OFF_SIM;
    const __half* rTh = (const __half*)(sm + OFF_RTH);
    uint32_t* rvS = (uint32_t*)(sm + OFF_RVP);

    const int t  = threadIdx.x;
    const int bb = blockIdx.x;
    const int n  = bb / 44;
    const int s  = bb - n*44;

    // load qkv slice + fp16 rel tables
    {
        const float* qsrc = g_qkv + (size_t)n*512*1936 + s*44;
        for (int idx = t; idx < 5632; idx += 1024) {
            int o = idx / 11, q = idx - o*11;
            float4 v4 = *(const float4*)(qsrc + (size_t)o*1936 + q*4);
            int g = o >> 7, wi = o & 127;
            if (wi < 64) {
                int col = g*64 + wi;
                qkT[(q*4+0)*260 + col] = v4.x;
                qkT[(q*4+1)*260 + col] = v4.y;
                qkT[(q*4+2)*260 + col] = v4.z;
                qkT[(q*4+3)*260 + col] = v4.w;
            } else {
                *(float4*)(vS + (g*64 + wi - 64)*44 + q*4) = v4;
            }
        }
        const uint32_t* rthG = (const uint32_t*)g_relTh[ax];
        uint32_t* rthS = (uint32_t*)(sm + OFF_RTH);
        for (int idx = t; idx < 3132; idx += 1024) rthS[idx] = rthG[idx];
        for (int idx = t; idx < 5632; idx += 1024) rvS[idx] = g_rvP[ax][idx];
    }
    __syncthreads();

    // sim
    for (int e = t; e < 7744; e += 1024) {
        int g = e / 1936;
        int r = e - g*1936;
        int i = r / 44;
        int j = r - i*44;
        const float4* qp = (const float4*)(qkT + i*260 + g*64);
        const float4* kp = (const float4*)(qkT + j*260 + g*64 + 32);
        const uint4* rq = (const uint4*)(rTh + (i - j + 43)*72);
        const uint4* rk = (const uint4*)(rTh + (j - i + 43)*72 + 32);
        float2 qk2 = make_float2(0.f,0.f), qr2 = qk2, kr2 = qk2;
        #pragma unroll
        for (int cc = 0; cc < 4; cc++) {
            float4 q4a = qp[2*cc], q4b = qp[2*cc+1];
            float4 k4a = kp[2*cc], k4b = kp[2*cc+1];
            uint4 rqu = rq[cc], rku = rk[cc];
            fma2(qk2, make_float2(q4a.x,q4a.y), make_float2(k4a.x,k4a.y));
            fma2(qk2, make_float2(q4a.z,q4a.w), make_float2(k4a.z,k4a.w));
            fma2(qk2, make_float2(q4b.x,q4b.y), make_float2(k4b.x,k4b.y));
            fma2(qk2, make_float2(q4b.z,q4b.w), make_float2(k4b.z,k4b.w));
            fma2(qr2, make_float2(q4a.x,q4a.y), h2f(rqu.x));
            fma2(qr2, make_float2(q4a.z,q4a.w), h2f(rqu.y));
            fma2(qr2, make_float2(q4b.x,q4b.y), h2f(rqu.z));
            fma2(qr2, make_float2(q4b.z,q4b.w), h2f(rqu.w));
            fma2(kr2, make_float2(k4a.x,k4a.y), h2f(rku.x));
            fma2(kr2, make_float2(k4a.z,k4a.w), h2f(rku.y));
            fma2(kr2, make_float2(k4b.x,k4b.y), h2f(rku.z));
            fma2(kr2, make_float2(k4b.z,k4b.w), h2f(rku.w));
        }
        float qk = qk2.x + qk2.y, qr = qr2.x + qr2.y, kr = kr2.x + kr2.y;
        simS[e] = g_simA[ax][g]*qk + g_simA[ax][4+g]*qr + g_simA[ax][8+g]*kr + g_simBsum[ax][g];
    }
    __syncthreads();

    // softmax: warp per row
    {
        const int wid = t >> 5, lane = t & 31;
        #pragma unroll
        for (int k = 0; k < 6; k++) {
            int r = wid + 32*k;
            if (r < 176) {
                float* row = simS + (r/44)*1936 + (r - (r/44)*44)*44;
                float v1 = row[lane];
                float v2 = (lane < 12) ? row[lane+32] : -1e30f;
                float m = fmaxf(v1, v2);
                #pragma unroll
                for (int off = 16; off; off >>= 1) m = fmaxf(m, __shfl_xor_sync(0xffffffffu, m, off));
                float e1 = __expf(v1 - m);
                float e2 = (lane < 12) ? __expf(v2 - m) : 0.f;
                float su = e1 + e2;
                #pragma unroll
                for (int off = 16; off; off >>= 1) su += __shfl_xor_sync(0xffffffffu, su, off);
                float inv = 1.f / su;
                row[lane] = e1 * inv;
                if (lane < 12) row[lane+32] = e2 * inv;
            }
        }
    }
    __syncthreads();

    // output: compute, stage into qkT (dead), then coalesced writeback
    {
        const int ch = t & 255, qtr = t >> 8;
        const int g = ch >> 6, c = ch & 63;
        float2 v2[22];
        const float4* vp = (const float4*)(vS + ch*44);
        #pragma unroll
        for (int q = 0; q < 11; q++) {
            float4 v4 = vp[q];
            v2[2*q]   = make_float2(v4.x, v4.y);
            v2[2*q+1] = make_float2(v4.z, v4.w);
        }
        const float aSV  = g_outA_sv[ax][ch];
        const float aSVE = g_outA_sve[ax][ch];
        const float bO   = g_outB[ax][ch];
        #pragma unroll 1
        for (int ii = 0; ii < 11; ii++) {
            int i = qtr*11 + ii;
            const float2* sr2 = (const float2*)(simS + g*1936 + i*44);
            int b0 = 43 - i;
            const uint32_t* wrow = rvS + (b0 & 1)*2816 + (b0 >> 1)*64 + c;
            float2 sv2 = make_float2(0.f, 0.f), sve2 = make_float2(0.f, 0.f);
            #pragma unroll
            for (int p = 0; p < 22; p++) {
                float2 s2 = sr2[p];
                fma2(sv2, s2, v2[p]);
                fma2(sve2, s2, h2f(wrow[p*64]));
            }
            qkT[ch*44 + i] = fmaf(aSV, sv2.x + sv2.y, fmaf(aSVE, sve2.x + sve2.y, bO));
        }
    }
    __syncthreads();
    {
        const float4* st4 = (const float4*)qkT;
        for (int idx = t; idx < 2816; idx += 1024) {
            int ch = idx / 11, q = idx - ch*11;
            *(float4*)(out + ((size_t)(n*256 + ch))*1936 + s*44 + q*4) = st4[idx];
        }
    }
}

// ---------------- conv input prep ----------------
__global__ void __launch_bounds__(256,1) conv_in_prep()
{
    __shared__ float srow[256*44];
    const int blk = blockIdx.x;
    const int n = blk / 46, py = blk - n*46;
    const int t = threadIdx.x;
    const bool interior = (py >= 1 && py <= 44);
    if (interior) {
        const int yy = py - 1;
        const size_t nb = (size_t)n * IMGSZ + yy*44;
        for (int idx = t; idx < 256*44; idx += 256) {
            int ci = idx / 44, xx = idx - ci*44;
            srow[idx] = g_t2[nb + (size_t)ci*1936 + xx] + g_p[nb + (size_t)ci*1936 + xx];
        }
    }
    __syncthreads();
    const size_t base = ((size_t)MARGIN_LO + (size_t)n * PPX + (size_t)py*48) * 256;
    for (int x = 0; x < 48; x++) {
        float val = 0.f;
        if (interior && x >= 1 && x <= 44) val = srow[t*44 + (x-1)];
        __nv_bfloat16 hi = __float2bfloat16(val);
        float lo = val - __bfloat162float(hi);
        g_xh[base + x*256 + t] = hi;
        g_xl[base + x*256 + t] = __float2bfloat16(lo);
    }
}

// ---------------- tensor-core conv3x3 (3-stage) ----------------
#define CONV_SMEM (3*CSTAGE + 512)

__global__ void __launch_bounds__(256,1) conv_mma_kernel(const float* __restrict__ conv_b,
                                                         float* __restrict__ out)
{
    extern __shared__ char smc[];
    const uint32_t sbase = smem_to_u32(smc);
    const int t = threadIdx.x;
    const int wid = t >> 5, lane = t & 31;
    const int bb = blockIdx.x;
    const int n = bb / 36;
    const int r_ = bb - n*36;
    const int widx = r_ >> 1, cohalf = r_ & 1;
    const int pxw = widx * 128;
    const int wm = wid & 1, wn = wid >> 1;

    float* biasS = (float*)(smc + 3*CSTAGE);
    if (t < 128) biasS[t] = conv_b[cohalf*128 + t];

    const long long arow0 = (long long)MARGIN_LO + (long long)n*PPX + pxw;

    auto load_chunk = [&](int kc, int stage) {
        const int tap = kc >> 4, sub = kc & 15;
        const int offr = (tap/3 - 1)*48 + (tap%3 - 1);
        const long long abase = arow0 + offr;
        const uint32_t sA = sbase + stage*CSTAGE;
        const uint32_t sB = sA + OFF_BH;
        #pragma unroll
        for (int i = 0; i < 4; i++) {
            int o = t + 256*i;
            if (o < 512) {
                int hl   = o & 1;
                int half = (o >> 1) & 1;
                int row  = o >> 2;
                const __nv_bfloat16* g = (hl ? g_xl : g_xh) + ((size_t)(abase + row))*256 + sub*16 + half*8;
                cp16(sA + hl*OFF_AL + row*48 + half*16, g);
            } else {
                int o2 = o - 512;
                int hl = o2 & 1;
                int rest = o2 >> 1;
                int krow = rest >> 4, unit = rest & 15;
                const __nv_bfloat16* g = (hl ? g_wl : g_wh)
                    + ((size_t)(tap*256 + sub*16 + krow))*256 + cohalf*128 + unit*8;
                cp16(sB + hl*(OFF_BL-OFF_BH) + krow*272 + unit*16, g);
            }
        }
    };

    float acc[4][4][4];
    #pragma unroll
    for (int mf = 0; mf < 4; mf++)
        #pragma unroll
        for (int nf = 0; nf < 4; nf++)
            #pragma unroll
            for (int k = 0; k < 4; k++) acc[mf][nf][k] = 0.f;

    load_chunk(0, 0); CP_COMMIT();
    load_chunk(1, 1); CP_COMMIT();

    for (int kc = 0; kc < 144; kc++) {
        const int stage = kc % 3;
        if (kc + 2 < 144) { load_chunk(kc+2, (kc+2)%3); CP_COMMIT(); CP_WAIT(2); }
        else if (kc + 1 < 144) { CP_WAIT(1); }
        else { CP_WAIT(0); }
        __syncthreads();

        const uint32_t sA = sbase + stage*CSTAGE;
        const uint32_t sB = sA + OFF_BH;

        uint32_t Ah[4][4], Al[4][4], Bh[4][2], Bl[4][2];
        #pragma unroll
        for (int mf = 0; mf < 4; mf++) {
            uint32_t a_off = (wm*64 + mf*16 + (lane & 15))*48 + (lane >> 4)*16;
            ldsm_x4(Ah[mf], sA + a_off);
            ldsm_x4(Al[mf], sA + OFF_AL + a_off);
        }
        #pragma unroll
        for (int nf = 0; nf < 4; nf++) {
            uint32_t b_off = (lane & 15)*272 + (wn*32 + nf*8)*2;
            ldsm_x2_t(Bh[nf], sB + b_off);
            ldsm_x2_t(Bl[nf], sB + (OFF_BL - OFF_BH) + b_off);
        }
        #pragma unroll
        for (int mf = 0; mf < 4; mf++)
            #pragma unroll
            for (int nf = 0; nf < 4; nf++) {
                mma_bf16(acc[mf][nf], Ah[mf], Bh[nf]);
                mma_bf16(acc[mf][nf], Ah[mf], Bl[nf]);
                mma_bf16(acc[mf][nf], Al[mf], Bh[nf]);
            }
        __syncthreads();
    }

    const int b_ = n >> 2, i2 = (n >> 1) & 1, j2 = n & 1;
    #pragma unroll
    for (int mf = 0; mf < 4; mf++) {
        #pragma unroll
        for (int half = 0; half < 2; half++) {
            int px = pxw + wm*64 + mf*16 + (lane >> 2) + half*8;
            int py = px / 48, pxx = px - py*48;
            bool valid = (py >= 1 && py <= 44) && (pxx >= 1 && pxx <= 44);
            if (!valid) continue;
            size_t ob = ((size_t)(b_*256))*7744 + (size_t)(i2*44 + (py-1))*88 + j2*44 + (pxx-1);
            #pragma unroll
            for (int nf = 0; nf < 4; nf++) {
                int col = wn*32 + nf*8 + (lane & 3)*2;
                int co = cohalf*128 + col;
                out[ob + (size_t)co*7744]     = acc[mf][nf][half*2+0] + biasS[col];
                out[ob + (size_t)(co+1)*7744] = acc[mf][nf][half*2+1] + biasS[col+1];
            }
        }
    }
}

// ---------------- launch ----------------
extern "C" void kernel_launch(void* const* d_in, const int* in_sizes, int n_in,
                              void* d_out, int out_size)
{
    const float* x        = (const float*)d_in[0];
    const float* h_qkv_w  = (const float*)d_in[1];
    const float* h_bn_qkv = (const float*)d_in[2];
    const float* h_bn_sim = (const float*)d_in[3];
    const float* h_bn_out = (const float*)d_in[4];
    const float* h_rel    = (const float*)d_in[5];
    const float* w_qkv_w  = (const float*)d_in[6];
    const float* w_bn_qkv = (const float*)d_in[7];
    const float* w_bn_sim = (const float*)d_in[8];
    const float* w_bn_out = (const float*)d_in[9];
    const float* w_rel    = (const float*)d_in[10];
    const float* conv_w   = (const float*)d_in[11];
    const float* conv_b   = (const float*)d_in[12];
    float* out = (float*)d_out;

    cudaFuncSetAttribute(axial_kernel,    cudaFuncAttributeMaxDynamicSharedMemorySize, AX_SMEM);
    cudaFuncSetAttribute(qkv_gemm_kernel, cudaFuncAttributeMaxDynamicSharedMemorySize, GEMM_SMEM);
    cudaFuncSetAttribute(conv_mma_kernel, cudaFuncAttributeMaxDynamicSharedMemorySize, CONV_SMEM);

    prep_kernel<<<(256*256*9 + 255)/256, 256>>>(h_qkv_w, h_bn_qkv, h_bn_sim, h_bn_out,
                                                w_qkv_w, w_bn_qkv, w_bn_sim, w_bn_out,
                                                conv_w, h_rel, w_rel);
    patchify_kernel<<<NPATCH*256, 256>>>(x);
    qkv_gemm_kernel<<<dim3(16,4,NPATCH), 256, GEMM_SMEM>>>(0);
    axial_kernel<<<NB, 1024, AX_SMEM>>>(0);
    transpose_kernel<<<NPATCH*256, 256>>>();
    qkv_gemm_kernel<<<dim3(16,4,NPATCH), 256, GEMM_SMEM>>>(1);
    axial_kernel<<<NB, 1024, AX_SMEM>>>(1);
    conv_in_prep<<<NPATCH*46, 256>>>();
    conv_mma_kernel<<<NPATCH*36, 256, CONV_SMEM>>>(conv_b, out);
}

// round 10
// speedup vs baseline: 2.0471x; 1.0457x over previous
#include <cuda_runtime.h>
#include <cuda_bf16.h>
#include <cuda_fp16.h>
#include <math.h>
#include <cstdint>

#define EPS 1e-5f
#define NPATCH 64
#define HS 44
#define NB (NPATCH*HS)          // 2816
#define PLANE 1936
#define IMGSZ (256*1936)

// padded conv geometry
#define PPX 2208
#define MARGIN_LO 128
#define XROWS (MARGIN_LO + NPATCH*PPX + 256)

typedef unsigned long long ull;
__device__ __forceinline__ void fma2(float2 &d, float2 a, float2 b) {
    asm("fma.rn.f32x2 %0, %1, %2, %0;"
        : "+l"(reinterpret_cast<ull&>(d))
        : "l"(reinterpret_cast<ull&>(a)), "l"(reinterpret_cast<ull&>(b)));
}
__device__ __forceinline__ float2 h2f(uint32_t u) {
    __half2 h = *reinterpret_cast<__half2*>(&u);
    return __half22float2(h);
}

// ---------------- mma / ldmatrix / cp.async helpers ----------------
__device__ __forceinline__ uint32_t smem_to_u32(const void* p) {
    uint32_t a;
    asm("{ .reg .u64 t; cvta.to.shared.u64 t, %1; cvt.u32.u64 %0, t; }" : "=r"(a) : "l"(p));
    return a;
}
__device__ __forceinline__ void ldsm_x4(uint32_t a[4], uint32_t addr) {
    asm volatile("ldmatrix.sync.aligned.m8n8.x4.shared.b16 {%0,%1,%2,%3}, [%4];"
        : "=r"(a[0]),"=r"(a[1]),"=r"(a[2]),"=r"(a[3]) : "r"(addr));
}
__device__ __forceinline__ void ldsm_x2_t(uint32_t b[2], uint32_t addr) {
    asm volatile("ldmatrix.sync.aligned.m8n8.x2.trans.shared.b16 {%0,%1}, [%2];"
        : "=r"(b[0]),"=r"(b[1]) : "r"(addr));
}
__device__ __forceinline__ void mma_bf16(float c[4], const uint32_t a[4], const uint32_t b[2]) {
    asm volatile("mma.sync.aligned.m16n8k16.row.col.f32.bf16.bf16.f32 "
        "{%0,%1,%2,%3}, {%4,%5,%6,%7}, {%8,%9}, {%0,%1,%2,%3};"
        : "+f"(c[0]),"+f"(c[1]),"+f"(c[2]),"+f"(c[3])
        : "r"(a[0]),"r"(a[1]),"r"(a[2]),"r"(a[3]), "r"(b[0]),"r"(b[1]));
}
__device__ __forceinline__ void cp16(uint32_t saddr, const void* g) {
    asm volatile("cp.async.cg.shared.global [%0], [%1], 16;" :: "r"(saddr), "l"(g));
}
#define CP_COMMIT() asm volatile("cp.async.commit_group;" ::: "memory")
#define CP_WAIT(n)  asm volatile("cp.async.wait_group %0;" :: "n"(n) : "memory")

// ---------------- static device scratch ----------------
__device__ float g_p [NPATCH*IMGSZ];
__device__ float g_t1[NPATCH*IMGSZ];
__device__ float g_qkv[(size_t)NPATCH*512*PLANE];
__device__ float g_qkvb[2][512];
__device__ float g_simA[2][12];
__device__ float g_simBsum[2][4];
__device__ float g_outA_sv[2][256];
__device__ float g_outA_sve[2][256];
__device__ float g_outB[2][256];
__device__ __half g_relTh[2][87*72];
__device__ uint32_t g_rvP[2][5632];
// tensor-core operand buffers
__device__ __align__(1024) __nv_bfloat16 g_xbh[(size_t)NPATCH*256*PLANE + 256];
__device__ __align__(1024) __nv_bfloat16 g_xbl[(size_t)NPATCH*256*PLANE + 256];
__device__ __align__(1024) __nv_bfloat16 g_qwh[2][512*256];
__device__ __align__(1024) __nv_bfloat16 g_qwl[2][512*256];
__device__ __align__(1024) __nv_bfloat16 g_xh[(size_t)XROWS*256];
__device__ __align__(1024) __nv_bfloat16 g_xl[(size_t)XROWS*256];
__device__ __align__(1024) __nv_bfloat16 g_wh[9*256*256];
__device__ __align__(1024) __nv_bfloat16 g_wl[9*256*256];

// ---------------- prep ----------------
__global__ void prep_kernel(const float* __restrict__ h_qkv_w, const float* __restrict__ h_bn_qkv,
                            const float* __restrict__ h_bn_sim, const float* __restrict__ h_bn_out,
                            const float* __restrict__ w_qkv_w, const float* __restrict__ w_bn_qkv,
                            const float* __restrict__ w_bn_sim, const float* __restrict__ w_bn_out,
                            const float* __restrict__ conv_w,
                            const float* __restrict__ h_rel, const float* __restrict__ w_rel)
{
    int idx = blockIdx.x * blockDim.x + threadIdx.x;
    const __nv_bfloat16 zero = __float2bfloat16(0.f);

    if (idx < 256*256*9) {
        int co  = idx / 2304;
        int rem = idx - co*2304;
        int ci  = rem / 9;
        int tap = rem - ci*9;
        float w = conv_w[idx];
        __nv_bfloat16 hi = __float2bfloat16(w);
        float lo = w - __bfloat162float(hi);
        g_wh[(tap*256 + ci)*256 + co] = hi;
        g_wl[(tap*256 + ci)*256 + co] = __float2bfloat16(lo);
    }
    if (idx < MARGIN_LO*256) {
        g_xh[idx] = zero;
        g_xl[idx] = zero;
    }
    if (idx < 256*256) {
        size_t off = (size_t)(MARGIN_LO + NPATCH*PPX)*256 + idx;
        g_xh[off] = zero;
        g_xl[off] = zero;
    }
    // NHWC patch-border zeroing: rows py=0/45, cols x in {0,45,46,47}
    for (int z = idx; z < NPATCH*69632; z += 2304*256) {
        int n = z / 69632, e = z - n*69632;
        int py, x, ch;
        if (e < 12288)      { py = 0;  x = e >> 8;              ch = e & 255; }
        else if (e < 24576) { int e2 = e - 12288; py = 45; x = e2 >> 8; ch = e2 & 255; }
        else {
            int e2 = e - 24576;
            py = 1 + (e2 >> 10);
            int r2 = e2 & 1023;
            int xi = r2 >> 8;
            x = (xi == 0) ? 0 : (44 + xi);
            ch = r2 & 255;
        }
        size_t a = ((size_t)MARGIN_LO + (size_t)n*PPX + py*48 + x)*256 + ch;
        g_xh[a] = zero;
        g_xl[a] = zero;
    }
    if (idx < 2*131072) {
        int ax = idx >> 17;
        int r  = idx & 131071;
        int o  = r & 511;
        int c  = r >> 9;
        const float* bn = ax ? w_bn_qkv : h_bn_qkv;
        const float* W  = ax ? w_qkv_w : h_qkv_w;
        float s = bn[o] * rsqrtf(bn[1536+o] + EPS);
        float wv = W[o*256 + c] * s;
        __nv_bfloat16 hi = __float2bfloat16(wv);
        float lo = wv - __bfloat162float(hi);
        g_qwh[ax][o*256 + c] = hi;
        g_qwl[ax][o*256 + c] = __float2bfloat16(lo);
        if (c == 0) g_qkvb[ax][o] = bn[512+o] - bn[1024+o]*s;
    }
    if (idx < 8) {
        int ax = idx >> 2, g = idx & 3;
        const float* bs = ax ? w_bn_sim : h_bn_sim;
        float shsum = 0.f;
        #pragma unroll
        for (int p = 0; p < 3; p++) {
            int ch = p*4 + g;
            float s = bs[ch] * rsqrtf(bs[36+ch] + EPS);
            g_simA[ax][p*4+g] = (p == 0 ? 1.f : 0.1f) * s;
            shsum += bs[12+ch] - bs[24+ch]*s;
        }
        g_simBsum[ax][g] = shsum;
    }
    if (idx < 512) {
        int ax = idx >> 8, cc = idx & 255;
        const float* bo = ax ? w_bn_out : h_bn_out;
        int o1 = 2*cc, o2 = 2*cc + 1;
        float s1 = bo[o1] * rsqrtf(bo[1536+o1] + EPS);
        float s2 = bo[o2] * rsqrtf(bo[1536+o2] + EPS);
        g_outA_sv[ax][cc]  = s1;
        g_outA_sve[ax][cc] = 0.1f * s2;
        g_outB[ax][cc] = (bo[512+o1] - bo[1024+o1]*s1) + (bo[512+o2] - bo[1024+o2]*s2);
    }
    if (idx < 2*87*72) {
        int ax = idx / 6264, r = idx - ax*6264;
        int d = r / 72, c = r - d*72;
        const float* rl = ax ? w_rel : h_rel;
        g_relTh[ax][r] = __float2half(c < 64 ? rl[c*87 + d] : 0.f);
    }
    if (idx < 2*5632) {
        int ax = idx / 5632, r = idx - ax*5632;
        int par = r / 2816, r2 = r - par*2816;
        int dhalf = r2 >> 6, c = r2 & 63;
        const float* rl = ax ? w_rel : h_rel;
        int d0 = 2*dhalf + par;
        float lo = (d0     <= 86) ? rl[(64+c)*87 + 86 - d0]     : 0.f;
        float hi = (d0 + 1 <= 86) ? rl[(64+c)*87 + 86 - d0 - 1] : 0.f;
        __half2 h2v = __halves2half2(__float2half(lo), __float2half(hi));
        g_rvP[ax][par*2816 + dhalf*64 + c] = *reinterpret_cast<uint32_t*>(&h2v);
    }
}

// ---------------- patchify ----------------
__global__ void __launch_bounds__(256,1) patchify_kernel(const float* __restrict__ x)
{
    __shared__ float tile[44*45];
    const int b = blockIdx.x;
    const int np = b >> 8, c = b & 255;
    const int bb_ = np >> 2, i2 = (np >> 1) & 1, j2 = np & 1;
    const float* src = x + ((size_t)(bb_*256 + c)*88 + i2*44)*88 + j2*44;
    float* dp = g_p + (size_t)b*1936;
    const int t = threadIdx.x;
    for (int idx = t; idx < 1936; idx += 256) {
        int y = idx / 44, xq = idx - y*44;
        float v = src[y*88 + xq];
        dp[idx] = v;
        tile[xq*45 + y] = v;
    }
    __syncthreads();
    const size_t base = (size_t)b*1936;
    for (int idx = t; idx < 1936; idx += 256) {
        int r = idx / 44, col = idx - r*44;
        float val = tile[r*45 + col];
        __nv_bfloat16 hi = __float2bfloat16(val);
        g_xbh[base + idx] = hi;
        g_xbl[base + idx] = __float2bfloat16(val - __bfloat162float(hi));
    }
}

// ---------------- transpose g_t1 [c][x][y] -> bf16 hi/lo [c][y][x] ----------------
__global__ void __launch_bounds__(256,1) transpose_kernel()
{
    __shared__ float tile[44*45];
    const int b = blockIdx.x;
    const float* src = g_t1 + (size_t)b*1936;
    const int t = threadIdx.x;
    for (int idx = t; idx < 1936; idx += 256) {
        int r = idx / 44, col = idx - r*44;
        tile[col*45 + r] = src[idx];
    }
    __syncthreads();
    const size_t base = (size_t)b*1936;
    for (int idx = t; idx < 1936; idx += 256) {
        int r = idx / 44, col = idx - r*44;
        float val = tile[r*45 + col];
        __nv_bfloat16 hi = __float2bfloat16(val);
        g_xbh[base + idx] = hi;
        g_xbl[base + idx] = __float2bfloat16(val - __bfloat162float(hi));
    }
}

// ---------------- qkv GEMM v2: B-panel resident, mtile loop ----------------
// smem: Bh[256*272]@0 | Bl@69632 | A stages @139264 (2 x 12288: Ah 6144 + Al 6144)
#define QB_BL   69632
#define QB_A    139264
#define QB_AST  12288
#define QB_ALO  6144
#define GEMM_SMEM 163840

__global__ void __launch_bounds__(256,1) qkv_gemm_kernel(int ax)
{
    extern __shared__ char smc[];
    const uint32_t sbase = smem_to_u32(smc);
    const int t = threadIdx.x;
    const int wid = t >> 5, lane = t & 31;
    const int ntile = blockIdx.x;
    const int n     = blockIdx.y;
    const int pxw = ntile * 128;
    const int wm = wid & 1, wn = wid >> 1;
    const __nv_bfloat16* qwh = g_qwh[ax];
    const __nv_bfloat16* qwl = g_qwl[ax];

    // load full B panel (x, hi/lo): 256 k-rows x 128 pos
    for (int j = t; j < 8192; j += 256) {
        int hl = j >> 12;
        int idx2 = j & 4095;
        int row = idx2 >> 4, unit = idx2 & 15;
        const __nv_bfloat16* g = (hl ? g_xbl : g_xbh)
            + ((size_t)(n*256 + row))*1936 + pxw + unit*8;
        cp16(sbase + hl*QB_BL + row*272 + unit*16, g);
    }
    CP_COMMIT();
    CP_WAIT(0);
    __syncthreads();

    auto load_A = [&](int mtile, int kc, int stage) {
        const int mrow0 = mtile*128;
        const uint32_t sA = sbase + QB_A + stage*QB_AST;
        #pragma unroll
        for (int i = 0; i < 2; i++) {
            int o = t + 256*i;
            int hl   = o & 1;
            int half = (o >> 1) & 1;
            int row  = o >> 2;
            const __nv_bfloat16* g = (hl ? qwl : qwh) + (size_t)(mrow0 + row)*256 + kc*16 + half*8;
            cp16(sA + hl*QB_ALO + row*48 + half*16, g);
        }
    };

    for (int mtile = 0; mtile < 4; mtile++) {
        float acc[4][4][4];
        #pragma unroll
        for (int mf = 0; mf < 4; mf++)
            #pragma unroll
            for (int nf = 0; nf < 4; nf++)
                #pragma unroll
                for (int k = 0; k < 4; k++) acc[mf][nf][k] = 0.f;

        load_A(mtile, 0, 0); CP_COMMIT();
        load_A(mtile, 1, 1); CP_COMMIT();

        for (int kc = 0; kc < 16; kc++) {
            const int stage = kc & 1;
            if (kc + 1 < 16) { CP_WAIT(1); }
            else             { CP_WAIT(0); }
            __syncthreads();

            const uint32_t sA = sbase + QB_A + stage*QB_AST;
            uint32_t Ah[4][4], Al[4][4], Bh[4][2], Bl[4][2];
            #pragma unroll
            for (int mf = 0; mf < 4; mf++) {
                uint32_t a_off = (wm*64 + mf*16 + (lane & 15))*48 + (lane >> 4)*16;
                ldsm_x4(Ah[mf], sA + a_off);
                ldsm_x4(Al[mf], sA + QB_ALO + a_off);
            }
            #pragma unroll
            for (int nf = 0; nf < 4; nf++) {
                uint32_t b_off = (kc*16 + (lane & 15))*272 + (wn*32 + nf*8)*2;
                ldsm_x2_t(Bh[nf], sbase + b_off);
                ldsm_x2_t(Bl[nf], sbase + QB_BL + b_off);
            }
            __syncthreads();
            if (kc + 2 < 16) { load_A(mtile, kc+2, stage); CP_COMMIT(); }
            #pragma unroll
            for (int mf = 0; mf < 4; mf++)
                #pragma unroll
                for (int nf = 0; nf < 4; nf++) {
                    mma_bf16(acc[mf][nf], Ah[mf], Bh[nf]);
                    mma_bf16(acc[mf][nf], Ah[mf], Bl[nf]);
                    mma_bf16(acc[mf][nf], Al[mf], Bh[nf]);
                }
        }

        // epilogue: direct float2 stores + bias
        const int mrow0 = mtile*128;
        #pragma unroll
        for (int mf = 0; mf < 4; mf++) {
            int row0 = mrow0 + wm*64 + mf*16 + (lane >> 2);
            #pragma unroll
            for (int nf = 0; nf < 4; nf++) {
                int pos = pxw + wn*32 + nf*8 + (lane & 3)*2;
                if (pos < 1936) {
                    float b0 = g_qkvb[ax][row0];
                    float b1 = g_qkvb[ax][row0 + 8];
                    *(float2*)(g_qkv + ((size_t)n*512 + row0)*1936 + pos) =
                        make_float2(acc[mf][nf][0] + b0, acc[mf][nf][1] + b0);
                    *(float2*)(g_qkv + ((size_t)n*512 + row0 + 8)*1936 + pos) =
                        make_float2(acc[mf][nf][2] + b1, acc[mf][nf][3] + b1);
                }
            }
        }
        __syncthreads();
    }
}

// ---------------- fused axial attention v7 ----------------
// floats: qkT/stage[44][260]@0 | vS[256][44]@11440 | sim[4][44][44]@22704 |
//         relTh(3132u)@30448 | rvP(5632u)@33580 | resS[256][44]@39212 (AX=1)
#define OFF_V    11440
#define OFF_SIM  22704
#define OFF_RTH  30448
#define OFF_RVP  33580
#define OFF_RES  39212
#define AX_SMEM  (50476*4)

template<int AX>
__global__ void __launch_bounds__(1024,1) axial_kernel()
{
    extern __shared__ float sm[];
    float* qkT  = sm;
    float* vS   = sm + OFF_V;
    float* simS = sm + OFF_SIM;
    const __half* rTh = (const __half*)(sm + OFF_RTH);
    uint32_t* rvS = (uint32_t*)(sm + OFF_RVP);
    float* resS = sm + OFF_RES;

    const int t  = threadIdx.x;
    const int bb = blockIdx.x;
    const int n  = bb / 44;
    const int s  = bb - n*44;

    // load qkv slice + fp16 rel tables (+ residual for AX=1)
    {
        const float* qsrc = g_qkv + (size_t)n*512*1936 + s*44;
        for (int idx = t; idx < 5632; idx += 1024) {
            int o = idx / 11, q = idx - o*11;
            float4 v4 = *(const float4*)(qsrc + (size_t)o*1936 + q*4);
            int g = o >> 7, wi = o & 127;
            if (wi < 64) {
                int col = g*64 + wi;
                qkT[(q*4+0)*260 + col] = v4.x;
                qkT[(q*4+1)*260 + col] = v4.y;
                qkT[(q*4+2)*260 + col] = v4.z;
                qkT[(q*4+3)*260 + col] = v4.w;
            } else {
                *(float4*)(vS + (g*64 + wi - 64)*44 + q*4) = v4;
            }
        }
        const uint32_t* rthG = (const uint32_t*)g_relTh[AX];
        uint32_t* rthS = (uint32_t*)(sm + OFF_RTH);
        for (int idx = t; idx < 3132; idx += 1024) rthS[idx] = rthG[idx];
        for (int idx = t; idx < 5632; idx += 1024) rvS[idx] = g_rvP[AX][idx];
        if (AX == 1) {
            const float4* rsrc = (const float4*)(g_p + (size_t)n*IMGSZ + s*44);
            float4* rd = (float4*)resS;
            for (int idx = t; idx < 2816; idx += 1024) {
                int ch = idx / 11, q = idx - ch*11;
                rd[idx] = rsrc[ch*484 + q];
            }
        }
    }
    __syncthreads();

    // sim
    for (int e = t; e < 7744; e += 1024) {
        int g = e / 1936;
        int r = e - g*1936;
        int i = r / 44;
        int j = r - i*44;
        const float4* qp = (const float4*)(qkT + i*260 + g*64);
        const float4* kp = (const float4*)(qkT + j*260 + g*64 + 32);
        const uint4* rq = (const uint4*)(rTh + (i - j + 43)*72);
        const uint4* rk = (const uint4*)(rTh + (j - i + 43)*72 + 32);
        float2 qk2 = make_float2(0.f,0.f), qr2 = qk2, kr2 = qk2;
        #pragma unroll
        for (int cc = 0; cc < 4; cc++) {
            float4 q4a = qp[2*cc], q4b = qp[2*cc+1];
            float4 k4a = kp[2*cc], k4b = kp[2*cc+1];
            uint4 rqu = rq[cc], rku = rk[cc];
            fma2(qk2, make_float2(q4a.x,q4a.y), make_float2(k4a.x,k4a.y));
            fma2(qk2, make_float2(q4a.z,q4a.w), make_float2(k4a.z,k4a.w));
            fma2(qk2, make_float2(q4b.x,q4b.y), make_float2(k4b.x,k4b.y));
            fma2(qk2, make_float2(q4b.z,q4b.w), make_float2(k4b.z,k4b.w));
            fma2(qr2, make_float2(q4a.x,q4a.y), h2f(rqu.x));
            fma2(qr2, make_float2(q4a.z,q4a.w), h2f(rqu.y));
            fma2(qr2, make_float2(q4b.x,q4b.y), h2f(rqu.z));
            fma2(qr2, make_float2(q4b.z,q4b.w), h2f(rqu.w));
            fma2(kr2, make_float2(k4a.x,k4a.y), h2f(rku.x));
            fma2(kr2, make_float2(k4a.z,k4a.w), h2f(rku.y));
            fma2(kr2, make_float2(k4b.x,k4b.y), h2f(rku.z));
            fma2(kr2, make_float2(k4b.z,k4b.w), h2f(rku.w));
        }
        float qk = qk2.x + qk2.y, qr = qr2.x + qr2.y, kr = kr2.x + kr2.y;
        simS[e] = g_simA[AX][g]*qk + g_simA[AX][4+g]*qr + g_simA[AX][8+g]*kr + g_simBsum[AX][g];
    }
    __syncthreads();

    // softmax: warp per row
    {
        const int wid = t >> 5, lane = t & 31;
        #pragma unroll
        for (int k = 0; k < 6; k++) {
            int r = wid + 32*k;
            if (r < 176) {
                float* row = simS + (r/44)*1936 + (r - (r/44)*44)*44;
                float v1 = row[lane];
                float v2 = (lane < 12) ? row[lane+32] : -1e30f;
                float m = fmaxf(v1, v2);
                #pragma unroll
                for (int off = 16; off; off >>= 1) m = fmaxf(m, __shfl_xor_sync(0xffffffffu, m, off));
                float e1 = __expf(v1 - m);
                float e2 = (lane < 12) ? __expf(v2 - m) : 0.f;
                float su = e1 + e2;
                #pragma unroll
                for (int off = 16; off; off >>= 1) su += __shfl_xor_sync(0xffffffffu, su, off);
                float inv = 1.f / su;
                row[lane] = e1 * inv;
                if (lane < 12) row[lane+32] = e2 * inv;
            }
        }
    }
    __syncthreads();

    // output
    {
        const int ch = t & 255, qtr = t >> 8;
        const int g = ch >> 6, c = ch & 63;
        float2 v2[22];
        const float4* vp = (const float4*)(vS + ch*44);
        #pragma unroll
        for (int q = 0; q < 11; q++) {
            float4 v4 = vp[q];
            v2[2*q]   = make_float2(v4.x, v4.y);
            v2[2*q+1] = make_float2(v4.z, v4.w);
        }
        const float aSV  = g_outA_sv[AX][ch];
        const float aSVE = g_outA_sve[AX][ch];
        const float bO   = g_outB[AX][ch];
        #pragma unroll 1
        for (int ii = 0; ii < 11; ii++) {
            int i = qtr*11 + ii;
            const float2* sr2 = (const float2*)(simS + g*1936 + i*44);
            int b0 = 43 - i;
            const uint32_t* wrow = rvS + (b0 & 1)*2816 + (b0 >> 1)*64 + c;
            float2 sv2 = make_float2(0.f, 0.f), sve2 = make_float2(0.f, 0.f);
            #pragma unroll
            for (int p = 0; p < 22; p++) {
                float2 s2 = sr2[p];
                fma2(sv2, s2, v2[p]);
                fma2(sve2, s2, h2f(wrow[p*64]));
            }
            float val = fmaf(aSV, sv2.x + sv2.y, fmaf(aSVE, sve2.x + sve2.y, bO));
            if (AX == 0) {
                qkT[ch*44 + i] = val;                 // stage [ch][i]
            } else {
                qkT[i*256 + ch] = val + resS[ch*44 + i];   // stage [i][ch] with residual
            }
        }
    }
    __syncthreads();
    if (AX == 0) {
        float* out = g_t1;
        const float4* st4 = (const float4*)qkT;
        for (int idx = t; idx < 2816; idx += 1024) {
            int ch = idx / 11, q = idx - ch*11;
            *(float4*)(out + ((size_t)(n*256 + ch))*1936 + s*44 + q*4) = st4[idx];
        }
    } else {
        // NHWC bf16 hi/lo stores: py = s+1, x = i+1, ch fast (coalesced)
        const size_t rowbase = ((size_t)MARGIN_LO + (size_t)n*PPX + (size_t)(s+1)*48 + 1)*256;
        for (int idx = t; idx < 11264; idx += 1024) {
            int i = idx >> 8, ch = idx & 255;
            float val = qkT[i*256 + ch];
            __nv_bfloat16 hi = __float2bfloat16(val);
            size_t a = rowbase + (size_t)i*256 + ch;
            g_xh[a] = hi;
            g_xl[a] = __float2bfloat16(val - __bfloat162float(hi));
        }
    }
}

// ---------------- tensor-core conv3x3 (3-stage) ----------------
#define CSTAGE 20992
#define OFF_AL 6144
#define OFF_BH 12288
#define OFF_BL 16640
#define CONV_SMEM (3*CSTAGE + 512)

__global__ void __launch_bounds__(256,1) conv_mma_kernel(const float* __restrict__ conv_b,
                                                         float* __restrict__ out)
{
    extern __shared__ char smc[];
    const uint32_t sbase = smem_to_u32(smc);
    const int t = threadIdx.x;
    const int wid = t >> 5, lane = t & 31;
    const int bb = blockIdx.x;
    const int n = bb / 36;
    const int r_ = bb - n*36;
    const int widx = r_ >> 1, cohalf = r_ & 1;
    const int pxw = widx * 128;
    const int wm = wid & 1, wn = wid >> 1;

    float* biasS = (float*)(smc + 3*CSTAGE);
    if (t < 128) biasS[t] = conv_b[cohalf*128 + t];

    const long long arow0 = (long long)MARGIN_LO + (long long)n*PPX + pxw;

    auto load_chunk = [&](int kc, int stage) {
        const int tap = kc >> 4, sub = kc & 15;
        const int offr = (tap/3 - 1)*48 + (tap%3 - 1);
        const long long abase = arow0 + offr;
        const uint32_t sA = sbase + stage*CSTAGE;
        const uint32_t sB = sA + OFF_BH;
        #pragma unroll
        for (int i = 0; i < 4; i++) {
            int o = t + 256*i;
            if (o < 512) {
                int hl   = o & 1;
                int half = (o >> 1) & 1;
                int row  = o >> 2;
                const __nv_bfloat16* g = (hl ? g_xl : g_xh) + ((size_t)(abase + row))*256 + sub*16 + half*8;
                cp16(sA + hl*OFF_AL + row*48 + half*16, g);
            } else {
                int o2 = o - 512;
                int hl = o2 & 1;
                int rest = o2 >> 1;
                int krow = rest >> 4, unit = rest & 15;
                const __nv_bfloat16* g = (hl ? g_wl : g_wh)
                    + ((size_t)(tap*256 + sub*16 + krow))*256 + cohalf*128 + unit*8;
                cp16(sB + hl*(OFF_BL-OFF_BH) + krow*272 + unit*16, g);
            }
        }
    };

    float acc[4][4][4];
    #pragma unroll
    for (int mf = 0; mf < 4; mf++)
        #pragma unroll
        for (int nf = 0; nf < 4; nf++)
            #pragma unroll
            for (int k = 0; k < 4; k++) acc[mf][nf][k] = 0.f;

    load_chunk(0, 0); CP_COMMIT();
    load_chunk(1, 1); CP_COMMIT();

    for (int kc = 0; kc < 144; kc++) {
        const int stage = kc % 3;
        if (kc + 2 < 144) { load_chunk(kc+2, (kc+2)%3); CP_COMMIT(); CP_WAIT(2); }
        else if (kc + 1 < 144) { CP_WAIT(1); }
        else { CP_WAIT(0); }
        __syncthreads();

        const uint32_t sA = sbase + stage*CSTAGE;
        const uint32_t sB = sA + OFF_BH;

        uint32_t Ah[4][4], Al[4][4], Bh[4][2], Bl[4][2];
        #pragma unroll
        for (int mf = 0; mf < 4; mf++) {
            uint32_t a_off = (wm*64 + mf*16 + (lane & 15))*48 + (lane >> 4)*16;
            ldsm_x4(Ah[mf], sA + a_off);
            ldsm_x4(Al[mf], sA + OFF_AL + a_off);
        }
        #pragma unroll
        for (int nf = 0; nf < 4; nf++) {
            uint32_t b_off = (lane & 15)*272 + (wn*32 + nf*8)*2;
            ldsm_x2_t(Bh[nf], sB + b_off);
            ldsm_x2_t(Bl[nf], sB + (OFF_BL - OFF_BH) + b_off);
        }
        #pragma unroll
        for (int mf = 0; mf < 4; mf++)
            #pragma unroll
            for (int nf = 0; nf < 4; nf++) {
                mma_bf16(acc[mf][nf], Ah[mf], Bh[nf]);
                mma_bf16(acc[mf][nf], Ah[mf], Bl[nf]);
                mma_bf16(acc[mf][nf], Al[mf], Bh[nf]);
            }
        __syncthreads();
    }

    const int b_ = n >> 2, i2 = (n >> 1) & 1, j2 = n & 1;
    #pragma unroll
    for (int mf = 0; mf < 4; mf++) {
        #pragma unroll
        for (int half = 0; half < 2; half++) {
            int px = pxw + wm*64 + mf*16 + (lane >> 2) + half*8;
            int py = px / 48, pxx = px - py*48;
            bool valid = (py >= 1 && py <= 44) && (pxx >= 1 && pxx <= 44);
            if (!valid) continue;
            size_t ob = ((size_t)(b_*256))*7744 + (size_t)(i2*44 + (py-1))*88 + j2*44 + (pxx-1);
            #pragma unroll
            for (int nf = 0; nf < 4; nf++) {
                int col = wn*32 + nf*8 + (lane & 3)*2;
                int co = cohalf*128 + col;
                out[ob + (size_t)co*7744]     = acc[mf][nf][half*2+0] + biasS[col];
                out[ob + (size_t)(co+1)*7744] = acc[mf][nf][half*2+1] + biasS[col+1];
            }
        }
    }
}

// ---------------- launch ----------------
extern "C" void kernel_launch(void* const* d_in, const int* in_sizes, int n_in,
                              void* d_out, int out_size)
{
    const float* x        = (const float*)d_in[0];
    const float* h_qkv_w  = (const float*)d_in[1];
    const float* h_bn_qkv = (const float*)d_in[2];
    const float* h_bn_sim = (const float*)d_in[3];
    const float* h_bn_out = (const float*)d_in[4];
    const float* h_rel    = (const float*)d_in[5];
    const float* w_qkv_w  = (const float*)d_in[6];
    const float* w_bn_qkv = (const float*)d_in[7];
    const float* w_bn_sim = (const float*)d_in[8];
    const float* w_bn_out = (const float*)d_in[9];
    const float* w_rel    = (const float*)d_in[10];
    const float* conv_w   = (const float*)d_in[11];
    const float* conv_b   = (const float*)d_in[12];
    float* out = (float*)d_out;

    cudaFuncSetAttribute(axial_kernel<0>,  cudaFuncAttributeMaxDynamicSharedMemorySize, AX_SMEM);
    cudaFuncSetAttribute(axial_kernel<1>,  cudaFuncAttributeMaxDynamicSharedMemorySize, AX_SMEM);
    cudaFuncSetAttribute(qkv_gemm_kernel,  cudaFuncAttributeMaxDynamicSharedMemorySize, GEMM_SMEM);
    cudaFuncSetAttribute(conv_mma_kernel,  cudaFuncAttributeMaxDynamicSharedMemorySize, CONV_SMEM);

    prep_kernel<<<(256*256*9 + 255)/256, 256>>>(h_qkv_w, h_bn_qkv, h_bn_sim, h_bn_out,
                                                w_qkv_w, w_bn_qkv, w_bn_sim, w_bn_out,
                                                conv_w, h_rel, w_rel);
    patchify_kernel<<<NPATCH*256, 256>>>(x);
    qkv_gemm_kernel<<<dim3(16,NPATCH), 256, GEMM_SMEM>>>(0);
    axial_kernel<0><<<NB, 1024, AX_SMEM>>>();
    transpose_kernel<<<NPATCH*256, 256>>>();
    qkv_gemm_kernel<<<dim3(16,NPATCH), 256, GEMM_SMEM>>>(1);
    axial_kernel<1><<<NB, 1024, AX_SMEM>>>();
    conv_mma_kernel<<<NPATCH*36, 256, CONV_SMEM>>>(conv_b, out);
}

// round 11
// speedup vs baseline: 2.2264x; 1.0876x over previous
#include <cuda_runtime.h>
#include <cuda_bf16.h>
#include <cuda_fp16.h>
#include <math.h>
#include <cstdint>

#define EPS 1e-5f
#define NPATCH 64
#define HS 44
#define NB (NPATCH*HS)          // 2816
#define PLANE 1936
#define IMGSZ (256*1936)

// padded conv geometry
#define PPX 2208
#define MARGIN_LO 128
#define XROWS (MARGIN_LO + NPATCH*PPX + 256)

typedef unsigned long long ull;
__device__ __forceinline__ void fma2(float2 &d, float2 a, float2 b) {
    asm("fma.rn.f32x2 %0, %1, %2, %0;"
        : "+l"(reinterpret_cast<ull&>(d))
        : "l"(reinterpret_cast<ull&>(a)), "l"(reinterpret_cast<ull&>(b)));
}
__device__ __forceinline__ float2 h2f(uint32_t u) {
    __half2 h = *reinterpret_cast<__half2*>(&u);
    return __half22float2(h);
}

// ---------------- mma / ldmatrix / cp.async helpers ----------------
__device__ __forceinline__ uint32_t smem_to_u32(const void* p) {
    uint32_t a;
    asm("{ .reg .u64 t; cvta.to.shared.u64 t, %1; cvt.u32.u64 %0, t; }" : "=r"(a) : "l"(p));
    return a;
}
__device__ __forceinline__ void ldsm_x4(uint32_t a[4], uint32_t addr) {
    asm volatile("ldmatrix.sync.aligned.m8n8.x4.shared.b16 {%0,%1,%2,%3}, [%4];"
        : "=r"(a[0]),"=r"(a[1]),"=r"(a[2]),"=r"(a[3]) : "r"(addr));
}
__device__ __forceinline__ void ldsm_x2_t(uint32_t b[2], uint32_t addr) {
    asm volatile("ldmatrix.sync.aligned.m8n8.x2.trans.shared.b16 {%0,%1}, [%2];"
        : "=r"(b[0]),"=r"(b[1]) : "r"(addr));
}
__device__ __forceinline__ void mma_bf16(float c[4], const uint32_t a[4], const uint32_t b[2]) {
    asm volatile("mma.sync.aligned.m16n8k16.row.col.f32.bf16.bf16.f32 "
        "{%0,%1,%2,%3}, {%4,%5,%6,%7}, {%8,%9}, {%0,%1,%2,%3};"
        : "+f"(c[0]),"+f"(c[1]),"+f"(c[2]),"+f"(c[3])
        : "r"(a[0]),"r"(a[1]),"r"(a[2]),"r"(a[3]), "r"(b[0]),"r"(b[1]));
}
__device__ __forceinline__ void cp16(uint32_t saddr, const void* g) {
    asm volatile("cp.async.cg.shared.global [%0], [%1], 16;" :: "r"(saddr), "l"(g));
}
#define CP_COMMIT() asm volatile("cp.async.commit_group;" ::: "memory")
#define CP_WAIT(n)  asm volatile("cp.async.wait_group %0;" :: "n"(n) : "memory")

// ---------------- static device scratch ----------------
__device__ float g_p [NPATCH*IMGSZ];
__device__ float g_t1[NPATCH*IMGSZ];
__device__ float g_qkv[(size_t)NPATCH*512*PLANE];
__device__ float g_qkvb[2][512];
__device__ float g_simA[2][12];
__device__ float g_simBsum[2][4];
__device__ float g_outA_sv[2][256];
__device__ float g_outA_sve[2][256];
__device__ float g_outB[2][256];
__device__ __half g_relTh[2][87*72];
__device__ uint32_t g_rvP[2][5632];
// tensor-core operand buffers
__device__ __align__(1024) __nv_bfloat16 g_xbh[(size_t)NPATCH*256*PLANE + 256];
__device__ __align__(1024) __nv_bfloat16 g_xbl[(size_t)NPATCH*256*PLANE + 256];
__device__ __align__(1024) __nv_bfloat16 g_qwh[2][512*256];
__device__ __align__(1024) __nv_bfloat16 g_qwl[2][512*256];
__device__ __align__(1024) __nv_bfloat16 g_xh[(size_t)XROWS*256];
__device__ __align__(1024) __nv_bfloat16 g_xl[(size_t)XROWS*256];
__device__ __align__(1024) __nv_bfloat16 g_wh[9*256*256];
__device__ __align__(1024) __nv_bfloat16 g_wl[9*256*256];

// ---------------- prep ----------------
__global__ void prep_kernel(const float* __restrict__ h_qkv_w, const float* __restrict__ h_bn_qkv,
                            const float* __restrict__ h_bn_sim, const float* __restrict__ h_bn_out,
                            const float* __restrict__ w_qkv_w, const float* __restrict__ w_bn_qkv,
                            const float* __restrict__ w_bn_sim, const float* __restrict__ w_bn_out,
                            const float* __restrict__ conv_w,
                            const float* __restrict__ h_rel, const float* __restrict__ w_rel)
{
    int idx = blockIdx.x * blockDim.x + threadIdx.x;
    const __nv_bfloat16 zero = __float2bfloat16(0.f);

    if (idx < 256*256*9) {
        int co  = idx / 2304;
        int rem = idx - co*2304;
        int ci  = rem / 9;
        int tap = rem - ci*9;
        float w = conv_w[idx];
        __nv_bfloat16 hi = __float2bfloat16(w);
        float lo = w - __bfloat162float(hi);
        g_wh[(tap*256 + ci)*256 + co] = hi;
        g_wl[(tap*256 + ci)*256 + co] = __float2bfloat16(lo);
    }
    if (idx < MARGIN_LO*256) {
        g_xh[idx] = zero;
        g_xl[idx] = zero;
    }
    if (idx < 256*256) {
        size_t off = (size_t)(MARGIN_LO + NPATCH*PPX)*256 + idx;
        g_xh[off] = zero;
        g_xl[off] = zero;
    }
    // NHWC patch-border zeroing
    for (int z = idx; z < NPATCH*69632; z += 2304*256) {
        int n = z / 69632, e = z - n*69632;
        int py, x, ch;
        if (e < 12288)      { py = 0;  x = e >> 8;              ch = e & 255; }
        else if (e < 24576) { int e2 = e - 12288; py = 45; x = e2 >> 8; ch = e2 & 255; }
        else {
            int e2 = e - 24576;
            py = 1 + (e2 >> 10);
            int r2 = e2 & 1023;
            int xi = r2 >> 8;
            x = (xi == 0) ? 0 : (44 + xi);
            ch = r2 & 255;
        }
        size_t a = ((size_t)MARGIN_LO + (size_t)n*PPX + py*48 + x)*256 + ch;
        g_xh[a] = zero;
        g_xl[a] = zero;
    }
    if (idx < 2*131072) {
        int ax = idx >> 17;
        int r  = idx & 131071;
        int o  = r & 511;
        int c  = r >> 9;
        const float* bn = ax ? w_bn_qkv : h_bn_qkv;
        const float* W  = ax ? w_qkv_w : h_qkv_w;
        float s = bn[o] * rsqrtf(bn[1536+o] + EPS);
        float wv = W[o*256 + c] * s;
        __nv_bfloat16 hi = __float2bfloat16(wv);
        float lo = wv - __bfloat162float(hi);
        g_qwh[ax][o*256 + c] = hi;
        g_qwl[ax][o*256 + c] = __float2bfloat16(lo);
        if (c == 0) g_qkvb[ax][o] = bn[512+o] - bn[1024+o]*s;
    }
    if (idx < 8) {
        int ax = idx >> 2, g = idx & 3;
        const float* bs = ax ? w_bn_sim : h_bn_sim;
        float shsum = 0.f;
        #pragma unroll
        for (int p = 0; p < 3; p++) {
            int ch = p*4 + g;
            float s = bs[ch] * rsqrtf(bs[36+ch] + EPS);
            g_simA[ax][p*4+g] = (p == 0 ? 1.f : 0.1f) * s;
            shsum += bs[12+ch] - bs[24+ch]*s;
        }
        g_simBsum[ax][g] = shsum;
    }
    if (idx < 512) {
        int ax = idx >> 8, cc = idx & 255;
        const float* bo = ax ? w_bn_out : h_bn_out;
        int o1 = 2*cc, o2 = 2*cc + 1;
        float s1 = bo[o1] * rsqrtf(bo[1536+o1] + EPS);
        float s2 = bo[o2] * rsqrtf(bo[1536+o2] + EPS);
        g_outA_sv[ax][cc]  = s1;
        g_outA_sve[ax][cc] = 0.1f * s2;
        g_outB[ax][cc] = (bo[512+o1] - bo[1024+o1]*s1) + (bo[512+o2] - bo[1024+o2]*s2);
    }
    if (idx < 2*87*72) {
        int ax = idx / 6264, r = idx - ax*6264;
        int d = r / 72, c = r - d*72;
        const float* rl = ax ? w_rel : h_rel;
        g_relTh[ax][r] = __float2half(c < 64 ? rl[c*87 + d] : 0.f);
    }
    if (idx < 2*5632) {
        int ax = idx / 5632, r = idx - ax*5632;
        int par = r / 2816, r2 = r - par*2816;
        int dhalf = r2 >> 6, c = r2 & 63;
        const float* rl = ax ? w_rel : h_rel;
        int d0 = 2*dhalf + par;
        float lo = (d0     <= 86) ? rl[(64+c)*87 + 86 - d0]     : 0.f;
        float hi = (d0 + 1 <= 86) ? rl[(64+c)*87 + 86 - d0 - 1] : 0.f;
        __half2 h2v = __halves2half2(__float2half(lo), __float2half(hi));
        g_rvP[ax][par*2816 + dhalf*64 + c] = *reinterpret_cast<uint32_t*>(&h2v);
    }
}

// ---------------- patchify ----------------
__global__ void __launch_bounds__(256,1) patchify_kernel(const float* __restrict__ x)
{
    __shared__ float tile[44*45];
    const int b = blockIdx.x;
    const int np = b >> 8, c = b & 255;
    const int bb_ = np >> 2, i2 = (np >> 1) & 1, j2 = np & 1;
    const float* src = x + ((size_t)(bb_*256 + c)*88 + i2*44)*88 + j2*44;
    float* dp = g_p + (size_t)b*1936;
    const int t = threadIdx.x;
    for (int idx = t; idx < 1936; idx += 256) {
        int y = idx / 44, xq = idx - y*44;
        float v = src[y*88 + xq];
        dp[idx] = v;
        tile[xq*45 + y] = v;
    }
    __syncthreads();
    const size_t base = (size_t)b*1936;
    for (int idx = t; idx < 1936; idx += 256) {
        int r = idx / 44, col = idx - r*44;
        float val = tile[r*45 + col];
        __nv_bfloat16 hi = __float2bfloat16(val);
        g_xbh[base + idx] = hi;
        g_xbl[base + idx] = __float2bfloat16(val - __bfloat162float(hi));
    }
}

// ---------------- transpose g_t1 [c][x][y] -> bf16 hi/lo [c][y][x] ----------------
__global__ void __launch_bounds__(256,1) transpose_kernel()
{
    __shared__ float tile[44*45];
    const int b = blockIdx.x;
    const float* src = g_t1 + (size_t)b*1936;
    const int t = threadIdx.x;
    for (int idx = t; idx < 1936; idx += 256) {
        int r = idx / 44, col = idx - r*44;
        tile[col*45 + r] = src[idx];
    }
    __syncthreads();
    const size_t base = (size_t)b*1936;
    for (int idx = t; idx < 1936; idx += 256) {
        int r = idx / 44, col = idx - r*44;
        float val = tile[r*45 + col];
        __nv_bfloat16 hi = __float2bfloat16(val);
        g_xbh[base + idx] = hi;
        g_xbl[base + idx] = __float2bfloat16(val - __bfloat162float(hi));
    }
}

// ---------------- qkv GEMM v2: B-panel resident, mtile loop ----------------
#define QB_BL   69632
#define QB_A    139264
#define QB_AST  12288
#define QB_ALO  6144
#define GEMM_SMEM 163840

__global__ void __launch_bounds__(256,1) qkv_gemm_kernel(int ax)
{
    extern __shared__ char smc[];
    const uint32_t sbase = smem_to_u32(smc);
    const int t = threadIdx.x;
    const int wid = t >> 5, lane = t & 31;
    const int ntile = blockIdx.x;
    const int n     = blockIdx.y;
    const int pxw = ntile * 128;
    const int wm = wid & 1, wn = wid >> 1;
    const __nv_bfloat16* qwh = g_qwh[ax];
    const __nv_bfloat16* qwl = g_qwl[ax];

    for (int j = t; j < 8192; j += 256) {
        int hl = j >> 12;
        int idx2 = j & 4095;
        int row = idx2 >> 4, unit = idx2 & 15;
        const __nv_bfloat16* g = (hl ? g_xbl : g_xbh)
            + ((size_t)(n*256 + row))*1936 + pxw + unit*8;
        cp16(sbase + hl*QB_BL + row*272 + unit*16, g);
    }
    CP_COMMIT();
    CP_WAIT(0);
    __syncthreads();

    auto load_A = [&](int mtile, int kc, int stage) {
        const int mrow0 = mtile*128;
        const uint32_t sA = sbase + QB_A + stage*QB_AST;
        #pragma unroll
        for (int i = 0; i < 2; i++) {
            int o = t + 256*i;
            int hl   = o & 1;
            int half = (o >> 1) & 1;
            int row  = o >> 2;
            const __nv_bfloat16* g = (hl ? qwl : qwh) + (size_t)(mrow0 + row)*256 + kc*16 + half*8;
            cp16(sA + hl*QB_ALO + row*48 + half*16, g);
        }
    };

    for (int mtile = 0; mtile < 4; mtile++) {
        float acc[4][4][4];
        #pragma unroll
        for (int mf = 0; mf < 4; mf++)
            #pragma unroll
            for (int nf = 0; nf < 4; nf++)
                #pragma unroll
                for (int k = 0; k < 4; k++) acc[mf][nf][k] = 0.f;

        load_A(mtile, 0, 0); CP_COMMIT();
        load_A(mtile, 1, 1); CP_COMMIT();

        for (int kc = 0; kc < 16; kc++) {
            const int stage = kc & 1;
            if (kc + 1 < 16) { CP_WAIT(1); }
            else             { CP_WAIT(0); }
            __syncthreads();

            const uint32_t sA = sbase + QB_A + stage*QB_AST;
            uint32_t Ah[4][4], Al[4][4], Bh[4][2], Bl[4][2];
            #pragma unroll
            for (int mf = 0; mf < 4; mf++) {
                uint32_t a_off = (wm*64 + mf*16 + (lane & 15))*48 + (lane >> 4)*16;
                ldsm_x4(Ah[mf], sA + a_off);
                ldsm_x4(Al[mf], sA + QB_ALO + a_off);
            }
            #pragma unroll
            for (int nf = 0; nf < 4; nf++) {
                uint32_t b_off = (kc*16 + (lane & 15))*272 + (wn*32 + nf*8)*2;
                ldsm_x2_t(Bh[nf], sbase + b_off);
                ldsm_x2_t(Bl[nf], sbase + QB_BL + b_off);
            }
            __syncthreads();
            if (kc + 2 < 16) { load_A(mtile, kc+2, stage); CP_COMMIT(); }
            #pragma unroll
            for (int mf = 0; mf < 4; mf++)
                #pragma unroll
                for (int nf = 0; nf < 4; nf++) {
                    mma_bf16(acc[mf][nf], Ah[mf], Bh[nf]);
                    mma_bf16(acc[mf][nf], Ah[mf], Bl[nf]);
                    mma_bf16(acc[mf][nf], Al[mf], Bh[nf]);
                }
        }

        const int mrow0 = mtile*128;
        #pragma unroll
        for (int mf = 0; mf < 4; mf++) {
            int row0 = mrow0 + wm*64 + mf*16 + (lane >> 2);
            #pragma unroll
            for (int nf = 0; nf < 4; nf++) {
                int pos = pxw + wn*32 + nf*8 + (lane & 3)*2;
                if (pos < 1936) {
                    float b0 = g_qkvb[ax][row0];
                    float b1 = g_qkvb[ax][row0 + 8];
                    *(float2*)(g_qkv + ((size_t)n*512 + row0)*1936 + pos) =
                        make_float2(acc[mf][nf][0] + b0, acc[mf][nf][1] + b0);
                    *(float2*)(g_qkv + ((size_t)n*512 + row0 + 8)*1936 + pos) =
                        make_float2(acc[mf][nf][2] + b1, acc[mf][nf][3] + b1);
                }
            }
        }
        __syncthreads();
    }
}

// ---------------- fused axial attention v8: group-paired sim ----------------
#define OFF_V    11440
#define OFF_SIM  22704
#define OFF_RTH  30448
#define OFF_RVP  33580
#define OFF_RES  39212
#define AX_SMEM  (50476*4)

template<int AX>
__global__ void __launch_bounds__(1024,1) axial_kernel()
{
    extern __shared__ float sm[];
    float* qkT  = sm;
    float* vS   = sm + OFF_V;
    float* simS = sm + OFF_SIM;
    const __half* rTh = (const __half*)(sm + OFF_RTH);
    uint32_t* rvS = (uint32_t*)(sm + OFF_RVP);
    float* resS = sm + OFF_RES;

    const int t  = threadIdx.x;
    const int bb = blockIdx.x;
    const int n  = bb / 44;
    const int s  = bb - n*44;

    // load qkv slice + fp16 rel tables (+ residual for AX=1)
    {
        const float* qsrc = g_qkv + (size_t)n*512*1936 + s*44;
        for (int idx = t; idx < 5632; idx += 1024) {
            int o = idx / 11, q = idx - o*11;
            float4 v4 = *(const float4*)(qsrc + (size_t)o*1936 + q*4);
            int g = o >> 7, wi = o & 127;
            if (wi < 64) {
                int col = g*64 + wi;
                qkT[(q*4+0)*260 + col] = v4.x;
                qkT[(q*4+1)*260 + col] = v4.y;
                qkT[(q*4+2)*260 + col] = v4.z;
                qkT[(q*4+3)*260 + col] = v4.w;
            } else {
                *(float4*)(vS + (g*64 + wi - 64)*44 + q*4) = v4;
            }
        }
        const uint32_t* rthG = (const uint32_t*)g_relTh[AX];
        uint32_t* rthS = (uint32_t*)(sm + OFF_RTH);
        for (int idx = t; idx < 3132; idx += 1024) rthS[idx] = rthG[idx];
        for (int idx = t; idx < 5632; idx += 1024) rvS[idx] = g_rvP[AX][idx];
        if (AX == 1) {
            const float4* rsrc = (const float4*)(g_p + (size_t)n*IMGSZ + s*44);
            float4* rd = (float4*)resS;
            for (int idx = t; idx < 2816; idx += 1024) {
                int ch = idx / 11, q = idx - ch*11;
                rd[idx] = rsrc[ch*484 + q];
            }
        }
    }
    __syncthreads();

    // sim: thread handles (i,j) for a group PAIR (rel rows shared across groups)
    for (int e2 = t; e2 < 3872; e2 += 1024) {
        int gp = e2 / 1936;            // 0 -> groups 0,1 ; 1 -> groups 2,3
        int r = e2 - gp*1936;
        int i = r / 44;
        int j = r - i*44;
        const uint4* rq = (const uint4*)(rTh + (i - j + 43)*72);
        const uint4* rk = (const uint4*)(rTh + (j - i + 43)*72 + 32);
        float2 qk2[2], qr2[2], kr2[2];
        #pragma unroll
        for (int gg = 0; gg < 2; gg++) {
            qk2[gg] = make_float2(0.f, 0.f);
            qr2[gg] = make_float2(0.f, 0.f);
            kr2[gg] = make_float2(0.f, 0.f);
        }
        #pragma unroll
        for (int cc = 0; cc < 4; cc++) {
            uint4 rqu = rq[cc], rku = rk[cc];
            float2 rq0 = h2f(rqu.x), rq1 = h2f(rqu.y), rq2 = h2f(rqu.z), rq3 = h2f(rqu.w);
            float2 rk0 = h2f(rku.x), rk1 = h2f(rku.y), rk2 = h2f(rku.z), rk3 = h2f(rku.w);
            #pragma unroll
            for (int gg = 0; gg < 2; gg++) {
                int g = gp*2 + gg;
                const float4* qp = (const float4*)(qkT + i*260 + g*64) + 2*cc;
                const float4* kp = (const float4*)(qkT + j*260 + g*64 + 32) + 2*cc;
                float4 q4a = qp[0], q4b = qp[1];
                float4 k4a = kp[0], k4b = kp[1];
                fma2(qk2[gg], make_float2(q4a.x,q4a.y), make_float2(k4a.x,k4a.y));
                fma2(qk2[gg], make_float2(q4a.z,q4a.w), make_float2(k4a.z,k4a.w));
                fma2(qk2[gg], make_float2(q4b.x,q4b.y), make_float2(k4b.x,k4b.y));
                fma2(qk2[gg], make_float2(q4b.z,q4b.w), make_float2(k4b.z,k4b.w));
                fma2(qr2[gg], make_float2(q4a.x,q4a.y), rq0);
                fma2(qr2[gg], make_float2(q4a.z,q4a.w), rq1);
                fma2(qr2[gg], make_float2(q4b.x,q4b.y), rq2);
                fma2(qr2[gg], make_float2(q4b.z,q4b.w), rq3);
                fma2(kr2[gg], make_float2(k4a.x,k4a.y), rk0);
                fma2(kr2[gg], make_float2(k4a.z,k4a.w), rk1);
                fma2(kr2[gg], make_float2(k4b.x,k4b.y), rk2);
                fma2(kr2[gg], make_float2(k4b.z,k4b.w), rk3);
            }
        }
        #pragma unroll
        for (int gg = 0; gg < 2; gg++) {
            int g = gp*2 + gg;
            float qk = qk2[gg].x + qk2[gg].y;
            float qr = qr2[gg].x + qr2[gg].y;
            float kr = kr2[gg].x + kr2[gg].y;
            simS[g*1936 + r] = g_simA[AX][g]*qk + g_simA[AX][4+g]*qr + g_simA[AX][8+g]*kr + g_simBsum[AX][g];
        }
    }
    __syncthreads();

    // softmax: warp per row
    {
        const int wid = t >> 5, lane = t & 31;
        #pragma unroll
        for (int k = 0; k < 6; k++) {
            int r = wid + 32*k;
            if (r < 176) {
                float* row = simS + (r/44)*1936 + (r - (r/44)*44)*44;
                float v1 = row[lane];
                float v2 = (lane < 12) ? row[lane+32] : -1e30f;
                float m = fmaxf(v1, v2);
                #pragma unroll
                for (int off = 16; off; off >>= 1) m = fmaxf(m, __shfl_xor_sync(0xffffffffu, m, off));
                float e1 = __expf(v1 - m);
                float e2 = (lane < 12) ? __expf(v2 - m) : 0.f;
                float su = e1 + e2;
                #pragma unroll
                for (int off = 16; off; off >>= 1) su += __shfl_xor_sync(0xffffffffu, su, off);
                float inv = 1.f / su;
                row[lane] = e1 * inv;
                if (lane < 12) row[lane+32] = e2 * inv;
            }
        }
    }
    __syncthreads();

    // output
    {
        const int ch = t & 255, qtr = t >> 8;
        const int g = ch >> 6, c = ch & 63;
        float2 v2[22];
        const float4* vp = (const float4*)(vS + ch*44);
        #pragma unroll
        for (int q = 0; q < 11; q++) {
            float4 v4 = vp[q];
            v2[2*q]   = make_float2(v4.x, v4.y);
            v2[2*q+1] = make_float2(v4.z, v4.w);
        }
        const float aSV  = g_outA_sv[AX][ch];
        const float aSVE = g_outA_sve[AX][ch];
        const float bO   = g_outB[AX][ch];
        #pragma unroll 1
        for (int ii = 0; ii < 11; ii++) {
            int i = qtr*11 + ii;
            const float2* sr2 = (const float2*)(simS + g*1936 + i*44);
            int b0 = 43 - i;
            const uint32_t* wrow = rvS + (b0 & 1)*2816 + (b0 >> 1)*64 + c;
            float2 sv2 = make_float2(0.f, 0.f), sve2 = make_float2(0.f, 0.f);
            #pragma unroll
            for (int p = 0; p < 22; p++) {
                float2 s2 = sr2[p];
                fma2(sv2, s2, v2[p]);
                fma2(sve2, s2, h2f(wrow[p*64]));
            }
            float val = fmaf(aSV, sv2.x + sv2.y, fmaf(aSVE, sve2.x + sve2.y, bO));
            if (AX == 0) {
                qkT[ch*44 + i] = val;
            } else {
                qkT[i*256 + ch] = val + resS[ch*44 + i];
            }
        }
    }
    __syncthreads();
    if (AX == 0) {
        float* out = g_t1;
        const float4* st4 = (const float4*)qkT;
        for (int idx = t; idx < 2816; idx += 1024) {
            int ch = idx / 11, q = idx - ch*11;
            *(float4*)(out + ((size_t)(n*256 + ch))*1936 + s*44 + q*4) = st4[idx];
        }
    } else {
        const size_t rowbase = ((size_t)MARGIN_LO + (size_t)n*PPX + (size_t)(s+1)*48 + 1)*256;
        for (int idx = t; idx < 11264; idx += 1024) {
            int i = idx >> 8, ch = idx & 255;
            float val = qkT[i*256 + ch];
            __nv_bfloat16 hi = __float2bfloat16(val);
            size_t a = rowbase + (size_t)i*256 + ch;
            g_xh[a] = hi;
            g_xl[a] = __float2bfloat16(val - __bfloat162float(hi));
        }
    }
}

// ---------------- tensor-core conv3x3 v2: full 256-co tile, 512 threads ----------------
#define C2STAGE 29184
#define C2_AL   6144
#define C2_BH   12288
#define C2_BHL  8448        // bytes per B hi/lo block (16 rows x 528)
#define CONV_SMEM (3*C2STAGE + 1024)

__global__ void __launch_bounds__(512,1) conv_mma_kernel(const float* __restrict__ conv_b,
                                                         float* __restrict__ out)
{
    extern __shared__ char smc[];
    const uint32_t sbase = smem_to_u32(smc);
    const int t = threadIdx.x;
    const int wid = t >> 5, lane = t & 31;
    const int bb = blockIdx.x;
    const int n = bb / 18;
    const int widx = bb - n*18;
    const int pxw = widx * 128;
    const int wm = wid & 1, wn = wid >> 1;     // 2 x 8 warp grid

    float* biasS = (float*)(smc + 3*C2STAGE);
    if (t < 256) biasS[t] = conv_b[t];

    const long long arow0 = (long long)MARGIN_LO + (long long)n*PPX + pxw;

    auto load_chunk = [&](int kc, int stage) {
        const int tap = kc >> 4, sub = kc & 15;
        const int offr = (tap/3 - 1)*48 + (tap%3 - 1);
        const long long abase = arow0 + offr;
        const uint32_t sA = sbase + stage*C2STAGE;
        const uint32_t sB = sA + C2_BH;
        #pragma unroll
        for (int i = 0; i < 3; i++) {
            int o = t + 512*i;
            if (o < 512) {
                int hl   = o & 1;
                int half = (o >> 1) & 1;
                int row  = o >> 2;
                const __nv_bfloat16* g = (hl ? g_xl : g_xh) + ((size_t)(abase + row))*256 + sub*16 + half*8;
                cp16(sA + hl*C2_AL + row*48 + half*16, g);
            } else {
                int o2 = o - 512;                 // 0..1023
                int hl = o2 & 1;
                int rest = o2 >> 1;               // 0..511
                int krow = rest >> 5, unit = rest & 31;
                const __nv_bfloat16* g = (hl ? g_wl : g_wh)
                    + ((size_t)(tap*256 + sub*16 + krow))*256 + unit*8;
                cp16(sB + hl*C2_BHL + krow*528 + unit*16, g);
            }
        }
    };

    float acc[4][4][4];
    #pragma unroll
    for (int mf = 0; mf < 4; mf++)
        #pragma unroll
        for (int nf = 0; nf < 4; nf++)
            #pragma unroll
            for (int k = 0; k < 4; k++) acc[mf][nf][k] = 0.f;

    load_chunk(0, 0); CP_COMMIT();
    load_chunk(1, 1); CP_COMMIT();

    for (int kc = 0; kc < 144; kc++) {
        const int stage = kc % 3;
        if (kc + 2 < 144) { load_chunk(kc+2, (kc+2)%3); CP_COMMIT(); CP_WAIT(2); }
        else if (kc + 1 < 144) { CP_WAIT(1); }
        else { CP_WAIT(0); }
        __syncthreads();

        const uint32_t sA = sbase + stage*C2STAGE;
        const uint32_t sB = sA + C2_BH;

        uint32_t Ah[4][4], Al[4][4], Bh[4][2], Bl[4][2];
        #pragma unroll
        for (int mf = 0; mf < 4; mf++) {
            uint32_t a_off = (wm*64 + mf*16 + (lane & 15))*48 + (lane >> 4)*16;
            ldsm_x4(Ah[mf], sA + a_off);
            ldsm_x4(Al[mf], sA + C2_AL + a_off);
        }
        #pragma unroll
        for (int nf = 0; nf < 4; nf++) {
            uint32_t b_off = (lane & 15)*528 + (wn*32 + nf*8)*2;
            ldsm_x2_t(Bh[nf], sB + b_off);
            ldsm_x2_t(Bl[nf], sB + C2_BHL + b_off);
        }
        #pragma unroll
        for (int mf = 0; mf < 4; mf++)
            #pragma unroll
            for (int nf = 0; nf < 4; nf++) {
                mma_bf16(acc[mf][nf], Ah[mf], Bh[nf]);
                mma_bf16(acc[mf][nf], Ah[mf], Bl[nf]);
                mma_bf16(acc[mf][nf], Al[mf], Bh[nf]);
            }
        __syncthreads();
    }

    const int b_ = n >> 2, i2 = (n >> 1) & 1, j2 = n & 1;
    #pragma unroll
    for (int mf = 0; mf < 4; mf++) {
        #pragma unroll
        for (int half = 0; half < 2; half++) {
            int px = pxw + wm*64 + mf*16 + (lane >> 2) + half*8;
            int py = px / 48, pxx = px - py*48;
            bool valid = (py >= 1 && py <= 44) && (pxx >= 1 && pxx <= 44);
            if (!valid) continue;
            size_t ob = ((size_t)(b_*256))*7744 + (size_t)(i2*44 + (py-1))*88 + j2*44 + (pxx-1);
            #pragma unroll
            for (int nf = 0; nf < 4; nf++) {
                int co = wn*32 + nf*8 + (lane & 3)*2;
                out[ob + (size_t)co*7744]     = acc[mf][nf][half*2+0] + biasS[co];
                out[ob + (size_t)(co+1)*7744] = acc[mf][nf][half*2+1] + biasS[co+1];
            }
        }
    }
}

// ---------------- launch ----------------
extern "C" void kernel_launch(void* const* d_in, const int* in_sizes, int n_in,
                              void* d_out, int out_size)
{
    const float* x        = (const float*)d_in[0];
    const float* h_qkv_w  = (const float*)d_in[1];
    const float* h_bn_qkv = (const float*)d_in[2];
    const float* h_bn_sim = (const float*)d_in[3];
    const float* h_bn_out = (const float*)d_in[4];
    const float* h_rel    = (const float*)d_in[5];
    const float* w_qkv_w  = (const float*)d_in[6];
    const float* w_bn_qkv = (const float*)d_in[7];
    const float* w_bn_sim = (const float*)d_in[8];
    const float* w_bn_out = (const float*)d_in[9];
    const float* w_rel    = (const float*)d_in[10];
    const float* conv_w   = (const float*)d_in[11];
    const float* conv_b   = (const float*)d_in[12];
    float* out = (float*)d_out;

    cudaFuncSetAttribute(axial_kernel<0>,  cudaFuncAttributeMaxDynamicSharedMemorySize, AX_SMEM);
    cudaFuncSetAttribute(axial_kernel<1>,  cudaFuncAttributeMaxDynamicSharedMemorySize, AX_SMEM);
    cudaFuncSetAttribute(qkv_gemm_kernel,  cudaFuncAttributeMaxDynamicSharedMemorySize, GEMM_SMEM);
    cudaFuncSetAttribute(conv_mma_kernel,  cudaFuncAttributeMaxDynamicSharedMemorySize, CONV_SMEM);

    prep_kernel<<<(256*256*9 + 255)/256, 256>>>(h_qkv_w, h_bn_qkv, h_bn_sim, h_bn_out,
                                                w_qkv_w, w_bn_qkv, w_bn_sim, w_bn_out,
                                                conv_w, h_rel, w_rel);
    patchify_kernel<<<NPATCH*256, 256>>>(x);
    qkv_gemm_kernel<<<dim3(16,NPATCH), 256, GEMM_SMEM>>>(0);
    axial_kernel<0><<<NB, 1024, AX_SMEM>>>();
    transpose_kernel<<<NPATCH*256, 256>>>();
    qkv_gemm_kernel<<<dim3(16,NPATCH), 256, GEMM_SMEM>>>(1);
    axial_kernel<1><<<NB, 1024, AX_SMEM>>>();
    conv_mma_kernel<<<NPATCH*18, 512, CONV_SMEM>>>(conv_b, out);
}

// round 12
// speedup vs baseline: 2.2434x; 1.0076x over previous
#include <cuda_runtime.h>
#include <cuda_bf16.h>
#include <cuda_fp16.h>
#include <math.h>
#include <cstdint>

#define EPS 1e-5f
#define NPATCH 64
#define HS 44
#define NB (NPATCH*HS)          // 2816
#define PLANE 1936
#define IMGSZ (256*1936)

// padded conv geometry
#define PPX 2208
#define MARGIN_LO 128
#define XROWS (MARGIN_LO + NPATCH*PPX + 256)

typedef unsigned long long ull;
__device__ __forceinline__ void fma2(float2 &d, float2 a, float2 b) {
    asm("fma.rn.f32x2 %0, %1, %2, %0;"
        : "+l"(reinterpret_cast<ull&>(d))
        : "l"(reinterpret_cast<ull&>(a)), "l"(reinterpret_cast<ull&>(b)));
}
__device__ __forceinline__ float2 h2f(uint32_t u) {
    __half2 h = *reinterpret_cast<__half2*>(&u);
    return __half22float2(h);
}

// ---------------- mma / ldmatrix / cp.async helpers ----------------
__device__ __forceinline__ uint32_t smem_to_u32(const void* p) {
    uint32_t a;
    asm("{ .reg .u64 t; cvta.to.shared.u64 t, %1; cvt.u32.u64 %0, t; }" : "=r"(a) : "l"(p));
    return a;
}
__device__ __forceinline__ void ldsm_x4(uint32_t a[4], uint32_t addr) {
    asm volatile("ldmatrix.sync.aligned.m8n8.x4.shared.b16 {%0,%1,%2,%3}, [%4];"
        : "=r"(a[0]),"=r"(a[1]),"=r"(a[2]),"=r"(a[3]) : "r"(addr));
}
__device__ __forceinline__ void ldsm_x2_t(uint32_t b[2], uint32_t addr) {
    asm volatile("ldmatrix.sync.aligned.m8n8.x2.trans.shared.b16 {%0,%1}, [%2];"
        : "=r"(b[0]),"=r"(b[1]) : "r"(addr));
}
__device__ __forceinline__ void mma_bf16(float c[4], const uint32_t a[4], const uint32_t b[2]) {
    asm volatile("mma.sync.aligned.m16n8k16.row.col.f32.bf16.bf16.f32 "
        "{%0,%1,%2,%3}, {%4,%5,%6,%7}, {%8,%9}, {%0,%1,%2,%3};"
        : "+f"(c[0]),"+f"(c[1]),"+f"(c[2]),"+f"(c[3])
        : "r"(a[0]),"r"(a[1]),"r"(a[2]),"r"(a[3]), "r"(b[0]),"r"(b[1]));
}
__device__ __forceinline__ void cp16(uint32_t saddr, const void* g) {
    asm volatile("cp.async.cg.shared.global [%0], [%1], 16;" :: "r"(saddr), "l"(g));
}
#define CP_COMMIT() asm volatile("cp.async.commit_group;" ::: "memory")
#define CP_WAIT(n)  asm volatile("cp.async.wait_group %0;" :: "n"(n) : "memory")

// ---------------- static device scratch ----------------
__device__ float g_p [NPATCH*IMGSZ];
__device__ float g_t1[NPATCH*IMGSZ];
__device__ float g_qkv[(size_t)NPATCH*512*PLANE];
__device__ float g_qkvb[2][512];
__device__ float g_simA[2][12];
__device__ float g_simBsum[2][4];
__device__ float g_outA_sv[2][256];
__device__ float g_outA_sve[2][256];
__device__ float g_outB[2][256];
__device__ __half g_relTh[2][87*72];
__device__ uint32_t g_rvP[2][5632];
// tensor-core operand buffers
__device__ __align__(1024) __nv_bfloat16 g_xbh[(size_t)NPATCH*256*PLANE + 256];
__device__ __align__(1024) __nv_bfloat16 g_xbl[(size_t)NPATCH*256*PLANE + 256];
__device__ __align__(1024) __nv_bfloat16 g_qwh[2][512*256];
__device__ __align__(1024) __nv_bfloat16 g_qwl[2][512*256];
__device__ __align__(1024) __nv_bfloat16 g_xh[(size_t)XROWS*256];
__device__ __align__(1024) __nv_bfloat16 g_xl[(size_t)XROWS*256];
__device__ __align__(1024) __nv_bfloat16 g_wh[9*256*256];
__device__ __align__(1024) __nv_bfloat16 g_wl[9*256*256];

// ---------------- prep ----------------
__global__ void prep_kernel(const float* __restrict__ h_qkv_w, const float* __restrict__ h_bn_qkv,
                            const float* __restrict__ h_bn_sim, const float* __restrict__ h_bn_out,
                            const float* __restrict__ w_qkv_w, const float* __restrict__ w_bn_qkv,
                            const float* __restrict__ w_bn_sim, const float* __restrict__ w_bn_out,
                            const float* __restrict__ conv_w,
                            const float* __restrict__ h_rel, const float* __restrict__ w_rel)
{
    int idx = blockIdx.x * blockDim.x + threadIdx.x;
    const __nv_bfloat16 zero = __float2bfloat16(0.f);

    if (idx < 256*256*9) {
        int co  = idx / 2304;
        int rem = idx - co*2304;
        int ci  = rem / 9;
        int tap = rem - ci*9;
        float w = conv_w[idx];
        __nv_bfloat16 hi = __float2bfloat16(w);
        float lo = w - __bfloat162float(hi);
        g_wh[(tap*256 + ci)*256 + co] = hi;
        g_wl[(tap*256 + ci)*256 + co] = __float2bfloat16(lo);
    }
    if (idx < MARGIN_LO*256) {
        g_xh[idx] = zero;
        g_xl[idx] = zero;
    }
    if (idx < 256*256) {
        size_t off = (size_t)(MARGIN_LO + NPATCH*PPX)*256 + idx;
        g_xh[off] = zero;
        g_xl[off] = zero;
    }
    // NHWC patch-border zeroing
    for (int z = idx; z < NPATCH*69632; z += 2304*256) {
        int n = z / 69632, e = z - n*69632;
        int py, x, ch;
        if (e < 12288)      { py = 0;  x = e >> 8;              ch = e & 255; }
        else if (e < 24576) { int e2 = e - 12288; py = 45; x = e2 >> 8; ch = e2 & 255; }
        else {
            int e2 = e - 24576;
            py = 1 + (e2 >> 10);
            int r2 = e2 & 1023;
            int xi = r2 >> 8;
            x = (xi == 0) ? 0 : (44 + xi);
            ch = r2 & 255;
        }
        size_t a = ((size_t)MARGIN_LO + (size_t)n*PPX + py*48 + x)*256 + ch;
        g_xh[a] = zero;
        g_xl[a] = zero;
    }
    if (idx < 2*131072) {
        int ax = idx >> 17;
        int r  = idx & 131071;
        int o  = r & 511;
        int c  = r >> 9;
        const float* bn = ax ? w_bn_qkv : h_bn_qkv;
        const float* W  = ax ? w_qkv_w : h_qkv_w;
        float s = bn[o] * rsqrtf(bn[1536+o] + EPS);
        float wv = W[o*256 + c] * s;
        __nv_bfloat16 hi = __float2bfloat16(wv);
        float lo = wv - __bfloat162float(hi);
        g_qwh[ax][o*256 + c] = hi;
        g_qwl[ax][o*256 + c] = __float2bfloat16(lo);
        if (c == 0) g_qkvb[ax][o] = bn[512+o] - bn[1024+o]*s;
    }
    if (idx < 8) {
        int ax = idx >> 2, g = idx & 3;
        const float* bs = ax ? w_bn_sim : h_bn_sim;
        float shsum = 0.f;
        #pragma unroll
        for (int p = 0; p < 3; p++) {
            int ch = p*4 + g;
            float s = bs[ch] * rsqrtf(bs[36+ch] + EPS);
            g_simA[ax][p*4+g] = (p == 0 ? 1.f : 0.1f) * s;
            shsum += bs[12+ch] - bs[24+ch]*s;
        }
        g_simBsum[ax][g] = shsum;
    }
    if (idx < 512) {
        int ax = idx >> 8, cc = idx & 255;
        const float* bo = ax ? w_bn_out : h_bn_out;
        int o1 = 2*cc, o2 = 2*cc + 1;
        float s1 = bo[o1] * rsqrtf(bo[1536+o1] + EPS);
        float s2 = bo[o2] * rsqrtf(bo[1536+o2] + EPS);
        g_outA_sv[ax][cc]  = s1;
        g_outA_sve[ax][cc] = 0.1f * s2;
        g_outB[ax][cc] = (bo[512+o1] - bo[1024+o1]*s1) + (bo[512+o2] - bo[1024+o2]*s2);
    }
    if (idx < 2*87*72) {
        int ax = idx / 6264, r = idx - ax*6264;
        int d = r / 72, c = r - d*72;
        const float* rl = ax ? w_rel : h_rel;
        g_relTh[ax][r] = __float2half(c < 64 ? rl[c*87 + d] : 0.f);
    }
    if (idx < 2*5632) {
        int ax = idx / 5632, r = idx - ax*5632;
        int par = r / 2816, r2 = r - par*2816;
        int dhalf = r2 >> 6, c = r2 & 63;
        const float* rl = ax ? w_rel : h_rel;
        int d0 = 2*dhalf + par;
        float lo = (d0     <= 86) ? rl[(64+c)*87 + 86 - d0]     : 0.f;
        float hi = (d0 + 1 <= 86) ? rl[(64+c)*87 + 86 - d0 - 1] : 0.f;
        __half2 h2v = __halves2half2(__float2half(lo), __float2half(hi));
        g_rvP[ax][par*2816 + dhalf*64 + c] = *reinterpret_cast<uint32_t*>(&h2v);
    }
}

// ---------------- patchify ----------------
__global__ void __launch_bounds__(256,1) patchify_kernel(const float* __restrict__ x)
{
    __shared__ float tile[44*45];
    const int b = blockIdx.x;
    const int np = b >> 8, c = b & 255;
    const int bb_ = np >> 2, i2 = (np >> 1) & 1, j2 = np & 1;
    const float* src = x + ((size_t)(bb_*256 + c)*88 + i2*44)*88 + j2*44;
    float* dp = g_p + (size_t)b*1936;
    const int t = threadIdx.x;
    for (int idx = t; idx < 1936; idx += 256) {
        int y = idx / 44, xq = idx - y*44;
        float v = src[y*88 + xq];
        dp[idx] = v;
        tile[xq*45 + y] = v;
    }
    __syncthreads();
    const size_t base = (size_t)b*1936;
    for (int idx = t; idx < 1936; idx += 256) {
        int r = idx / 44, col = idx - r*44;
        float val = tile[r*45 + col];
        __nv_bfloat16 hi = __float2bfloat16(val);
        g_xbh[base + idx] = hi;
        g_xbl[base + idx] = __float2bfloat16(val - __bfloat162float(hi));
    }
}

// ---------------- transpose g_t1 [c][x][y] -> bf16 hi/lo [c][y][x] ----------------
__global__ void __launch_bounds__(256,1) transpose_kernel()
{
    __shared__ float tile[44*45];
    const int b = blockIdx.x;
    const float* src = g_t1 + (size_t)b*1936;
    const int t = threadIdx.x;
    for (int idx = t; idx < 1936; idx += 256) {
        int r = idx / 44, col = idx - r*44;
        tile[col*45 + r] = src[idx];
    }
    __syncthreads();
    const size_t base = (size_t)b*1936;
    for (int idx = t; idx < 1936; idx += 256) {
        int r = idx / 44, col = idx - r*44;
        float val = tile[r*45 + col];
        __nv_bfloat16 hi = __float2bfloat16(val);
        g_xbh[base + idx] = hi;
        g_xbl[base + idx] = __float2bfloat16(val - __bfloat162float(hi));
    }
}

// ---------------- qkv GEMM v3: B-panel resident, 512 threads ----------------
#define QB_BL   69632
#define QB_A    139264
#define QB_AST  12288
#define QB_ALO  6144
#define GEMM_SMEM 163840

__global__ void __launch_bounds__(512,1) qkv_gemm_kernel(int ax)
{
    extern __shared__ char smc[];
    const uint32_t sbase = smem_to_u32(smc);
    const int t = threadIdx.x;
    const int wid = t >> 5, lane = t & 31;
    const int ntile = blockIdx.x;
    const int n     = blockIdx.y;
    const int pxw = ntile * 128;
    const int wm = wid & 1, wn = wid >> 1;    // 2 x 8 warp grid
    const __nv_bfloat16* qwh = g_qwh[ax];
    const __nv_bfloat16* qwl = g_qwl[ax];

    for (int j = t; j < 8192; j += 512) {
        int hl = j >> 12;
        int idx2 = j & 4095;
        int row = idx2 >> 4, unit = idx2 & 15;
        const __nv_bfloat16* g = (hl ? g_xbl : g_xbh)
            + ((size_t)(n*256 + row))*1936 + pxw + unit*8;
        cp16(sbase + hl*QB_BL + row*272 + unit*16, g);
    }
    CP_COMMIT();
    CP_WAIT(0);
    __syncthreads();

    auto load_A = [&](int mtile, int kc, int stage) {
        const int mrow0 = mtile*128;
        const uint32_t sA = sbase + QB_A + stage*QB_AST;
        int o = t;
        int hl   = o & 1;
        int half = (o >> 1) & 1;
        int row  = o >> 2;
        const __nv_bfloat16* g = (hl ? qwl : qwh) + (size_t)(mrow0 + row)*256 + kc*16 + half*8;
        cp16(sA + hl*QB_ALO + row*48 + half*16, g);
    };

    for (int mtile = 0; mtile < 4; mtile++) {
        float acc[4][2][4];
        #pragma unroll
        for (int mf = 0; mf < 4; mf++)
            #pragma unroll
            for (int nf = 0; nf < 2; nf++)
                #pragma unroll
                for (int k = 0; k < 4; k++) acc[mf][nf][k] = 0.f;

        load_A(mtile, 0, 0); CP_COMMIT();
        load_A(mtile, 1, 1); CP_COMMIT();

        for (int kc = 0; kc < 16; kc++) {
            const int stage = kc & 1;
            if (kc + 1 < 16) { CP_WAIT(1); }
            else             { CP_WAIT(0); }
            __syncthreads();

            const uint32_t sA = sbase + QB_A + stage*QB_AST;
            uint32_t Ah[4][4], Al[4][4], Bh[2][2], Bl[2][2];
            #pragma unroll
            for (int mf = 0; mf < 4; mf++) {
                uint32_t a_off = (wm*64 + mf*16 + (lane & 15))*48 + (lane >> 4)*16;
                ldsm_x4(Ah[mf], sA + a_off);
                ldsm_x4(Al[mf], sA + QB_ALO + a_off);
            }
            #pragma unroll
            for (int nf = 0; nf < 2; nf++) {
                uint32_t b_off = (kc*16 + (lane & 15))*272 + (wn*16 + nf*8)*2;
                ldsm_x2_t(Bh[nf], sbase + b_off);
                ldsm_x2_t(Bl[nf], sbase + QB_BL + b_off);
            }
            __syncthreads();
            if (kc + 2 < 16) { load_A(mtile, kc+2, stage); CP_COMMIT(); }
            #pragma unroll
            for (int mf = 0; mf < 4; mf++)
                #pragma unroll
                for (int nf = 0; nf < 2; nf++) {
                    mma_bf16(acc[mf][nf], Ah[mf], Bh[nf]);
                    mma_bf16(acc[mf][nf], Ah[mf], Bl[nf]);
                    mma_bf16(acc[mf][nf], Al[mf], Bh[nf]);
                }
        }

        const int mrow0 = mtile*128;
        #pragma unroll
        for (int mf = 0; mf < 4; mf++) {
            int row0 = mrow0 + wm*64 + mf*16 + (lane >> 2);
            #pragma unroll
            for (int nf = 0; nf < 2; nf++) {
                int pos = pxw + wn*16 + nf*8 + (lane & 3)*2;
                if (pos < 1936) {
                    float b0 = g_qkvb[ax][row0];
                    float b1 = g_qkvb[ax][row0 + 8];
                    *(float2*)(g_qkv + ((size_t)n*512 + row0)*1936 + pos) =
                        make_float2(acc[mf][nf][0] + b0, acc[mf][nf][1] + b0);
                    *(float2*)(g_qkv + ((size_t)n*512 + row0 + 8)*1936 + pos) =
                        make_float2(acc[mf][nf][2] + b1, acc[mf][nf][3] + b1);
                }
            }
        }
        __syncthreads();
    }
}

// ---------------- fused axial attention v9: group-pair + j-pair sim ----------------
#define OFF_V    11440
#define OFF_SIM  22704
#define OFF_RTH  30448
#define OFF_RVP  33580
#define OFF_RES  39212
#define AX_SMEM  (50476*4)

template<int AX>
__global__ void __launch_bounds__(1024,1) axial_kernel()
{
    extern __shared__ float sm[];
    float* qkT  = sm;
    float* vS   = sm + OFF_V;
    float* simS = sm + OFF_SIM;
    const __half* rTh = (const __half*)(sm + OFF_RTH);
    uint32_t* rvS = (uint32_t*)(sm + OFF_RVP);
    float* resS = sm + OFF_RES;

    const int t  = threadIdx.x;
    const int bb = blockIdx.x;
    const int n  = bb / 44;
    const int s  = bb - n*44;

    // load qkv slice + fp16 rel tables (+ residual for AX=1)
    {
        const float* qsrc = g_qkv + (size_t)n*512*1936 + s*44;
        for (int idx = t; idx < 5632; idx += 1024) {
            int o = idx / 11, q = idx - o*11;
            float4 v4 = *(const float4*)(qsrc + (size_t)o*1936 + q*4);
            int g = o >> 7, wi = o & 127;
            if (wi < 64) {
                int col = g*64 + wi;
                qkT[(q*4+0)*260 + col] = v4.x;
                qkT[(q*4+1)*260 + col] = v4.y;
                qkT[(q*4+2)*260 + col] = v4.z;
                qkT[(q*4+3)*260 + col] = v4.w;
            } else {
                *(float4*)(vS + (g*64 + wi - 64)*44 + q*4) = v4;
            }
        }
        const uint32_t* rthG = (const uint32_t*)g_relTh[AX];
        uint32_t* rthS = (uint32_t*)(sm + OFF_RTH);
        for (int idx = t; idx < 3132; idx += 1024) rthS[idx] = rthG[idx];
        for (int idx = t; idx < 5632; idx += 1024) rvS[idx] = g_rvP[AX][idx];
        if (AX == 1) {
            const float4* rsrc = (const float4*)(g_p + (size_t)n*IMGSZ + s*44);
            float4* rd = (float4*)resS;
            for (int idx = t; idx < 2816; idx += 1024) {
                int ch = idx / 11, q = idx - ch*11;
                rd[idx] = rsrc[ch*484 + q];
            }
        }
    }
    __syncthreads();

    // sim: thread handles (i, {j, j+22}) for a group PAIR -> 4 elements
    for (int e3 = t; e3 < 1936; e3 += 1024) {
        int gp = e3 / 968;
        int r = e3 - gp*968;
        int i = r / 22;
        int jj = r - i*22;
        const int g0 = gp*2, g1 = gp*2 + 1;
        const float4* qg0 = (const float4*)(qkT + i*260 + g0*64);
        const float4* qg1 = qg0 + 16;
        const float4* kg[2][2];
        const uint2* rqp[2];
        const uint2* rkp[2];
        #pragma unroll
        for (int jx = 0; jx < 2; jx++) {
            int j = jj + jx*22;
            kg[jx][0] = (const float4*)(qkT + j*260 + g0*64 + 32);
            kg[jx][1] = (const float4*)(qkT + j*260 + g1*64 + 32);
            rqp[jx] = (const uint2*)(rTh + (i - j + 43)*72);
            rkp[jx] = (const uint2*)(rTh + (j - i + 43)*72 + 32);
        }
        float2 qk2[2][2], qr2[2][2], kr2[2][2];
        #pragma unroll
        for (int jx = 0; jx < 2; jx++)
            #pragma unroll
            for (int gg = 0; gg < 2; gg++) {
                qk2[jx][gg] = make_float2(0.f, 0.f);
                qr2[jx][gg] = make_float2(0.f, 0.f);
                kr2[jx][gg] = make_float2(0.f, 0.f);
            }
        #pragma unroll
        for (int cc = 0; cc < 8; cc++) {
            float4 q0 = qg0[cc], q1 = qg1[cc];
            float2 q0a = make_float2(q0.x, q0.y), q0b = make_float2(q0.z, q0.w);
            float2 q1a = make_float2(q1.x, q1.y), q1b = make_float2(q1.z, q1.w);
            #pragma unroll
            for (int jx = 0; jx < 2; jx++) {
                float4 k0 = kg[jx][0][cc], k1 = kg[jx][1][cc];
                uint2 rqu = rqp[jx][cc], rku = rkp[jx][cc];
                float2 rqa = h2f(rqu.x), rqb = h2f(rqu.y);
                float2 rka = h2f(rku.x), rkb = h2f(rku.y);
                float2 k0a = make_float2(k0.x, k0.y), k0b = make_float2(k0.z, k0.w);
                float2 k1a = make_float2(k1.x, k1.y), k1b = make_float2(k1.z, k1.w);
                fma2(qk2[jx][0], q0a, k0a); fma2(qk2[jx][0], q0b, k0b);
                fma2(qk2[jx][1], q1a, k1a); fma2(qk2[jx][1], q1b, k1b);
                fma2(qr2[jx][0], q0a, rqa); fma2(qr2[jx][0], q0b, rqb);
                fma2(qr2[jx][1], q1a, rqa); fma2(qr2[jx][1], q1b, rqb);
                fma2(kr2[jx][0], k0a, rka); fma2(kr2[jx][0], k0b, rkb);
                fma2(kr2[jx][1], k1a, rka); fma2(kr2[jx][1], k1b, rkb);
            }
        }
        #pragma unroll
        for (int jx = 0; jx < 2; jx++)
            #pragma unroll
            for (int gg = 0; gg < 2; gg++) {
                int g = gp*2 + gg;
                int j = jj + jx*22;
                float qk = qk2[jx][gg].x + qk2[jx][gg].y;
                float qr = qr2[jx][gg].x + qr2[jx][gg].y;
                float kr = kr2[jx][gg].x + kr2[jx][gg].y;
                simS[g*1936 + i*44 + j] =
                    g_simA[AX][g]*qk + g_simA[AX][4+g]*qr + g_simA[AX][8+g]*kr + g_simBsum[AX][g];
            }
    }
    __syncthreads();

    // softmax: warp per row
    {
        const int wid = t >> 5, lane = t & 31;
        #pragma unroll
        for (int k = 0; k < 6; k++) {
            int r = wid + 32*k;
            if (r < 176) {
                float* row = simS + (r/44)*1936 + (r - (r/44)*44)*44;
                float v1 = row[lane];
                float v2 = (lane < 12) ? row[lane+32] : -1e30f;
                float m = fmaxf(v1, v2);
                #pragma unroll
                for (int off = 16; off; off >>= 1) m = fmaxf(m, __shfl_xor_sync(0xffffffffu, m, off));
                float e1 = __expf(v1 - m);
                float e2 = (lane < 12) ? __expf(v2 - m) : 0.f;
                float su = e1 + e2;
                #pragma unroll
                for (int off = 16; off; off >>= 1) su += __shfl_xor_sync(0xffffffffu, su, off);
                float inv = 1.f / su;
                row[lane] = e1 * inv;
                if (lane < 12) row[lane+32] = e2 * inv;
            }
        }
    }
    __syncthreads();

    // output
    {
        const int ch = t & 255, qtr = t >> 8;
        const int g = ch >> 6, c = ch & 63;
        float2 v2[22];
        const float4* vp = (const float4*)(vS + ch*44);
        #pragma unroll
        for (int q = 0; q < 11; q++) {
            float4 v4 = vp[q];
            v2[2*q]   = make_float2(v4.x, v4.y);
            v2[2*q+1] = make_float2(v4.z, v4.w);
        }
        const float aSV  = g_outA_sv[AX][ch];
        const float aSVE = g_outA_sve[AX][ch];
        const float bO   = g_outB[AX][ch];
        #pragma unroll 1
        for (int ii = 0; ii < 11; ii++) {
            int i = qtr*11 + ii;
            const float2* sr2 = (const float2*)(simS + g*1936 + i*44);
            int b0 = 43 - i;
            const uint32_t* wrow = rvS + (b0 & 1)*2816 + (b0 >> 1)*64 + c;
            float2 sv2 = make_float2(0.f, 0.f), sve2 = make_float2(0.f, 0.f);
            #pragma unroll
            for (int p = 0; p < 22; p++) {
                float2 s2 = sr2[p];
                fma2(sv2, s2, v2[p]);
                fma2(sve2, s2, h2f(wrow[p*64]));
            }
            float val = fmaf(aSV, sv2.x + sv2.y, fmaf(aSVE, sve2.x + sve2.y, bO));
            if (AX == 0) {
                qkT[ch*44 + i] = val;
            } else {
                qkT[i*256 + ch] = val + resS[ch*44 + i];
            }
        }
    }
    __syncthreads();
    if (AX == 0) {
        float* out = g_t1;
        const float4* st4 = (const float4*)qkT;
        for (int idx = t; idx < 2816; idx += 1024) {
            int ch = idx / 11, q = idx - ch*11;
            *(float4*)(out + ((size_t)(n*256 + ch))*1936 + s*44 + q*4) = st4[idx];
        }
    } else {
        const size_t rowbase = ((size_t)MARGIN_LO + (size_t)n*PPX + (size_t)(s+1)*48 + 1)*256;
        for (int idx = t; idx < 11264; idx += 1024) {
            int i = idx >> 8, ch = idx & 255;
            float val = qkT[i*256 + ch];
            __nv_bfloat16 hi = __float2bfloat16(val);
            size_t a = rowbase + (size_t)i*256 + ch;
            g_xh[a] = hi;
            g_xl[a] = __float2bfloat16(val - __bfloat162float(hi));
        }
    }
}

// ---------------- tensor-core conv3x3 v2: full 256-co tile, 512 threads ----------------
#define C2STAGE 29184
#define C2_AL   6144
#define C2_BH   12288
#define C2_BHL  8448
#define CONV_SMEM (3*C2STAGE + 1024)

__global__ void __launch_bounds__(512,1) conv_mma_kernel(const float* __restrict__ conv_b,
                                                         float* __restrict__ out)
{
    extern __shared__ char smc[];
    const uint32_t sbase = smem_to_u32(smc);
    const int t = threadIdx.x;
    const int wid = t >> 5, lane = t & 31;
    const int bb = blockIdx.x;
    const int n = bb / 18;
    const int widx = bb - n*18;
    const int pxw = widx * 128;
    const int wm = wid & 1, wn = wid >> 1;

    float* biasS = (float*)(smc + 3*C2STAGE);
    if (t < 256) biasS[t] = conv_b[t];

    const long long arow0 = (long long)MARGIN_LO + (long long)n*PPX + pxw;

    auto load_chunk = [&](int kc, int stage) {
        const int tap = kc >> 4, sub = kc & 15;
        const int offr = (tap/3 - 1)*48 + (tap%3 - 1);
        const long long abase = arow0 + offr;
        const uint32_t sA = sbase + stage*C2STAGE;
        const uint32_t sB = sA + C2_BH;
        #pragma unroll
        for (int i = 0; i < 3; i++) {
            int o = t + 512*i;
            if (o < 512) {
                int hl   = o & 1;
                int half = (o >> 1) & 1;
                int row  = o >> 2;
                const __nv_bfloat16* g = (hl ? g_xl : g_xh) + ((size_t)(abase + row))*256 + sub*16 + half*8;
                cp16(sA + hl*C2_AL + row*48 + half*16, g);
            } else {
                int o2 = o - 512;
                int hl = o2 & 1;
                int rest = o2 >> 1;
                int krow = rest >> 5, unit = rest & 31;
                const __nv_bfloat16* g = (hl ? g_wl : g_wh)
                    + ((size_t)(tap*256 + sub*16 + krow))*256 + unit*8;
                cp16(sB + hl*C2_BHL + krow*528 + unit*16, g);
            }
        }
    };

    float acc[4][4][4];
    #pragma unroll
    for (int mf = 0; mf < 4; mf++)
        #pragma unroll
        for (int nf = 0; nf < 4; nf++)
            #pragma unroll
            for (int k = 0; k < 4; k++) acc[mf][nf][k] = 0.f;

    load_chunk(0, 0); CP_COMMIT();
    load_chunk(1, 1); CP_COMMIT();

    for (int kc = 0; kc < 144; kc++) {
        const int stage = kc % 3;
        if (kc + 2 < 144) { load_chunk(kc+2, (kc+2)%3); CP_COMMIT(); CP_WAIT(2); }
        else if (kc + 1 < 144) { CP_WAIT(1); }
        else { CP_WAIT(0); }
        __syncthreads();

        const uint32_t sA = sbase + stage*C2STAGE;
        const uint32_t sB = sA + C2_BH;

        uint32_t Ah[4][4], Al[4][4], Bh[4][2], Bl[4][2];
        #pragma unroll
        for (int mf = 0; mf < 4; mf++) {
            uint32_t a_off = (wm*64 + mf*16 + (lane & 15))*48 + (lane >> 4)*16;
            ldsm_x4(Ah[mf], sA + a_off);
            ldsm_x4(Al[mf], sA + C2_AL + a_off);
        }
        #pragma unroll
        for (int nf = 0; nf < 4; nf++) {
            uint32_t b_off = (lane & 15)*528 + (wn*32 + nf*8)*2;
            ldsm_x2_t(Bh[nf], sB + b_off);
            ldsm_x2_t(Bl[nf], sB + C2_BHL + b_off);
        }
        #pragma unroll
        for (int mf = 0; mf < 4; mf++)
            #pragma unroll
            for (int nf = 0; nf < 4; nf++) {
                mma_bf16(acc[mf][nf], Ah[mf], Bh[nf]);
                mma_bf16(acc[mf][nf], Ah[mf], Bl[nf]);
                mma_bf16(acc[mf][nf], Al[mf], Bh[nf]);
            }
        __syncthreads();
    }

    const int b_ = n >> 2, i2 = (n >> 1) & 1, j2 = n & 1;
    #pragma unroll
    for (int mf = 0; mf < 4; mf++) {
        #pragma unroll
        for (int half = 0; half < 2; half++) {
            int px = pxw + wm*64 + mf*16 + (lane >> 2) + half*8;
            int py = px / 48, pxx = px - py*48;
            bool valid = (py >= 1 && py <= 44) && (pxx >= 1 && pxx <= 44);
            if (!valid) continue;
            size_t ob = ((size_t)(b_*256))*7744 + (size_t)(i2*44 + (py-1))*88 + j2*44 + (pxx-1);
            #pragma unroll
            for (int nf = 0; nf < 4; nf++) {
                int co = wn*32 + nf*8 + (lane & 3)*2;
                out[ob + (size_t)co*7744]     = acc[mf][nf][half*2+0] + biasS[co];
                out[ob + (size_t)(co+1)*7744] = acc[mf][nf][half*2+1] + biasS[co+1];
            }
        }
    }
}

// ---------------- launch ----------------
extern "C" void kernel_launch(void* const* d_in, const int* in_sizes, int n_in,
                              void* d_out, int out_size)
{
    const float* x        = (const float*)d_in[0];
    const float* h_qkv_w  = (const float*)d_in[1];
    const float* h_bn_qkv = (const float*)d_in[2];
    const float* h_bn_sim = (const float*)d_in[3];
    const float* h_bn_out = (const float*)d_in[4];
    const float* h_rel    = (const float*)d_in[5];
    const float* w_qkv_w  = (const float*)d_in[6];
    const float* w_bn_qkv = (const float*)d_in[7];
    const float* w_bn_sim = (const float*)d_in[8];
    const float* w_bn_out = (const float*)d_in[9];
    const float* w_rel    = (const float*)d_in[10];
    const float* conv_w   = (const float*)d_in[11];
    const float* conv_b   = (const float*)d_in[12];
    float* out = (float*)d_out;

    cudaFuncSetAttribute(axial_kernel<0>,  cudaFuncAttributeMaxDynamicSharedMemorySize, AX_SMEM);
    cudaFuncSetAttribute(axial_kernel<1>,  cudaFuncAttributeMaxDynamicSharedMemorySize, AX_SMEM);
    cudaFuncSetAttribute(qkv_gemm_kernel,  cudaFuncAttributeMaxDynamicSharedMemorySize, GEMM_SMEM);
    cudaFuncSetAttribute(conv_mma_kernel,  cudaFuncAttributeMaxDynamicSharedMemorySize, CONV_SMEM);

    prep_kernel<<<(256*256*9 + 255)/256, 256>>>(h_qkv_w, h_bn_qkv, h_bn_sim, h_bn_out,
                                                w_qkv_w, w_bn_qkv, w_bn_sim, w_bn_out,
                                                conv_w, h_rel, w_rel);
    patchify_kernel<<<NPATCH*256, 256>>>(x);
    qkv_gemm_kernel<<<dim3(16,NPATCH), 512, GEMM_SMEM>>>(0);
    axial_kernel<0><<<NB, 1024, AX_SMEM>>>();
    transpose_kernel<<<NPATCH*256, 256>>>();
    qkv_gemm_kernel<<<dim3(16,NPATCH), 512, GEMM_SMEM>>>(1);
    axial_kernel<1><<<NB, 1024, AX_SMEM>>>();
    conv_mma_kernel<<<NPATCH*18, 512, CONV_SMEM>>>(conv_b, out);
}

// round 13
// speedup vs baseline: 2.9989x; 1.3368x over previous
#include <cuda_runtime.h>
#include <cuda_bf16.h>
#include <cuda_fp16.h>
#include <math.h>
#include <cstdint>

#define EPS 1e-5f
#define NPATCH 64
#define HS 44
#define NB (NPATCH*HS)          // 2816
#define PLANE 1936
#define IMGSZ (256*1936)

// padded conv geometry
#define PPX 2208
#define MARGIN_LO 128
#define XROWS (MARGIN_LO + NPATCH*PPX + 256)

typedef unsigned long long ull;
__device__ __forceinline__ void fma2(float2 &d, float2 a, float2 b) {
    asm("fma.rn.f32x2 %0, %1, %2, %0;"
        : "+l"(reinterpret_cast<ull&>(d))
        : "l"(reinterpret_cast<ull&>(a)), "l"(reinterpret_cast<ull&>(b)));
}
__device__ __forceinline__ float2 h2f(uint32_t u) {
    __half2 h = *reinterpret_cast<__half2*>(&u);
    return __half22float2(h);
}

// ---------------- mma / ldmatrix / cp.async helpers ----------------
__device__ __forceinline__ uint32_t smem_to_u32(const void* p) {
    uint32_t a;
    asm("{ .reg .u64 t; cvta.to.shared.u64 t, %1; cvt.u32.u64 %0, t; }" : "=r"(a) : "l"(p));
    return a;
}
__device__ __forceinline__ void ldsm_x4(uint32_t a[4], uint32_t addr) {
    asm volatile("ldmatrix.sync.aligned.m8n8.x4.shared.b16 {%0,%1,%2,%3}, [%4];"
        : "=r"(a[0]),"=r"(a[1]),"=r"(a[2]),"=r"(a[3]) : "r"(addr));
}
__device__ __forceinline__ void ldsm_x2_t(uint32_t b[2], uint32_t addr) {
    asm volatile("ldmatrix.sync.aligned.m8n8.x2.trans.shared.b16 {%0,%1}, [%2];"
        : "=r"(b[0]),"=r"(b[1]) : "r"(addr));
}
__device__ __forceinline__ void mma_bf16(float c[4], const uint32_t a[4], const uint32_t b[2]) {
    asm volatile("mma.sync.aligned.m16n8k16.row.col.f32.bf16.bf16.f32 "
        "{%0,%1,%2,%3}, {%4,%5,%6,%7}, {%8,%9}, {%0,%1,%2,%3};"
        : "+f"(c[0]),"+f"(c[1]),"+f"(c[2]),"+f"(c[3])
        : "r"(a[0]),"r"(a[1]),"r"(a[2]),"r"(a[3]), "r"(b[0]),"r"(b[1]));
}
__device__ __forceinline__ void mma_f16(float c[4], const uint32_t a[4], const uint32_t b[2]) {
    asm volatile("mma.sync.aligned.m16n8k16.row.col.f32.f16.f16.f32 "
        "{%0,%1,%2,%3}, {%4,%5,%6,%7}, {%8,%9}, {%0,%1,%2,%3};"
        : "+f"(c[0]),"+f"(c[1]),"+f"(c[2]),"+f"(c[3])
        : "r"(a[0]),"r"(a[1]),"r"(a[2]),"r"(a[3]), "r"(b[0]),"r"(b[1]));
}
__device__ __forceinline__ void cp16(uint32_t saddr, const void* g) {
    asm volatile("cp.async.cg.shared.global [%0], [%1], 16;" :: "r"(saddr), "l"(g));
}
#define CP_COMMIT() asm volatile("cp.async.commit_group;" ::: "memory")
#define CP_WAIT(n)  asm volatile("cp.async.wait_group %0;" :: "n"(n) : "memory")

// ---------------- static device scratch ----------------
__device__ float g_p [NPATCH*IMGSZ];
__device__ float g_t1[NPATCH*IMGSZ];
__device__ float g_qkv[(size_t)NPATCH*512*PLANE];
__device__ float g_qkvb[2][512];
__device__ float g_simA[2][12];
__device__ float g_simBsum[2][4];
__device__ float g_outA_sv[2][256];
__device__ float g_outA_sve[2][256];
__device__ float g_outB[2][256];
__device__ __half g_relTh[2][87*72];
__device__ uint32_t g_rvP[2][5632];
// tensor-core operand buffers
__device__ __align__(1024) __nv_bfloat16 g_xbh[(size_t)NPATCH*256*PLANE + 256];
__device__ __align__(1024) __nv_bfloat16 g_xbl[(size_t)NPATCH*256*PLANE + 256];
__device__ __align__(1024) __nv_bfloat16 g_qwh[2][512*256];
__device__ __align__(1024) __nv_bfloat16 g_qwl[2][512*256];
__device__ __align__(1024) __half g_xc[(size_t)XROWS*256];   // conv activations fp16
__device__ __align__(1024) __half g_wc[9*256*256];           // conv weights fp16 [tap][ci][co]

// ---------------- prep ----------------
__global__ void prep_kernel(const float* __restrict__ h_qkv_w, const float* __restrict__ h_bn_qkv,
                            const float* __restrict__ h_bn_sim, const float* __restrict__ h_bn_out,
                            const float* __restrict__ w_qkv_w, const float* __restrict__ w_bn_qkv,
                            const float* __restrict__ w_bn_sim, const float* __restrict__ w_bn_out,
                            const float* __restrict__ conv_w,
                            const float* __restrict__ h_rel, const float* __restrict__ w_rel)
{
    int idx = blockIdx.x * blockDim.x + threadIdx.x;
    const __half zero = __float2half(0.f);

    if (idx < 256*256*9) {
        int co  = idx / 2304;
        int rem = idx - co*2304;
        int ci  = rem / 9;
        int tap = rem - ci*9;
        g_wc[(tap*256 + ci)*256 + co] = __float2half(conv_w[idx]);
    }
    if (idx < MARGIN_LO*256) g_xc[idx] = zero;
    if (idx < 256*256) g_xc[(size_t)(MARGIN_LO + NPATCH*PPX)*256 + idx] = zero;
    // NHWC patch-border zeroing
    for (int z = idx; z < NPATCH*69632; z += 2304*256) {
        int n = z / 69632, e = z - n*69632;
        int py, x, ch;
        if (e < 12288)      { py = 0;  x = e >> 8;              ch = e & 255; }
        else if (e < 24576) { int e2 = e - 12288; py = 45; x = e2 >> 8; ch = e2 & 255; }
        else {
            int e2 = e - 24576;
            py = 1 + (e2 >> 10);
            int r2 = e2 & 1023;
            int xi = r2 >> 8;
            x = (xi == 0) ? 0 : (44 + xi);
            ch = r2 & 255;
        }
        g_xc[((size_t)MARGIN_LO + (size_t)n*PPX + py*48 + x)*256 + ch] = zero;
    }
    if (idx < 2*131072) {
        int ax = idx >> 17;
        int r  = idx & 131071;
        int o  = r & 511;
        int c  = r >> 9;
        const float* bn = ax ? w_bn_qkv : h_bn_qkv;
        const float* W  = ax ? w_qkv_w : h_qkv_w;
        float s = bn[o] * rsqrtf(bn[1536+o] + EPS);
        float wv = W[o*256 + c] * s;
        __nv_bfloat16 hi = __float2bfloat16(wv);
        float lo = wv - __bfloat162float(hi);
        g_qwh[ax][o*256 + c] = hi;
        g_qwl[ax][o*256 + c] = __float2bfloat16(lo);
        if (c == 0) g_qkvb[ax][o] = bn[512+o] - bn[1024+o]*s;
    }
    if (idx < 8) {
        int ax = idx >> 2, g = idx & 3;
        const float* bs = ax ? w_bn_sim : h_bn_sim;
        float shsum = 0.f;
        #pragma unroll
        for (int p = 0; p < 3; p++) {
            int ch = p*4 + g;
            float s = bs[ch] * rsqrtf(bs[36+ch] + EPS);
            g_simA[ax][p*4+g] = (p == 0 ? 1.f : 0.1f) * s;
            shsum += bs[12+ch] - bs[24+ch]*s;
        }
        g_simBsum[ax][g] = shsum;
    }
    if (idx < 512) {
        int ax = idx >> 8, cc = idx & 255;
        const float* bo = ax ? w_bn_out : h_bn_out;
        int o1 = 2*cc, o2 = 2*cc + 1;
        float s1 = bo[o1] * rsqrtf(bo[1536+o1] + EPS);
        float s2 = bo[o2] * rsqrtf(bo[1536+o2] + EPS);
        g_outA_sv[ax][cc]  = s1;
        g_outA_sve[ax][cc] = 0.1f * s2;
        g_outB[ax][cc] = (bo[512+o1] - bo[1024+o1]*s1) + (bo[512+o2] - bo[1024+o2]*s2);
    }
    if (idx < 2*87*72) {
        int ax = idx / 6264, r = idx - ax*6264;
        int d = r / 72, c = r - d*72;
        const float* rl = ax ? w_rel : h_rel;
        g_relTh[ax][r] = __float2half(c < 64 ? rl[c*87 + d] : 0.f);
    }
    if (idx < 2*5632) {
        int ax = idx / 5632, r = idx - ax*5632;
        int par = r / 2816, r2 = r - par*2816;
        int dhalf = r2 >> 6, c = r2 & 63;
        const float* rl = ax ? w_rel : h_rel;
        int d0 = 2*dhalf + par;
        float lo = (d0     <= 86) ? rl[(64+c)*87 + 86 - d0]     : 0.f;
        float hi = (d0 + 1 <= 86) ? rl[(64+c)*87 + 86 - d0 - 1] : 0.f;
        __half2 h2v = __halves2half2(__float2half(lo), __float2half(hi));
        g_rvP[ax][par*2816 + dhalf*64 + c] = *reinterpret_cast<uint32_t*>(&h2v);
    }
}

// ---------------- patchify ----------------
__global__ void __launch_bounds__(256,1) patchify_kernel(const float* __restrict__ x)
{
    __shared__ float tile[44*45];
    const int b = blockIdx.x;
    const int np = b >> 8, c = b & 255;
    const int bb_ = np >> 2, i2 = (np >> 1) & 1, j2 = np & 1;
    const float* src = x + ((size_t)(bb_*256 + c)*88 + i2*44)*88 + j2*44;
    float* dp = g_p + (size_t)b*1936;
    const int t = threadIdx.x;
    for (int idx = t; idx < 1936; idx += 256) {
        int y = idx / 44, xq = idx - y*44;
        float v = src[y*88 + xq];
        dp[idx] = v;
        tile[xq*45 + y] = v;
    }
    __syncthreads();
    const size_t base = (size_t)b*1936;
    for (int idx = t; idx < 1936; idx += 256) {
        int r = idx / 44, col = idx - r*44;
        float val = tile[r*45 + col];
        __nv_bfloat16 hi = __float2bfloat16(val);
        g_xbh[base + idx] = hi;
        g_xbl[base + idx] = __float2bfloat16(val - __bfloat162float(hi));
    }
}

// ---------------- transpose g_t1 [c][x][y] -> bf16 hi/lo [c][y][x] ----------------
__global__ void __launch_bounds__(256,1) transpose_kernel()
{
    __shared__ float tile[44*45];
    const int b = blockIdx.x;
    const float* src = g_t1 + (size_t)b*1936;
    const int t = threadIdx.x;
    for (int idx = t; idx < 1936; idx += 256) {
        int r = idx / 44, col = idx - r*44;
        tile[col*45 + r] = src[idx];
    }
    __syncthreads();
    const size_t base = (size_t)b*1936;
    for (int idx = t; idx < 1936; idx += 256) {
        int r = idx / 44, col = idx - r*44;
        float val = tile[r*45 + col];
        __nv_bfloat16 hi = __float2bfloat16(val);
        g_xbh[base + idx] = hi;
        g_xbl[base + idx] = __float2bfloat16(val - __bfloat162float(hi));
    }
}

// ---------------- qkv GEMM v3: B-panel resident, 512 threads ----------------
#define QB_BL   69632
#define QB_A    139264
#define QB_AST  12288
#define QB_ALO  6144
#define GEMM_SMEM 163840

__global__ void __launch_bounds__(512,1) qkv_gemm_kernel(int ax)
{
    extern __shared__ char smc[];
    const uint32_t sbase = smem_to_u32(smc);
    const int t = threadIdx.x;
    const int wid = t >> 5, lane = t & 31;
    const int ntile = blockIdx.x;
    const int n     = blockIdx.y;
    const int pxw = ntile * 128;
    const int wm = wid & 1, wn = wid >> 1;
    const __nv_bfloat16* qwh = g_qwh[ax];
    const __nv_bfloat16* qwl = g_qwl[ax];

    for (int j = t; j < 8192; j += 512) {
        int hl = j >> 12;
        int idx2 = j & 4095;
        int row = idx2 >> 4, unit = idx2 & 15;
        const __nv_bfloat16* g = (hl ? g_xbl : g_xbh)
            + ((size_t)(n*256 + row))*1936 + pxw + unit*8;
        cp16(sbase + hl*QB_BL + row*272 + unit*16, g);
    }
    CP_COMMIT();
    CP_WAIT(0);
    __syncthreads();

    auto load_A = [&](int mtile, int kc, int stage) {
        const int mrow0 = mtile*128;
        const uint32_t sA = sbase + QB_A + stage*QB_AST;
        int o = t;
        int hl   = o & 1;
        int half = (o >> 1) & 1;
        int row  = o >> 2;
        const __nv_bfloat16* g = (hl ? qwl : qwh) + (size_t)(mrow0 + row)*256 + kc*16 + half*8;
        cp16(sA + hl*QB_ALO + row*48 + half*16, g);
    };

    for (int mtile = 0; mtile < 4; mtile++) {
        float acc[4][2][4];
        #pragma unroll
        for (int mf = 0; mf < 4; mf++)
            #pragma unroll
            for (int nf = 0; nf < 2; nf++)
                #pragma unroll
                for (int k = 0; k < 4; k++) acc[mf][nf][k] = 0.f;

        load_A(mtile, 0, 0); CP_COMMIT();
        load_A(mtile, 1, 1); CP_COMMIT();

        for (int kc = 0; kc < 16; kc++) {
            const int stage = kc & 1;
            if (kc + 1 < 16) { CP_WAIT(1); }
            else             { CP_WAIT(0); }
            __syncthreads();

            const uint32_t sA = sbase + QB_A + stage*QB_AST;
            uint32_t Ah[4][4], Al[4][4], Bh[2][2], Bl[2][2];
            #pragma unroll
            for (int mf = 0; mf < 4; mf++) {
                uint32_t a_off = (wm*64 + mf*16 + (lane & 15))*48 + (lane >> 4)*16;
                ldsm_x4(Ah[mf], sA + a_off);
                ldsm_x4(Al[mf], sA + QB_ALO + a_off);
            }
            #pragma unroll
            for (int nf = 0; nf < 2; nf++) {
                uint32_t b_off = (kc*16 + (lane & 15))*272 + (wn*16 + nf*8)*2;
                ldsm_x2_t(Bh[nf], sbase + b_off);
                ldsm_x2_t(Bl[nf], sbase + QB_BL + b_off);
            }
            __syncthreads();
            if (kc + 2 < 16) { load_A(mtile, kc+2, stage); CP_COMMIT(); }
            #pragma unroll
            for (int mf = 0; mf < 4; mf++)
                #pragma unroll
                for (int nf = 0; nf < 2; nf++) {
                    mma_bf16(acc[mf][nf], Ah[mf], Bh[nf]);
                    mma_bf16(acc[mf][nf], Ah[mf], Bl[nf]);
                    mma_bf16(acc[mf][nf], Al[mf], Bh[nf]);
                }
        }

        const int mrow0 = mtile*128;
        #pragma unroll
        for (int mf = 0; mf < 4; mf++) {
            int row0 = mrow0 + wm*64 + mf*16 + (lane >> 2);
            #pragma unroll
            for (int nf = 0; nf < 2; nf++) {
                int pos = pxw + wn*16 + nf*8 + (lane & 3)*2;
                if (pos < 1936) {
                    float b0 = g_qkvb[ax][row0];
                    float b1 = g_qkvb[ax][row0 + 8];
                    *(float2*)(g_qkv + ((size_t)n*512 + row0)*1936 + pos) =
                        make_float2(acc[mf][nf][0] + b0, acc[mf][nf][1] + b0);
                    *(float2*)(g_qkv + ((size_t)n*512 + row0 + 8)*1936 + pos) =
                        make_float2(acc[mf][nf][2] + b1, acc[mf][nf][3] + b1);
                }
            }
        }
        __syncthreads();
    }
}

// ---------------- fused axial attention (R11 sim: group-paired) ----------------
#define OFF_V    11440
#define OFF_SIM  22704
#define OFF_RTH  30448
#define OFF_RVP  33580
#define OFF_RES  39212
#define AX_SMEM  (50476*4)

template<int AX>
__global__ void __launch_bounds__(1024,1) axial_kernel()
{
    extern __shared__ float sm[];
    float* qkT  = sm;
    float* vS   = sm + OFF_V;
    float* simS = sm + OFF_SIM;
    const __half* rTh = (const __half*)(sm + OFF_RTH);
    uint32_t* rvS = (uint32_t*)(sm + OFF_RVP);
    float* resS = sm + OFF_RES;

    const int t  = threadIdx.x;
    const int bb = blockIdx.x;
    const int n  = bb / 44;
    const int s  = bb - n*44;

    {
        const float* qsrc = g_qkv + (size_t)n*512*1936 + s*44;
        for (int idx = t; idx < 5632; idx += 1024) {
            int o = idx / 11, q = idx - o*11;
            float4 v4 = *(const float4*)(qsrc + (size_t)o*1936 + q*4);
            int g = o >> 7, wi = o & 127;
            if (wi < 64) {
                int col = g*64 + wi;
                qkT[(q*4+0)*260 + col] = v4.x;
                qkT[(q*4+1)*260 + col] = v4.y;
                qkT[(q*4+2)*260 + col] = v4.z;
                qkT[(q*4+3)*260 + col] = v4.w;
            } else {
                *(float4*)(vS + (g*64 + wi - 64)*44 + q*4) = v4;
            }
        }
        const uint32_t* rthG = (const uint32_t*)g_relTh[AX];
        uint32_t* rthS = (uint32_t*)(sm + OFF_RTH);
        for (int idx = t; idx < 3132; idx += 1024) rthS[idx] = rthG[idx];
        for (int idx = t; idx < 5632; idx += 1024) rvS[idx] = g_rvP[AX][idx];
        if (AX == 1) {
            const float4* rsrc = (const float4*)(g_p + (size_t)n*IMGSZ + s*44);
            float4* rd = (float4*)resS;
            for (int idx = t; idx < 2816; idx += 1024) {
                int ch = idx / 11, q = idx - ch*11;
                rd[idx] = rsrc[ch*484 + q];
            }
        }
    }
    __syncthreads();

    // sim: thread handles (i,j) for a group PAIR
    for (int e2 = t; e2 < 3872; e2 += 1024) {
        int gp = e2 / 1936;
        int r = e2 - gp*1936;
        int i = r / 44;
        int j = r - i*44;
        const uint4* rq = (const uint4*)(rTh + (i - j + 43)*72);
        const uint4* rk = (const uint4*)(rTh + (j - i + 43)*72 + 32);
        float2 qk2[2], qr2[2], kr2[2];
        #pragma unroll
        for (int gg = 0; gg < 2; gg++) {
            qk2[gg] = make_float2(0.f, 0.f);
            qr2[gg] = make_float2(0.f, 0.f);
            kr2[gg] = make_float2(0.f, 0.f);
        }
        #pragma unroll
        for (int cc = 0; cc < 4; cc++) {
            uint4 rqu = rq[cc], rku = rk[cc];
            float2 rq0 = h2f(rqu.x), rq1 = h2f(rqu.y), rq2 = h2f(rqu.z), rq3 = h2f(rqu.w);
            float2 rk0 = h2f(rku.x), rk1 = h2f(rku.y), rk2 = h2f(rku.z), rk3 = h2f(rku.w);
            #pragma unroll
            for (int gg = 0; gg < 2; gg++) {
                int g = gp*2 + gg;
                const float4* qp = (const float4*)(qkT + i*260 + g*64) + 2*cc;
                const float4* kp = (const float4*)(qkT + j*260 + g*64 + 32) + 2*cc;
                float4 q4a = qp[0], q4b = qp[1];
                float4 k4a = kp[0], k4b = kp[1];
                fma2(qk2[gg], make_float2(q4a.x,q4a.y), make_float2(k4a.x,k4a.y));
                fma2(qk2[gg], make_float2(q4a.z,q4a.w), make_float2(k4a.z,k4a.w));
                fma2(qk2[gg], make_float2(q4b.x,q4b.y), make_float2(k4b.x,k4b.y));
                fma2(qk2[gg], make_float2(q4b.z,q4b.w), make_float2(k4b.z,k4b.w));
                fma2(qr2[gg], make_float2(q4a.x,q4a.y), rq0);
                fma2(qr2[gg], make_float2(q4a.z,q4a.w), rq1);
                fma2(qr2[gg], make_float2(q4b.x,q4b.y), rq2);
                fma2(qr2[gg], make_float2(q4b.z,q4b.w), rq3);
                fma2(kr2[gg], make_float2(k4a.x,k4a.y), rk0);
                fma2(kr2[gg], make_float2(k4a.z,k4a.w), rk1);
                fma2(kr2[gg], make_float2(k4b.x,k4b.y), rk2);
                fma2(kr2[gg], make_float2(k4b.z,k4b.w), rk3);
            }
        }
        #pragma unroll
        for (int gg = 0; gg < 2; gg++) {
            int g = gp*2 + gg;
            float qk = qk2[gg].x + qk2[gg].y;
            float qr = qr2[gg].x + qr2[gg].y;
            float kr = kr2[gg].x + kr2[gg].y;
            simS[g*1936 + r] = g_simA[AX][g]*qk + g_simA[AX][4+g]*qr + g_simA[AX][8+g]*kr + g_simBsum[AX][g];
        }
    }
    __syncthreads();

    // softmax: warp per row
    {
        const int wid = t >> 5, lane = t & 31;
        #pragma unroll
        for (int k = 0; k < 6; k++) {
            int r = wid + 32*k;
            if (r < 176) {
                float* row = simS + (r/44)*1936 + (r - (r/44)*44)*44;
                float v1 = row[lane];
                float v2 = (lane < 12) ? row[lane+32] : -1e30f;
                float m = fmaxf(v1, v2);
                #pragma unroll
                for (int off = 16; off; off >>= 1) m = fmaxf(m, __shfl_xor_sync(0xffffffffu, m, off));
                float e1 = __expf(v1 - m);
                float e2 = (lane < 12) ? __expf(v2 - m) : 0.f;
                float su = e1 + e2;
                #pragma unroll
                for (int off = 16; off; off >>= 1) su += __shfl_xor_sync(0xffffffffu, su, off);
                float inv = 1.f / su;
                row[lane] = e1 * inv;
                if (lane < 12) row[lane+32] = e2 * inv;
            }
        }
    }
    __syncthreads();

    // output
    {
        const int ch = t & 255, qtr = t >> 8;
        const int g = ch >> 6, c = ch & 63;
        float2 v2[22];
        const float4* vp = (const float4*)(vS + ch*44);
        #pragma unroll
        for (int q = 0; q < 11; q++) {
            float4 v4 = vp[q];
            v2[2*q]   = make_float2(v4.x, v4.y);
            v2[2*q+1] = make_float2(v4.z, v4.w);
        }
        const float aSV  = g_outA_sv[AX][ch];
        const float aSVE = g_outA_sve[AX][ch];
        const float bO   = g_outB[AX][ch];
        #pragma unroll 1
        for (int ii = 0; ii < 11; ii++) {
            int i = qtr*11 + ii;
            const float2* sr2 = (const float2*)(simS + g*1936 + i*44);
            int b0 = 43 - i;
            const uint32_t* wrow = rvS + (b0 & 1)*2816 + (b0 >> 1)*64 + c;
            float2 sv2 = make_float2(0.f, 0.f), sve2 = make_float2(0.f, 0.f);
            #pragma unroll
            for (int p = 0; p < 22; p++) {
                float2 s2 = sr2[p];
                fma2(sv2, s2, v2[p]);
                fma2(sve2, s2, h2f(wrow[p*64]));
            }
            float val = fmaf(aSV, sv2.x + sv2.y, fmaf(aSVE, sve2.x + sve2.y, bO));
            if (AX == 0) {
                qkT[ch*44 + i] = val;
            } else {
                qkT[i*256 + ch] = val + resS[ch*44 + i];
            }
        }
    }
    __syncthreads();
    if (AX == 0) {
        float* out = g_t1;
        const float4* st4 = (const float4*)qkT;
        for (int idx = t; idx < 2816; idx += 1024) {
            int ch = idx / 11, q = idx - ch*11;
            *(float4*)(out + ((size_t)(n*256 + ch))*1936 + s*44 + q*4) = st4[idx];
        }
    } else {
        // NHWC fp16 stores: py = s+1, x = i+1, ch fast
        const size_t rowbase = ((size_t)MARGIN_LO + (size_t)n*PPX + (size_t)(s+1)*48 + 1)*256;
        for (int idx = t; idx < 11264; idx += 1024) {
            int i = idx >> 8, ch = idx & 255;
            g_xc[rowbase + (size_t)i*256 + ch] = __float2half(qkT[i*256 + ch]);
        }
    }
}

// ---------------- tensor-core conv3x3 v3: fp16 single-pass ----------------
#define C3STAGE 14592
#define C3_B    6144
#define CONV_SMEM (3*C3STAGE + 1024)

__global__ void __launch_bounds__(512,1) conv_mma_kernel(const float* __restrict__ conv_b,
                                                         float* __restrict__ out)
{
    extern __shared__ char smc[];
    const uint32_t sbase = smem_to_u32(smc);
    const int t = threadIdx.x;
    const int wid = t >> 5, lane = t & 31;
    const int bb = blockIdx.x;
    const int n = bb / 18;
    const int widx = bb - n*18;
    const int pxw = widx * 128;
    const int wm = wid & 1, wn = wid >> 1;     // 2 x 8 warp grid

    float* biasS = (float*)(smc + 3*C3STAGE);
    if (t < 256) biasS[t] = conv_b[t];

    const long long arow0 = (long long)MARGIN_LO + (long long)n*PPX + pxw;

    auto load_chunk = [&](int kc, int stage) {
        const int tap = kc >> 4, sub = kc & 15;
        const int offr = (tap/3 - 1)*48 + (tap%3 - 1);
        const long long abase = arow0 + offr;
        const uint32_t sA = sbase + stage*C3STAGE;
        const uint32_t sB = sA + C3_B;
        #pragma unroll
        for (int i = 0; i < 2; i++) {
            int o = t + 512*i;
            if (o < 256) {
                int half = o & 1;
                int row  = o >> 1;
                const __half* g = g_xc + ((size_t)(abase + row))*256 + sub*16 + half*8;
                cp16(sA + row*48 + half*16, g);
            } else if (o < 768) {
                int o2 = o - 256;                 // 0..511
                int krow = o2 >> 5, unit = o2 & 31;
                const __half* g = g_wc + ((size_t)(tap*256 + sub*16 + krow))*256 + unit*8;
                cp16(sB + krow*528 + unit*16, g);
            }
        }
    };

    float acc[4][4][4];
    #pragma unroll
    for (int mf = 0; mf < 4; mf++)
        #pragma unroll
        for (int nf = 0; nf < 4; nf++)
            #pragma unroll
            for (int k = 0; k < 4; k++) acc[mf][nf][k] = 0.f;

    load_chunk(0, 0); CP_COMMIT();
    load_chunk(1, 1); CP_COMMIT();

    for (int kc = 0; kc < 144; kc++) {
        const int stage = kc % 3;
        if (kc + 2 < 144) { load_chunk(kc+2, (kc+2)%3); CP_COMMIT(); CP_WAIT(2); }
        else if (kc + 1 < 144) { CP_WAIT(1); }
        else { CP_WAIT(0); }
        __syncthreads();

        const uint32_t sA = sbase + stage*C3STAGE;
        const uint32_t sB = sA + C3_B;

        uint32_t A[4][4], B[4][2];
        #pragma unroll
        for (int mf = 0; mf < 4; mf++) {
            uint32_t a_off = (wm*64 + mf*16 + (lane & 15))*48 + (lane >> 4)*16;
            ldsm_x4(A[mf], sA + a_off);
        }
        #pragma unroll
        for (int nf = 0; nf < 4; nf++) {
            uint32_t b_off = (lane & 15)*528 + (wn*32 + nf*8)*2;
            ldsm_x2_t(B[nf], sB + b_off);
        }
        #pragma unroll
        for (int mf = 0; mf < 4; mf++)
            #pragma unroll
            for (int nf = 0; nf < 4; nf++)
                mma_f16(acc[mf][nf], A[mf], B[nf]);
        __syncthreads();
    }

    const int b_ = n >> 2, i2 = (n >> 1) & 1, j2 = n & 1;
    #pragma unroll
    for (int mf = 0; mf < 4; mf++) {
        #pragma unroll
        for (int half = 0; half < 2; half++) {
            int px = pxw + wm*64 + mf*16 + (lane >> 2) + half*8;
            int py = px / 48, pxx = px - py*48;
            bool valid = (py >= 1 && py <= 44) && (pxx >= 1 && pxx <= 44);
            if (!valid) continue;
            size_t ob = ((size_t)(b_*256))*7744 + (size_t)(i2*44 + (py-1))*88 + j2*44 + (pxx-1);
            #pragma unroll
            for (int nf = 0; nf < 4; nf++) {
                int co = wn*32 + nf*8 + (lane & 3)*2;
                out[ob + (size_t)co*7744]     = acc[mf][nf][half*2+0] + biasS[co];
                out[ob + (size_t)(co+1)*7744] = acc[mf][nf][half*2+1] + biasS[co+1];
            }
        }
    }
}

// ---------------- launch ----------------
extern "C" void kernel_launch(void* const* d_in, const int* in_sizes, int n_in,
                              void* d_out, int out_size)
{
    const float* x        = (const float*)d_in[0];
    const float* h_qkv_w  = (const float*)d_in[1];
    const float* h_bn_qkv = (const float*)d_in[2];
    const float* h_bn_sim = (const float*)d_in[3];
    const float* h_bn_out = (const float*)d_in[4];
    const float* h_rel    = (const float*)d_in[5];
    const float* w_qkv_w  = (const float*)d_in[6];
    const float* w_bn_qkv = (const float*)d_in[7];
    const float* w_bn_sim = (const float*)d_in[8];
    const float* w_bn_out = (const float*)d_in[9];
    const float* w_rel    = (const float*)d_in[10];
    const float* conv_w   = (const float*)d_in[11];
    const float* conv_b   = (const float*)d_in[12];
    float* out = (float*)d_out;

    cudaFuncSetAttribute(axial_kernel<0>,  cudaFuncAttributeMaxDynamicSharedMemorySize, AX_SMEM);
    cudaFuncSetAttribute(axial_kernel<1>,  cudaFuncAttributeMaxDynamicSharedMemorySize, AX_SMEM);
    cudaFuncSetAttribute(qkv_gemm_kernel,  cudaFuncAttributeMaxDynamicSharedMemorySize, GEMM_SMEM);
    cudaFuncSetAttribute(conv_mma_kernel,  cudaFuncAttributeMaxDynamicSharedMemorySize, CONV_SMEM);

    prep_kernel<<<(256*256*9 + 255)/256, 256>>>(h_qkv_w, h_bn_qkv, h_bn_sim, h_bn_out,
                                                w_qkv_w, w_bn_qkv, w_bn_sim, w_bn_out,
                                                conv_w, h_rel, w_rel);
    patchify_kernel<<<NPATCH*256, 256>>>(x);
    qkv_gemm_kernel<<<dim3(16,NPATCH), 512, GEMM_SMEM>>>(0);
    axial_kernel<0><<<NB, 1024, AX_SMEM>>>();
    transpose_kernel<<<NPATCH*256, 256>>>();
    qkv_gemm_kernel<<<dim3(16,NPATCH), 512, GEMM_SMEM>>>(1);
    axial_kernel<1><<<NB, 1024, AX_SMEM>>>();
    conv_mma_kernel<<<NPATCH*18, 512, CONV_SMEM>>>(conv_b, out);
}

// round 14
// speedup vs baseline: 3.0866x; 1.0292x over previous
#include <cuda_runtime.h>
#include <cuda_bf16.h>
#include <cuda_fp16.h>
#include <math.h>
#include <cstdint>

#define EPS 1e-5f
#define NPATCH 64
#define HS 44
#define NB (NPATCH*HS)          // 2816
#define PLANE 1936
#define IMGSZ (256*1936)

// padded conv geometry
#define PPX 2208
#define MARGIN_LO 128
#define XROWS (MARGIN_LO + NPATCH*PPX + 256)

typedef unsigned long long ull;
__device__ __forceinline__ void fma2(float2 &d, float2 a, float2 b) {
    asm("fma.rn.f32x2 %0, %1, %2, %0;"
        : "+l"(reinterpret_cast<ull&>(d))
        : "l"(reinterpret_cast<ull&>(a)), "l"(reinterpret_cast<ull&>(b)));
}
__device__ __forceinline__ float2 h2f(uint32_t u) {
    __half2 h = *reinterpret_cast<__half2*>(&u);
    return __half22float2(h);
}

// ---------------- mma / ldmatrix / cp.async helpers ----------------
__device__ __forceinline__ uint32_t smem_to_u32(const void* p) {
    uint32_t a;
    asm("{ .reg .u64 t; cvta.to.shared.u64 t, %1; cvt.u32.u64 %0, t; }" : "=r"(a) : "l"(p));
    return a;
}
__device__ __forceinline__ void ldsm_x4(uint32_t a[4], uint32_t addr) {
    asm volatile("ldmatrix.sync.aligned.m8n8.x4.shared.b16 {%0,%1,%2,%3}, [%4];"
        : "=r"(a[0]),"=r"(a[1]),"=r"(a[2]),"=r"(a[3]) : "r"(addr));
}
__device__ __forceinline__ void ldsm_x2_t(uint32_t b[2], uint32_t addr) {
    asm volatile("ldmatrix.sync.aligned.m8n8.x2.trans.shared.b16 {%0,%1}, [%2];"
        : "=r"(b[0]),"=r"(b[1]) : "r"(addr));
}
__device__ __forceinline__ void mma_f16(float c[4], const uint32_t a[4], const uint32_t b[2]) {
    asm volatile("mma.sync.aligned.m16n8k16.row.col.f32.f16.f16.f32 "
        "{%0,%1,%2,%3}, {%4,%5,%6,%7}, {%8,%9}, {%0,%1,%2,%3};"
        : "+f"(c[0]),"+f"(c[1]),"+f"(c[2]),"+f"(c[3])
        : "r"(a[0]),"r"(a[1]),"r"(a[2]),"r"(a[3]), "r"(b[0]),"r"(b[1]));
}
__device__ __forceinline__ void cp16(uint32_t saddr, const void* g) {
    asm volatile("cp.async.cg.shared.global [%0], [%1], 16;" :: "r"(saddr), "l"(g));
}
#define CP_COMMIT() asm volatile("cp.async.commit_group;" ::: "memory")
#define CP_WAIT(n)  asm volatile("cp.async.wait_group %0;" :: "n"(n) : "memory")

// ---------------- static device scratch ----------------
__device__ float g_p [NPATCH*IMGSZ];
__device__ float g_t1[NPATCH*IMGSZ];
__device__ float g_qkv[(size_t)NPATCH*512*PLANE];
__device__ float g_qkvb[2][512];
__device__ float g_simA[2][12];
__device__ float g_simBsum[2][4];
__device__ float g_outA_sv[2][256];
__device__ float g_outA_sve[2][256];
__device__ float g_outB[2][256];
__device__ __half g_relTh[2][87*72];
__device__ uint32_t g_rvP[2][5632];
// tensor-core operand buffers
__device__ __align__(1024) __half g_xb[(size_t)NPATCH*256*PLANE + 256];  // qkv-gemm x (fp16 single)
__device__ __align__(1024) __half g_qwh[2][512*256];   // qkv W fp16 hi
__device__ __align__(1024) __half g_qwl[2][512*256];   // qkv W fp16 lo
__device__ __align__(1024) __half g_xc[(size_t)XROWS*256];   // conv activations fp16
__device__ __align__(1024) __half g_wc[9*256*256];           // conv weights fp16 [tap][ci][co]

// ---------------- prep ----------------
__global__ void prep_kernel(const float* __restrict__ h_qkv_w, const float* __restrict__ h_bn_qkv,
                            const float* __restrict__ h_bn_sim, const float* __restrict__ h_bn_out,
                            const float* __restrict__ w_qkv_w, const float* __restrict__ w_bn_qkv,
                            const float* __restrict__ w_bn_sim, const float* __restrict__ w_bn_out,
                            const float* __restrict__ conv_w,
                            const float* __restrict__ h_rel, const float* __restrict__ w_rel)
{
    int idx = blockIdx.x * blockDim.x + threadIdx.x;
    const __half zero = __float2half(0.f);

    if (idx < 256*256*9) {
        int co  = idx / 2304;
        int rem = idx - co*2304;
        int ci  = rem / 9;
        int tap = rem - ci*9;
        g_wc[(tap*256 + ci)*256 + co] = __float2half(conv_w[idx]);
    }
    if (idx < MARGIN_LO*256) g_xc[idx] = zero;
    if (idx < 256*256) g_xc[(size_t)(MARGIN_LO + NPATCH*PPX)*256 + idx] = zero;
    // NHWC patch-border zeroing
    for (int z = idx; z < NPATCH*69632; z += 2304*256) {
        int n = z / 69632, e = z - n*69632;
        int py, x, ch;
        if (e < 12288)      { py = 0;  x = e >> 8;              ch = e & 255; }
        else if (e < 24576) { int e2 = e - 12288; py = 45; x = e2 >> 8; ch = e2 & 255; }
        else {
            int e2 = e - 24576;
            py = 1 + (e2 >> 10);
            int r2 = e2 & 1023;
            int xi = r2 >> 8;
            x = (xi == 0) ? 0 : (44 + xi);
            ch = r2 & 255;
        }
        g_xc[((size_t)MARGIN_LO + (size_t)n*PPX + py*48 + x)*256 + ch] = zero;
    }
    if (idx < 2*131072) {
        int ax = idx >> 17;
        int r  = idx & 131071;
        int o  = r & 511;
        int c  = r >> 9;
        const float* bn = ax ? w_bn_qkv : h_bn_qkv;
        const float* W  = ax ? w_qkv_w : h_qkv_w;
        float s = bn[o] * rsqrtf(bn[1536+o] + EPS);
        float wv = W[o*256 + c] * s;
        __half hi = __float2half(wv);
        float lo = wv - __half2float(hi);
        g_qwh[ax][o*256 + c] = hi;
        g_qwl[ax][o*256 + c] = __float2half(lo);
        if (c == 0) g_qkvb[ax][o] = bn[512+o] - bn[1024+o]*s;
    }
    if (idx < 8) {
        int ax = idx >> 2, g = idx & 3;
        const float* bs = ax ? w_bn_sim : h_bn_sim;
        float shsum = 0.f;
        #pragma unroll
        for (int p = 0; p < 3; p++) {
            int ch = p*4 + g;
            float s = bs[ch] * rsqrtf(bs[36+ch] + EPS);
            g_simA[ax][p*4+g] = (p == 0 ? 1.f : 0.1f) * s;
            shsum += bs[12+ch] - bs[24+ch]*s;
        }
        g_simBsum[ax][g] = shsum;
    }
    if (idx < 512) {
        int ax = idx >> 8, cc = idx & 255;
        const float* bo = ax ? w_bn_out : h_bn_out;
        int o1 = 2*cc, o2 = 2*cc + 1;
        float s1 = bo[o1] * rsqrtf(bo[1536+o1] + EPS);
        float s2 = bo[o2] * rsqrtf(bo[1536+o2] + EPS);
        g_outA_sv[ax][cc]  = s1;
        g_outA_sve[ax][cc] = 0.1f * s2;
        g_outB[ax][cc] = (bo[512+o1] - bo[1024+o1]*s1) + (bo[512+o2] - bo[1024+o2]*s2);
    }
    if (idx < 2*87*72) {
        int ax = idx / 6264, r = idx - ax*6264;
        int d = r / 72, c = r - d*72;
        const float* rl = ax ? w_rel : h_rel;
        g_relTh[ax][r] = __float2half(c < 64 ? rl[c*87 + d] : 0.f);
    }
    if (idx < 2*5632) {
        int ax = idx / 5632, r = idx - ax*5632;
        int par = r / 2816, r2 = r - par*2816;
        int dhalf = r2 >> 6, c = r2 & 63;
        const float* rl = ax ? w_rel : h_rel;
        int d0 = 2*dhalf + par;
        float lo = (d0     <= 86) ? rl[(64+c)*87 + 86 - d0]     : 0.f;
        float hi = (d0 + 1 <= 86) ? rl[(64+c)*87 + 86 - d0 - 1] : 0.f;
        __half2 h2v = __halves2half2(__float2half(lo), __float2half(hi));
        g_rvP[ax][par*2816 + dhalf*64 + c] = *reinterpret_cast<uint32_t*>(&h2v);
    }
}

// ---------------- patchify ----------------
__global__ void __launch_bounds__(256,1) patchify_kernel(const float* __restrict__ x)
{
    __shared__ float tile[44*45];
    const int b = blockIdx.x;
    const int np = b >> 8, c = b & 255;
    const int bb_ = np >> 2, i2 = (np >> 1) & 1, j2 = np & 1;
    const float* src = x + ((size_t)(bb_*256 + c)*88 + i2*44)*88 + j2*44;
    float* dp = g_p + (size_t)b*1936;
    const int t = threadIdx.x;
    for (int idx = t; idx < 1936; idx += 256) {
        int y = idx / 44, xq = idx - y*44;
        float v = src[y*88 + xq];
        dp[idx] = v;
        tile[xq*45 + y] = v;
    }
    __syncthreads();
    const size_t base = (size_t)b*1936;
    for (int idx = t; idx < 1936; idx += 256) {
        int r = idx / 44, col = idx - r*44;
        g_xb[base + idx] = __float2half(tile[r*45 + col]);
    }
}

// ---------------- transpose g_t1 [c][x][y] -> fp16 [c][y][x] ----------------
__global__ void __launch_bounds__(256,1) transpose_kernel()
{
    __shared__ float tile[44*45];
    const int b = blockIdx.x;
    const float* src = g_t1 + (size_t)b*1936;
    const int t = threadIdx.x;
    for (int idx = t; idx < 1936; idx += 256) {
        int r = idx / 44, col = idx - r*44;
        tile[col*45 + r] = src[idx];
    }
    __syncthreads();
    const size_t base = (size_t)b*1936;
    for (int idx = t; idx < 1936; idx += 256) {
        int r = idx / 44, col = idx - r*44;
        g_xb[base + idx] = __float2half(tile[r*45 + col]);
    }
}

// ---------------- qkv GEMM v4: fp16 2-pass (x single, w hi/lo), 512 threads ----------------
// smem: B[256 rows x 272B]@0 = 69632 | A stages @69632 (2 x 12288: Ah 6144 + Al 6144)
#define QB_A    69632
#define QB_AST  12288
#define QB_ALO  6144
#define GEMM_SMEM (69632 + 2*12288)

__global__ void __launch_bounds__(512,1) qkv_gemm_kernel(int ax)
{
    extern __shared__ char smc[];
    const uint32_t sbase = smem_to_u32(smc);
    const int t = threadIdx.x;
    const int wid = t >> 5, lane = t & 31;
    const int ntile = blockIdx.x;
    const int n     = blockIdx.y;
    const int pxw = ntile * 128;
    const int wm = wid & 1, wn = wid >> 1;    // 2 x 8 warp grid
    const __half* qwh = g_qwh[ax];
    const __half* qwl = g_qwl[ax];

    // load B panel (x fp16): 256 k-rows x 128 pos, rows padded to 272 B
    for (int j = t; j < 4096; j += 512) {
        int row = j >> 4, unit = j & 15;
        const __half* g = g_xb + ((size_t)(n*256 + row))*1936 + pxw + unit*8;
        cp16(sbase + row*272 + unit*16, g);
    }
    CP_COMMIT();
    CP_WAIT(0);
    __syncthreads();

    auto load_A = [&](int mtile, int kc, int stage) {
        const int mrow0 = mtile*128;
        const uint32_t sA = sbase + QB_A + stage*QB_AST;
        int o = t;
        int hl   = o & 1;
        int half = (o >> 1) & 1;
        int row  = o >> 2;
        const __half* g = (hl ? qwl : qwh) + (size_t)(mrow0 + row)*256 + kc*16 + half*8;
        cp16(sA + hl*QB_ALO + row*48 + half*16, g);
    };

    for (int mtile = 0; mtile < 4; mtile++) {
        float acc[4][2][4];
        #pragma unroll
        for (int mf = 0; mf < 4; mf++)
            #pragma unroll
            for (int nf = 0; nf < 2; nf++)
                #pragma unroll
                for (int k = 0; k < 4; k++) acc[mf][nf][k] = 0.f;

        load_A(mtile, 0, 0); CP_COMMIT();
        load_A(mtile, 1, 1); CP_COMMIT();

        for (int kc = 0; kc < 16; kc++) {
            const int stage = kc & 1;
            if (kc + 1 < 16) { CP_WAIT(1); }
            else             { CP_WAIT(0); }
            __syncthreads();

            const uint32_t sA = sbase + QB_A + stage*QB_AST;
            uint32_t Ah[4][4], Al[4][4], B[2][2];
            #pragma unroll
            for (int mf = 0; mf < 4; mf++) {
                uint32_t a_off = (wm*64 + mf*16 + (lane & 15))*48 + (lane >> 4)*16;
                ldsm_x4(Ah[mf], sA + a_off);
                ldsm_x4(Al[mf], sA + QB_ALO + a_off);
            }
            #pragma unroll
            for (int nf = 0; nf < 2; nf++) {
                uint32_t b_off = (kc*16 + (lane & 15))*272 + (wn*16 + nf*8)*2;
                ldsm_x2_t(B[nf], sbase + b_off);
            }
            __syncthreads();
            if (kc + 2 < 16) { load_A(mtile, kc+2, stage); CP_COMMIT(); }
            #pragma unroll
            for (int mf = 0; mf < 4; mf++)
                #pragma unroll
                for (int nf = 0; nf < 2; nf++) {
                    mma_f16(acc[mf][nf], Ah[mf], B[nf]);
                    mma_f16(acc[mf][nf], Al[mf], B[nf]);
                }
        }

        const int mrow0 = mtile*128;
        #pragma unroll
        for (int mf = 0; mf < 4; mf++) {
            int row0 = mrow0 + wm*64 + mf*16 + (lane >> 2);
            #pragma unroll
            for (int nf = 0; nf < 2; nf++) {
                int pos = pxw + wn*16 + nf*8 + (lane & 3)*2;
                if (pos < 1936) {
                    float b0 = g_qkvb[ax][row0];
                    float b1 = g_qkvb[ax][row0 + 8];
                    *(float2*)(g_qkv + ((size_t)n*512 + row0)*1936 + pos) =
                        make_float2(acc[mf][nf][0] + b0, acc[mf][nf][1] + b0);
                    *(float2*)(g_qkv + ((size_t)n*512 + row0 + 8)*1936 + pos) =
                        make_float2(acc[mf][nf][2] + b1, acc[mf][nf][3] + b1);
                }
            }
        }
        __syncthreads();
    }
}

// ---------------- fused axial attention (R13 version) ----------------
#define OFF_V    11440
#define OFF_SIM  22704
#define OFF_RTH  30448
#define OFF_RVP  33580
#define OFF_RES  39212
#define AX_SMEM  (50476*4)

template<int AX>
__global__ void __launch_bounds__(1024,1) axial_kernel()
{
    extern __shared__ float sm[];
    float* qkT  = sm;
    float* vS   = sm + OFF_V;
    float* simS = sm + OFF_SIM;
    const __half* rTh = (const __half*)(sm + OFF_RTH);
    uint32_t* rvS = (uint32_t*)(sm + OFF_RVP);
    float* resS = sm + OFF_RES;

    const int t  = threadIdx.x;
    const int bb = blockIdx.x;
    const int n  = bb / 44;
    const int s  = bb - n*44;

    {
        const float* qsrc = g_qkv + (size_t)n*512*1936 + s*44;
        for (int idx = t; idx < 5632; idx += 1024) {
            int o = idx / 11, q = idx - o*11;
            float4 v4 = *(const float4*)(qsrc + (size_t)o*1936 + q*4);
            int g = o >> 7, wi = o & 127;
            if (wi < 64) {
                int col = g*64 + wi;
                qkT[(q*4+0)*260 + col] = v4.x;
                qkT[(q*4+1)*260 + col] = v4.y;
                qkT[(q*4+2)*260 + col] = v4.z;
                qkT[(q*4+3)*260 + col] = v4.w;
            } else {
                *(float4*)(vS + (g*64 + wi - 64)*44 + q*4) = v4;
            }
        }
        const uint32_t* rthG = (const uint32_t*)g_relTh[AX];
        uint32_t* rthS = (uint32_t*)(sm + OFF_RTH);
        for (int idx = t; idx < 3132; idx += 1024) rthS[idx] = rthG[idx];
        for (int idx = t; idx < 5632; idx += 1024) rvS[idx] = g_rvP[AX][idx];
        if (AX == 1) {
            const float4* rsrc = (const float4*)(g_p + (size_t)n*IMGSZ + s*44);
            float4* rd = (float4*)resS;
            for (int idx = t; idx < 2816; idx += 1024) {
                int ch = idx / 11, q = idx - ch*11;
                rd[idx] = rsrc[ch*484 + q];
            }
        }
    }
    __syncthreads();

    // sim: thread handles (i,j) for a group PAIR
    for (int e2 = t; e2 < 3872; e2 += 1024) {
        int gp = e2 / 1936;
        int r = e2 - gp*1936;
        int i = r / 44;
        int j = r - i*44;
        const uint4* rq = (const uint4*)(rTh + (i - j + 43)*72);
        const uint4* rk = (const uint4*)(rTh + (j - i + 43)*72 + 32);
        float2 qk2[2], qr2[2], kr2[2];
        #pragma unroll
        for (int gg = 0; gg < 2; gg++) {
            qk2[gg] = make_float2(0.f, 0.f);
            qr2[gg] = make_float2(0.f, 0.f);
            kr2[gg] = make_float2(0.f, 0.f);
        }
        #pragma unroll
        for (int cc = 0; cc < 4; cc++) {
            uint4 rqu = rq[cc], rku = rk[cc];
            float2 rq0 = h2f(rqu.x), rq1 = h2f(rqu.y), rq2 = h2f(rqu.z), rq3 = h2f(rqu.w);
            float2 rk0 = h2f(rku.x), rk1 = h2f(rku.y), rk2 = h2f(rku.z), rk3 = h2f(rku.w);
            #pragma unroll
            for (int gg = 0; gg < 2; gg++) {
                int g = gp*2 + gg;
                const float4* qp = (const float4*)(qkT + i*260 + g*64) + 2*cc;
                const float4* kp = (const float4*)(qkT + j*260 + g*64 + 32) + 2*cc;
                float4 q4a = qp[0], q4b = qp[1];
                float4 k4a = kp[0], k4b = kp[1];
                fma2(qk2[gg], make_float2(q4a.x,q4a.y), make_float2(k4a.x,k4a.y));
                fma2(qk2[gg], make_float2(q4a.z,q4a.w), make_float2(k4a.z,k4a.w));
                fma2(qk2[gg], make_float2(q4b.x,q4b.y), make_float2(k4b.x,k4b.y));
                fma2(qk2[gg], make_float2(q4b.z,q4b.w), make_float2(k4b.z,k4b.w));
                fma2(qr2[gg], make_float2(q4a.x,q4a.y), rq0);
                fma2(qr2[gg], make_float2(q4a.z,q4a.w), rq1);
                fma2(qr2[gg], make_float2(q4b.x,q4b.y), rq2);
                fma2(qr2[gg], make_float2(q4b.z,q4b.w), rq3);
                fma2(kr2[gg], make_float2(k4a.x,k4a.y), rk0);
                fma2(kr2[gg], make_float2(k4a.z,k4a.w), rk1);
                fma2(kr2[gg], make_float2(k4b.x,k4b.y), rk2);
                fma2(kr2[gg], make_float2(k4b.z,k4b.w), rk3);
            }
        }
        #pragma unroll
        for (int gg = 0; gg < 2; gg++) {
            int g = gp*2 + gg;
            float qk = qk2[gg].x + qk2[gg].y;
            float qr = qr2[gg].x + qr2[gg].y;
            float kr = kr2[gg].x + kr2[gg].y;
            simS[g*1936 + r] = g_simA[AX][g]*qk + g_simA[AX][4+g]*qr + g_simA[AX][8+g]*kr + g_simBsum[AX][g];
        }
    }
    __syncthreads();

    // softmax: warp per row
    {
        const int wid = t >> 5, lane = t & 31;
        #pragma unroll
        for (int k = 0; k < 6; k++) {
            int r = wid + 32*k;
            if (r < 176) {
                float* row = simS + (r/44)*1936 + (r - (r/44)*44)*44;
                float v1 = row[lane];
                float v2 = (lane < 12) ? row[lane+32] : -1e30f;
                float m = fmaxf(v1, v2);
                #pragma unroll
                for (int off = 16; off; off >>= 1) m = fmaxf(m, __shfl_xor_sync(0xffffffffu, m, off));
                float e1 = __expf(v1 - m);
                float e2 = (lane < 12) ? __expf(v2 - m) : 0.f;
                float su = e1 + e2;
                #pragma unroll
                for (int off = 16; off; off >>= 1) su += __shfl_xor_sync(0xffffffffu, su, off);
                float inv = 1.f / su;
                row[lane] = e1 * inv;
                if (lane < 12) row[lane+32] = e2 * inv;
            }
        }
    }
    __syncthreads();

    // output
    {
        const int ch = t & 255, qtr = t >> 8;
        const int g = ch >> 6, c = ch & 63;
        float2 v2[22];
        const float4* vp = (const float4*)(vS + ch*44);
        #pragma unroll
        for (int q = 0; q < 11; q++) {
            float4 v4 = vp[q];
            v2[2*q]   = make_float2(v4.x, v4.y);
            v2[2*q+1] = make_float2(v4.z, v4.w);
        }
        const float aSV  = g_outA_sv[AX][ch];
        const float aSVE = g_outA_sve[AX][ch];
        const float bO   = g_outB[AX][ch];
        #pragma unroll 1
        for (int ii = 0; ii < 11; ii++) {
            int i = qtr*11 + ii;
            const float2* sr2 = (const float2*)(simS + g*1936 + i*44);
            int b0 = 43 - i;
            const uint32_t* wrow = rvS + (b0 & 1)*2816 + (b0 >> 1)*64 + c;
            float2 sv2 = make_float2(0.f, 0.f), sve2 = make_float2(0.f, 0.f);
            #pragma unroll
            for (int p = 0; p < 22; p++) {
                float2 s2 = sr2[p];
                fma2(sv2, s2, v2[p]);
                fma2(sve2, s2, h2f(wrow[p*64]));
            }
            float val = fmaf(aSV, sv2.x + sv2.y, fmaf(aSVE, sve2.x + sve2.y, bO));
            if (AX == 0) {
                qkT[ch*44 + i] = val;
            } else {
                qkT[i*256 + ch] = val + resS[ch*44 + i];
            }
        }
    }
    __syncthreads();
    if (AX == 0) {
        float* out = g_t1;
        const float4* st4 = (const float4*)qkT;
        for (int idx = t; idx < 2816; idx += 1024) {
            int ch = idx / 11, q = idx - ch*11;
            *(float4*)(out + ((size_t)(n*256 + ch))*1936 + s*44 + q*4) = st4[idx];
        }
    } else {
        const size_t rowbase = ((size_t)MARGIN_LO + (size_t)n*PPX + (size_t)(s+1)*48 + 1)*256;
        for (int idx = t; idx < 11264; idx += 1024) {
            int i = idx >> 8, ch = idx & 255;
            g_xc[rowbase + (size_t)i*256 + ch] = __float2half(qkT[i*256 + ch]);
        }
    }
}

// ---------------- tensor-core conv3x3 v3: fp16 single-pass (R13) ----------------
#define C3STAGE 14592
#define C3_B    6144
#define CONV_SMEM (3*C3STAGE + 1024)

__global__ void __launch_bounds__(512,1) conv_mma_kernel(const float* __restrict__ conv_b,
                                                         float* __restrict__ out)
{
    extern __shared__ char smc[];
    const uint32_t sbase = smem_to_u32(smc);
    const int t = threadIdx.x;
    const int wid = t >> 5, lane = t & 31;
    const int bb = blockIdx.x;
    const int n = bb / 18;
    const int widx = bb - n*18;
    const int pxw = widx * 128;
    const int wm = wid & 1, wn = wid >> 1;

    float* biasS = (float*)(smc + 3*C3STAGE);
    if (t < 256) biasS[t] = conv_b[t];

    const long long arow0 = (long long)MARGIN_LO + (long long)n*PPX + pxw;

    auto load_chunk = [&](int kc, int stage) {
        const int tap = kc >> 4, sub = kc & 15;
        const int offr = (tap/3 - 1)*48 + (tap%3 - 1);
        const long long abase = arow0 + offr;
        const uint32_t sA = sbase + stage*C3STAGE;
        const uint32_t sB = sA + C3_B;
        #pragma unroll
        for (int i = 0; i < 2; i++) {
            int o = t + 512*i;
            if (o < 256) {
                int half = o & 1;
                int row  = o >> 1;
                const __half* g = g_xc + ((size_t)(abase + row))*256 + sub*16 + half*8;
                cp16(sA + row*48 + half*16, g);
            } else if (o < 768) {
                int o2 = o - 256;
                int krow = o2 >> 5, unit = o2 & 31;
                const __half* g = g_wc + ((size_t)(tap*256 + sub*16 + krow))*256 + unit*8;
                cp16(sB + krow*528 + unit*16, g);
            }
        }
    };

    float acc[4][4][4];
    #pragma unroll
    for (int mf = 0; mf < 4; mf++)
        #pragma unroll
        for (int nf = 0; nf < 4; nf++)
            #pragma unroll
            for (int k = 0; k < 4; k++) acc[mf][nf][k] = 0.f;

    load_chunk(0, 0); CP_COMMIT();
    load_chunk(1, 1); CP_COMMIT();

    for (int kc = 0; kc < 144; kc++) {
        const int stage = kc % 3;
        if (kc + 2 < 144) { load_chunk(kc+2, (kc+2)%3); CP_COMMIT(); CP_WAIT(2); }
        else if (kc + 1 < 144) { CP_WAIT(1); }
        else { CP_WAIT(0); }
        __syncthreads();

        const uint32_t sA = sbase + stage*C3STAGE;
        const uint32_t sB = sA + C3_B;

        uint32_t A[4][4], B[4][2];
        #pragma unroll
        for (int mf = 0; mf < 4; mf++) {
            uint32_t a_off = (wm*64 + mf*16 + (lane & 15))*48 + (lane >> 4)*16;
            ldsm_x4(A[mf], sA + a_off);
        }
        #pragma unroll
        for (int nf = 0; nf < 4; nf++) {
            uint32_t b_off = (lane & 15)*528 + (wn*32 + nf*8)*2;
            ldsm_x2_t(B[nf], sB + b_off);
        }
        #pragma unroll
        for (int mf = 0; mf < 4; mf++)
            #pragma unroll
            for (int nf = 0; nf < 4; nf++)
                mma_f16(acc[mf][nf], A[mf], B[nf]);
        __syncthreads();
    }

    const int b_ = n >> 2, i2 = (n >> 1) & 1, j2 = n & 1;
    #pragma unroll
    for (int mf = 0; mf < 4; mf++) {
        #pragma unroll
        for (int half = 0; half < 2; half++) {
            int px = pxw + wm*64 + mf*16 + (lane >> 2) + half*8;
            int py = px / 48, pxx = px - py*48;
            bool valid = (py >= 1 && py <= 44) && (pxx >= 1 && pxx <= 44);
            if (!valid) continue;
            size_t ob = ((size_t)(b_*256))*7744 + (size_t)(i2*44 + (py-1))*88 + j2*44 + (pxx-1);
            #pragma unroll
            for (int nf = 0; nf < 4; nf++) {
                int co = wn*32 + nf*8 + (lane & 3)*2;
                out[ob + (size_t)co*7744]     = acc[mf][nf][half*2+0] + biasS[co];
                out[ob + (size_t)(co+1)*7744] = acc[mf][nf][half*2+1] + biasS[co+1];
            }
        }
    }
}

// ---------------- launch ----------------
extern "C" void kernel_launch(void* const* d_in, const int* in_sizes, int n_in,
                              void* d_out, int out_size)
{
    const float* x        = (const float*)d_in[0];
    const float* h_qkv_w  = (const float*)d_in[1];
    const float* h_bn_qkv = (const float*)d_in[2];
    const float* h_bn_sim = (const float*)d_in[3];
    const float* h_bn_out = (const float*)d_in[4];
    const float* h_rel    = (const float*)d_in[5];
    const float* w_qkv_w  = (const float*)d_in[6];
    const float* w_bn_qkv = (const float*)d_in[7];
    const float* w_bn_sim = (const float*)d_in[8];
    const float* w_bn_out = (const float*)d_in[9];
    const float* w_rel    = (const float*)d_in[10];
    const float* conv_w   = (const float*)d_in[11];
    const float* conv_b   = (const float*)d_in[12];
    float* out = (float*)d_out;

    cudaFuncSetAttribute(axial_kernel<0>,  cudaFuncAttributeMaxDynamicSharedMemorySize, AX_SMEM);
    cudaFuncSetAttribute(axial_kernel<1>,  cudaFuncAttributeMaxDynamicSharedMemorySize, AX_SMEM);
    cudaFuncSetAttribute(qkv_gemm_kernel,  cudaFuncAttributeMaxDynamicSharedMemorySize, GEMM_SMEM);
    cudaFuncSetAttribute(conv_mma_kernel,  cudaFuncAttributeMaxDynamicSharedMemorySize, CONV_SMEM);

    prep_kernel<<<(256*256*9 + 255)/256, 256>>>(h_qkv_w, h_bn_qkv, h_bn_sim, h_bn_out,
                                                w_qkv_w, w_bn_qkv, w_bn_sim, w_bn_out,
                                                conv_w, h_rel, w_rel);
    patchify_kernel<<<NPATCH*256, 256>>>(x);
    qkv_gemm_kernel<<<dim3(16,NPATCH), 512, GEMM_SMEM>>>(0);
    axial_kernel<0><<<NB, 1024, AX_SMEM>>>();
    transpose_kernel<<<NPATCH*256, 256>>>();
    qkv_gemm_kernel<<<dim3(16,NPATCH), 512, GEMM_SMEM>>>(1);
    axial_kernel<1><<<NB, 1024, AX_SMEM>>>();
    conv_mma_kernel<<<NPATCH*18, 512, CONV_SMEM>>>(conv_b, out);
}

// round 15
// speedup vs baseline: 3.1132x; 1.0086x over previous
#include <cuda_runtime.h>
#include <cuda_bf16.h>
#include <cuda_fp16.h>
#include <math.h>
#include <cstdint>

#define EPS 1e-5f
#define NPATCH 64
#define HS 44
#define NB (NPATCH*HS)          // 2816
#define PLANE 1936
#define IMGSZ (256*1936)

// padded conv geometry
#define PPX 2208
#define MARGIN_LO 128
#define XROWS (MARGIN_LO + NPATCH*PPX + 256)

typedef unsigned long long ull;
__device__ __forceinline__ void fma2(float2 &d, float2 a, float2 b) {
    asm("fma.rn.f32x2 %0, %1, %2, %0;"
        : "+l"(reinterpret_cast<ull&>(d))
        : "l"(reinterpret_cast<ull&>(a)), "l"(reinterpret_cast<ull&>(b)));
}
__device__ __forceinline__ float2 h2f(uint32_t u) {
    __half2 h = *reinterpret_cast<__half2*>(&u);
    return __half22float2(h);
}

// ---------------- mma / ldmatrix / cp.async helpers ----------------
__device__ __forceinline__ uint32_t smem_to_u32(const void* p) {
    uint32_t a;
    asm("{ .reg .u64 t; cvta.to.shared.u64 t, %1; cvt.u32.u64 %0, t; }" : "=r"(a) : "l"(p));
    return a;
}
__device__ __forceinline__ void ldsm_x4(uint32_t a[4], uint32_t addr) {
    asm volatile("ldmatrix.sync.aligned.m8n8.x4.shared.b16 {%0,%1,%2,%3}, [%4];"
        : "=r"(a[0]),"=r"(a[1]),"=r"(a[2]),"=r"(a[3]) : "r"(addr));
}
__device__ __forceinline__ void ldsm_x2_t(uint32_t b[2], uint32_t addr) {
    asm volatile("ldmatrix.sync.aligned.m8n8.x2.trans.shared.b16 {%0,%1}, [%2];"
        : "=r"(b[0]),"=r"(b[1]) : "r"(addr));
}
__device__ __forceinline__ void mma_f16(float c[4], const uint32_t a[4], const uint32_t b[2]) {
    asm volatile("mma.sync.aligned.m16n8k16.row.col.f32.f16.f16.f32 "
        "{%0,%1,%2,%3}, {%4,%5,%6,%7}, {%8,%9}, {%0,%1,%2,%3};"
        : "+f"(c[0]),"+f"(c[1]),"+f"(c[2]),"+f"(c[3])
        : "r"(a[0]),"r"(a[1]),"r"(a[2]),"r"(a[3]), "r"(b[0]),"r"(b[1]));
}
__device__ __forceinline__ void cp16(uint32_t saddr, const void* g) {
    asm volatile("cp.async.cg.shared.global [%0], [%1], 16;" :: "r"(saddr), "l"(g));
}
#define CP_COMMIT() asm volatile("cp.async.commit_group;" ::: "memory")
#define CP_WAIT(n)  asm volatile("cp.async.wait_group %0;" :: "n"(n) : "memory")

// ---------------- static device scratch ----------------
__device__ float g_p [NPATCH*IMGSZ];
__device__ float g_t1[NPATCH*IMGSZ];
__device__ __half g_qkv[(size_t)NPATCH*512*PLANE];   // fp16 qkv intermediate
__device__ float g_qkvb[2][512];
__device__ float g_simA[2][12];
__device__ float g_simBsum[2][4];
__device__ float g_outA_sv[2][256];
__device__ float g_outA_sve[2][256];
__device__ float g_outB[2][256];
__device__ __half g_relTh[2][87*72];
__device__ uint32_t g_rvP[2][5632];
// tensor-core operand buffers
__device__ __align__(1024) __half g_xb[(size_t)NPATCH*256*PLANE + 256];
__device__ __align__(1024) __half g_qwh[2][512*256];
__device__ __align__(1024) __half g_qwl[2][512*256];
__device__ __align__(1024) __half g_xc[(size_t)XROWS*256];
__device__ __align__(1024) __half g_wc[9*256*256];

// ---------------- prep ----------------
__global__ void prep_kernel(const float* __restrict__ h_qkv_w, const float* __restrict__ h_bn_qkv,
                            const float* __restrict__ h_bn_sim, const float* __restrict__ h_bn_out,
                            const float* __restrict__ w_qkv_w, const float* __restrict__ w_bn_qkv,
                            const float* __restrict__ w_bn_sim, const float* __restrict__ w_bn_out,
                            const float* __restrict__ conv_w,
                            const float* __restrict__ h_rel, const float* __restrict__ w_rel)
{
    int idx = blockIdx.x * blockDim.x + threadIdx.x;
    const __half zero = __float2half(0.f);

    if (idx < 256*256*9) {
        int co  = idx / 2304;
        int rem = idx - co*2304;
        int ci  = rem / 9;
        int tap = rem - ci*9;
        g_wc[(tap*256 + ci)*256 + co] = __float2half(conv_w[idx]);
    }
    if (idx < MARGIN_LO*256) g_xc[idx] = zero;
    if (idx < 256*256) g_xc[(size_t)(MARGIN_LO + NPATCH*PPX)*256 + idx] = zero;
    // NHWC patch-border zeroing
    for (int z = idx; z < NPATCH*69632; z += 2304*256) {
        int n = z / 69632, e = z - n*69632;
        int py, x, ch;
        if (e < 12288)      { py = 0;  x = e >> 8;              ch = e & 255; }
        else if (e < 24576) { int e2 = e - 12288; py = 45; x = e2 >> 8; ch = e2 & 255; }
        else {
            int e2 = e - 24576;
            py = 1 + (e2 >> 10);
            int r2 = e2 & 1023;
            int xi = r2 >> 8;
            x = (xi == 0) ? 0 : (44 + xi);
            ch = r2 & 255;
        }
        g_xc[((size_t)MARGIN_LO + (size_t)n*PPX + py*48 + x)*256 + ch] = zero;
    }
    if (idx < 2*131072) {
        int ax = idx >> 17;
        int r  = idx & 131071;
        int o  = r & 511;
        int c  = r >> 9;
        const float* bn = ax ? w_bn_qkv : h_bn_qkv;
        const float* W  = ax ? w_qkv_w : h_qkv_w;
        float s = bn[o] * rsqrtf(bn[1536+o] + EPS);
        float wv = W[o*256 + c] * s;
        __half hi = __float2half(wv);
        float lo = wv - __half2float(hi);
        g_qwh[ax][o*256 + c] = hi;
        g_qwl[ax][o*256 + c] = __float2half(lo);
        if (c == 0) g_qkvb[ax][o] = bn[512+o] - bn[1024+o]*s;
    }
    if (idx < 8) {
        int ax = idx >> 2, g = idx & 3;
        const float* bs = ax ? w_bn_sim : h_bn_sim;
        float shsum = 0.f;
        #pragma unroll
        for (int p = 0; p < 3; p++) {
            int ch = p*4 + g;
            float s = bs[ch] * rsqrtf(bs[36+ch] + EPS);
            g_simA[ax][p*4+g] = (p == 0 ? 1.f : 0.1f) * s;
            shsum += bs[12+ch] - bs[24+ch]*s;
        }
        g_simBsum[ax][g] = shsum;
    }
    if (idx < 512) {
        int ax = idx >> 8, cc = idx & 255;
        const float* bo = ax ? w_bn_out : h_bn_out;
        int o1 = 2*cc, o2 = 2*cc + 1;
        float s1 = bo[o1] * rsqrtf(bo[1536+o1] + EPS);
        float s2 = bo[o2] * rsqrtf(bo[1536+o2] + EPS);
        g_outA_sv[ax][cc]  = s1;
        g_outA_sve[ax][cc] = 0.1f * s2;
        g_outB[ax][cc] = (bo[512+o1] - bo[1024+o1]*s1) + (bo[512+o2] - bo[1024+o2]*s2);
    }
    if (idx < 2*87*72) {
        int ax = idx / 6264, r = idx - ax*6264;
        int d = r / 72, c = r - d*72;
        const float* rl = ax ? w_rel : h_rel;
        g_relTh[ax][r] = __float2half(c < 64 ? rl[c*87 + d] : 0.f);
    }
    if (idx < 2*5632) {
        int ax = idx / 5632, r = idx - ax*5632;
        int par = r / 2816, r2 = r - par*2816;
        int dhalf = r2 >> 6, c = r2 & 63;
        const float* rl = ax ? w_rel : h_rel;
        int d0 = 2*dhalf + par;
        float lo = (d0     <= 86) ? rl[(64+c)*87 + 86 - d0]     : 0.f;
        float hi = (d0 + 1 <= 86) ? rl[(64+c)*87 + 86 - d0 - 1] : 0.f;
        __half2 h2v = __halves2half2(__float2half(lo), __float2half(hi));
        g_rvP[ax][par*2816 + dhalf*64 + c] = *reinterpret_cast<uint32_t*>(&h2v);
    }
}

// ---------------- patchify ----------------
__global__ void __launch_bounds__(256,1) patchify_kernel(const float* __restrict__ x)
{
    __shared__ float tile[44*45];
    const int b = blockIdx.x;
    const int np = b >> 8, c = b & 255;
    const int bb_ = np >> 2, i2 = (np >> 1) & 1, j2 = np & 1;
    const float* src = x + ((size_t)(bb_*256 + c)*88 + i2*44)*88 + j2*44;
    float* dp = g_p + (size_t)b*1936;
    const int t = threadIdx.x;
    for (int idx = t; idx < 1936; idx += 256) {
        int y = idx / 44, xq = idx - y*44;
        float v = src[y*88 + xq];
        dp[idx] = v;
        tile[xq*45 + y] = v;
    }
    __syncthreads();
    const size_t base = (size_t)b*1936;
    for (int idx = t; idx < 1936; idx += 256) {
        int r = idx / 44, col = idx - r*44;
        g_xb[base + idx] = __float2half(tile[r*45 + col]);
    }
}

// ---------------- transpose g_t1 [c][x][y] -> fp16 [c][y][x] ----------------
__global__ void __launch_bounds__(256,1) transpose_kernel()
{
    __shared__ float tile[44*45];
    const int b = blockIdx.x;
    const float* src = g_t1 + (size_t)b*1936;
    const int t = threadIdx.x;
    for (int idx = t; idx < 1936; idx += 256) {
        int r = idx / 44, col = idx - r*44;
        tile[col*45 + r] = src[idx];
    }
    __syncthreads();
    const size_t base = (size_t)b*1936;
    for (int idx = t; idx < 1936; idx += 256) {
        int r = idx / 44, col = idx - r*44;
        g_xb[base + idx] = __float2half(tile[r*45 + col]);
    }
}

// ---------------- qkv GEMM v5: fp16 2-pass, fp16 output ----------------
#define QB_A    69632
#define QB_AST  12288
#define QB_ALO  6144
#define GEMM_SMEM (69632 + 2*12288)

__global__ void __launch_bounds__(512,1) qkv_gemm_kernel(int ax)
{
    extern __shared__ char smc[];
    const uint32_t sbase = smem_to_u32(smc);
    const int t = threadIdx.x;
    const int wid = t >> 5, lane = t & 31;
    const int ntile = blockIdx.x;
    const int n     = blockIdx.y;
    const int pxw = ntile * 128;
    const int wm = wid & 1, wn = wid >> 1;
    const __half* qwh = g_qwh[ax];
    const __half* qwl = g_qwl[ax];

    for (int j = t; j < 4096; j += 512) {
        int row = j >> 4, unit = j & 15;
        const __half* g = g_xb + ((size_t)(n*256 + row))*1936 + pxw + unit*8;
        cp16(sbase + row*272 + unit*16, g);
    }
    CP_COMMIT();
    CP_WAIT(0);
    __syncthreads();

    auto load_A = [&](int mtile, int kc, int stage) {
        const int mrow0 = mtile*128;
        const uint32_t sA = sbase + QB_A + stage*QB_AST;
        int o = t;
        int hl   = o & 1;
        int half = (o >> 1) & 1;
        int row  = o >> 2;
        const __half* g = (hl ? qwl : qwh) + (size_t)(mrow0 + row)*256 + kc*16 + half*8;
        cp16(sA + hl*QB_ALO + row*48 + half*16, g);
    };

    for (int mtile = 0; mtile < 4; mtile++) {
        float acc[4][2][4];
        #pragma unroll
        for (int mf = 0; mf < 4; mf++)
            #pragma unroll
            for (int nf = 0; nf < 2; nf++)
                #pragma unroll
                for (int k = 0; k < 4; k++) acc[mf][nf][k] = 0.f;

        load_A(mtile, 0, 0); CP_COMMIT();
        load_A(mtile, 1, 1); CP_COMMIT();

        for (int kc = 0; kc < 16; kc++) {
            const int stage = kc & 1;
            if (kc + 1 < 16) { CP_WAIT(1); }
            else             { CP_WAIT(0); }
            __syncthreads();

            const uint32_t sA = sbase + QB_A + stage*QB_AST;
            uint32_t Ah[4][4], Al[4][4], B[2][2];
            #pragma unroll
            for (int mf = 0; mf < 4; mf++) {
                uint32_t a_off = (wm*64 + mf*16 + (lane & 15))*48 + (lane >> 4)*16;
                ldsm_x4(Ah[mf], sA + a_off);
                ldsm_x4(Al[mf], sA + QB_ALO + a_off);
            }
            #pragma unroll
            for (int nf = 0; nf < 2; nf++) {
                uint32_t b_off = (kc*16 + (lane & 15))*272 + (wn*16 + nf*8)*2;
                ldsm_x2_t(B[nf], sbase + b_off);
            }
            __syncthreads();
            if (kc + 2 < 16) { load_A(mtile, kc+2, stage); CP_COMMIT(); }
            #pragma unroll
            for (int mf = 0; mf < 4; mf++)
                #pragma unroll
                for (int nf = 0; nf < 2; nf++) {
                    mma_f16(acc[mf][nf], Ah[mf], B[nf]);
                    mma_f16(acc[mf][nf], Al[mf], B[nf]);
                }
        }

        const int mrow0 = mtile*128;
        #pragma unroll
        for (int mf = 0; mf < 4; mf++) {
            int row0 = mrow0 + wm*64 + mf*16 + (lane >> 2);
            #pragma unroll
            for (int nf = 0; nf < 2; nf++) {
                int pos = pxw + wn*16 + nf*8 + (lane & 3)*2;
                if (pos < 1936) {
                    float b0 = g_qkvb[ax][row0];
                    float b1 = g_qkvb[ax][row0 + 8];
                    *(__half2*)(g_qkv + ((size_t)n*512 + row0)*1936 + pos) =
                        __floats2half2_rn(acc[mf][nf][0] + b0, acc[mf][nf][1] + b0);
                    *(__half2*)(g_qkv + ((size_t)n*512 + row0 + 8)*1936 + pos) =
                        __floats2half2_rn(acc[mf][nf][2] + b1, acc[mf][nf][3] + b1);
                }
            }
        }
        __syncthreads();
    }
}

// ---------------- fused axial attention (fp16 qkv input) ----------------
#define OFF_V    11440
#define OFF_SIM  22704
#define OFF_RTH  30448
#define OFF_RVP  33580
#define OFF_RES  39212
#define AX_SMEM  (50476*4)

template<int AX>
__global__ void __launch_bounds__(1024,1) axial_kernel()
{
    extern __shared__ float sm[];
    float* qkT  = sm;
    float* vS   = sm + OFF_V;
    float* simS = sm + OFF_SIM;
    const __half* rTh = (const __half*)(sm + OFF_RTH);
    uint32_t* rvS = (uint32_t*)(sm + OFF_RVP);
    float* resS = sm + OFF_RES;

    const int t  = threadIdx.x;
    const int bb = blockIdx.x;
    const int n  = bb / 44;
    const int s  = bb - n*44;

    {
        const __half* qsrc = g_qkv + (size_t)n*512*1936 + s*44;
        for (int idx = t; idx < 5632; idx += 1024) {
            int o = idx / 11, q = idx - o*11;
            uint2 u2 = *(const uint2*)(qsrc + (size_t)o*1936 + q*4);
            float2 va = h2f(u2.x), vb = h2f(u2.y);
            int g = o >> 7, wi = o & 127;
            if (wi < 64) {
                int col = g*64 + wi;
                qkT[(q*4+0)*260 + col] = va.x;
                qkT[(q*4+1)*260 + col] = va.y;
                qkT[(q*4+2)*260 + col] = vb.x;
                qkT[(q*4+3)*260 + col] = vb.y;
            } else {
                float* vd = vS + (g*64 + wi - 64)*44 + q*4;
                vd[0] = va.x; vd[1] = va.y; vd[2] = vb.x; vd[3] = vb.y;
            }
        }
        const uint32_t* rthG = (const uint32_t*)g_relTh[AX];
        uint32_t* rthS = (uint32_t*)(sm + OFF_RTH);
        for (int idx = t; idx < 3132; idx += 1024) rthS[idx] = rthG[idx];
        for (int idx = t; idx < 5632; idx += 1024) rvS[idx] = g_rvP[AX][idx];
        if (AX == 1) {
            const float4* rsrc = (const float4*)(g_p + (size_t)n*IMGSZ + s*44);
            float4* rd = (float4*)resS;
            for (int idx = t; idx < 2816; idx += 1024) {
                int ch = idx / 11, q = idx - ch*11;
                rd[idx] = rsrc[ch*484 + q];
            }
        }
    }
    __syncthreads();

    // sim: thread handles (i,j) for a group PAIR
    for (int e2 = t; e2 < 3872; e2 += 1024) {
        int gp = e2 / 1936;
        int r = e2 - gp*1936;
        int i = r / 44;
        int j = r - i*44;
        const uint4* rq = (const uint4*)(rTh + (i - j + 43)*72);
        const uint4* rk = (const uint4*)(rTh + (j - i + 43)*72 + 32);
        float2 qk2[2], qr2[2], kr2[2];
        #pragma unroll
        for (int gg = 0; gg < 2; gg++) {
            qk2[gg] = make_float2(0.f, 0.f);
            qr2[gg] = make_float2(0.f, 0.f);
            kr2[gg] = make_float2(0.f, 0.f);
        }
        #pragma unroll
        for (int cc = 0; cc < 4; cc++) {
            uint4 rqu = rq[cc], rku = rk[cc];
            float2 rq0 = h2f(rqu.x), rq1 = h2f(rqu.y), rq2 = h2f(rqu.z), rq3 = h2f(rqu.w);
            float2 rk0 = h2f(rku.x), rk1 = h2f(rku.y), rk2 = h2f(rku.z), rk3 = h2f(rku.w);
            #pragma unroll
            for (int gg = 0; gg < 2; gg++) {
                int g = gp*2 + gg;
                const float4* qp = (const float4*)(qkT + i*260 + g*64) + 2*cc;
                const float4* kp = (const float4*)(qkT + j*260 + g*64 + 32) + 2*cc;
                float4 q4a = qp[0], q4b = qp[1];
                float4 k4a = kp[0], k4b = kp[1];
                fma2(qk2[gg], make_float2(q4a.x,q4a.y), make_float2(k4a.x,k4a.y));
                fma2(qk2[gg], make_float2(q4a.z,q4a.w), make_float2(k4a.z,k4a.w));
                fma2(qk2[gg], make_float2(q4b.x,q4b.y), make_float2(k4b.x,k4b.y));
                fma2(qk2[gg], make_float2(q4b.z,q4b.w), make_float2(k4b.z,k4b.w));
                fma2(qr2[gg], make_float2(q4a.x,q4a.y), rq0);
                fma2(qr2[gg], make_float2(q4a.z,q4a.w), rq1);
                fma2(qr2[gg], make_float2(q4b.x,q4b.y), rq2);
                fma2(qr2[gg], make_float2(q4b.z,q4b.w), rq3);
                fma2(kr2[gg], make_float2(k4a.x,k4a.y), rk0);
                fma2(kr2[gg], make_float2(k4a.z,k4a.w), rk1);
                fma2(kr2[gg], make_float2(k4b.x,k4b.y), rk2);
                fma2(kr2[gg], make_float2(k4b.z,k4b.w), rk3);
            }
        }
        #pragma unroll
        for (int gg = 0; gg < 2; gg++) {
            int g = gp*2 + gg;
            float qk = qk2[gg].x + qk2[gg].y;
            float qr = qr2[gg].x + qr2[gg].y;
            float kr = kr2[gg].x + kr2[gg].y;
            simS[g*1936 + r] = g_simA[AX][g]*qk + g_simA[AX][4+g]*qr + g_simA[AX][8+g]*kr + g_simBsum[AX][g];
        }
    }
    __syncthreads();

    // softmax: warp per row
    {
        const int wid = t >> 5, lane = t & 31;
        #pragma unroll
        for (int k = 0; k < 6; k++) {
            int r = wid + 32*k;
            if (r < 176) {
                float* row = simS + (r/44)*1936 + (r - (r/44)*44)*44;
                float v1 = row[lane];
                float v2 = (lane < 12) ? row[lane+32] : -1e30f;
                float m = fmaxf(v1, v2);
                #pragma unroll
                for (int off = 16; off; off >>= 1) m = fmaxf(m, __shfl_xor_sync(0xffffffffu, m, off));
                float e1 = __expf(v1 - m);
                float e2 = (lane < 12) ? __expf(v2 - m) : 0.f;
                float su = e1 + e2;
                #pragma unroll
                for (int off = 16; off; off >>= 1) su += __shfl_xor_sync(0xffffffffu, su, off);
                float inv = 1.f / su;
                row[lane] = e1 * inv;
                if (lane < 12) row[lane+32] = e2 * inv;
            }
        }
    }
    __syncthreads();

    // output
    {
        const int ch = t & 255, qtr = t >> 8;
        const int g = ch >> 6, c = ch & 63;
        float2 v2[22];
        const float4* vp = (const float4*)(vS + ch*44);
        #pragma unroll
        for (int q = 0; q < 11; q++) {
            float4 v4 = vp[q];
            v2[2*q]   = make_float2(v4.x, v4.y);
            v2[2*q+1] = make_float2(v4.z, v4.w);
        }
        const float aSV  = g_outA_sv[AX][ch];
        const float aSVE = g_outA_sve[AX][ch];
        const float bO   = g_outB[AX][ch];
        #pragma unroll 1
        for (int ii = 0; ii < 11; ii++) {
            int i = qtr*11 + ii;
            const float2* sr2 = (const float2*)(simS + g*1936 + i*44);
            int b0 = 43 - i;
            const uint32_t* wrow = rvS + (b0 & 1)*2816 + (b0 >> 1)*64 + c;
            float2 sv2 = make_float2(0.f, 0.f), sve2 = make_float2(0.f, 0.f);
            #pragma unroll
            for (int p = 0; p < 22; p++) {
                float2 s2 = sr2[p];
                fma2(sv2, s2, v2[p]);
                fma2(sve2, s2, h2f(wrow[p*64]));
            }
            float val = fmaf(aSV, sv2.x + sv2.y, fmaf(aSVE, sve2.x + sve2.y, bO));
            if (AX == 0) {
                qkT[ch*44 + i] = val;
            } else {
                qkT[i*256 + ch] = val + resS[ch*44 + i];
            }
        }
    }
    __syncthreads();
    if (AX == 0) {
        float* out = g_t1;
        const float4* st4 = (const float4*)qkT;
        for (int idx = t; idx < 2816; idx += 1024) {
            int ch = idx / 11, q = idx - ch*11;
            *(float4*)(out + ((size_t)(n*256 + ch))*1936 + s*44 + q*4) = st4[idx];
        }
    } else {
        const size_t rowbase = ((size_t)MARGIN_LO + (size_t)n*PPX + (size_t)(s+1)*48 + 1)*256;
        for (int idx = t; idx < 11264; idx += 1024) {
            int i = idx >> 8, ch = idx & 255;
            g_xc[rowbase + (size_t)i*256 + ch] = __float2half(qkT[i*256 + ch]);
        }
    }
}

// ---------------- tensor-core conv3x3 v3: fp16 single-pass ----------------
#define C3STAGE 14592
#define C3_B    6144
#define CONV_SMEM (3*C3STAGE + 1024)

__global__ void __launch_bounds__(512,1) conv_mma_kernel(const float* __restrict__ conv_b,
                                                         float* __restrict__ out)
{
    extern __shared__ char smc[];
    const uint32_t sbase = smem_to_u32(smc);
    const int t = threadIdx.x;
    const int wid = t >> 5, lane = t & 31;
    const int bb = blockIdx.x;
    const int n = bb / 18;
    const int widx = bb - n*18;
    const int pxw = widx * 128;
    const int wm = wid & 1, wn = wid >> 1;

    float* biasS = (float*)(smc + 3*C3STAGE);
    if (t < 256) biasS[t] = conv_b[t];

    const long long arow0 = (long long)MARGIN_LO + (long long)n*PPX + pxw;

    auto load_chunk = [&](int kc, int stage) {
        const int tap = kc >> 4, sub = kc & 15;
        const int offr = (tap/3 - 1)*48 + (tap%3 - 1);
        const long long abase = arow0 + offr;
        const uint32_t sA = sbase + stage*C3STAGE;
        const uint32_t sB = sA + C3_B;
        #pragma unroll
        for (int i = 0; i < 2; i++) {
            int o = t + 512*i;
            if (o < 256) {
                int half = o & 1;
                int row  = o >> 1;
                const __half* g = g_xc + ((size_t)(abase + row))*256 + sub*16 + half*8;
                cp16(sA + row*48 + half*16, g);
            } else if (o < 768) {
                int o2 = o - 256;
                int krow = o2 >> 5, unit = o2 & 31;
                const __half* g = g_wc + ((size_t)(tap*256 + sub*16 + krow))*256 + unit*8;
                cp16(sB + krow*528 + unit*16, g);
            }
        }
    };

    float acc[4][4][4];
    #pragma unroll
    for (int mf = 0; mf < 4; mf++)
        #pragma unroll
        for (int nf = 0; nf < 4; nf++)
            #pragma unroll
            for (int k = 0; k < 4; k++) acc[mf][nf][k] = 0.f;

    load_chunk(0, 0); CP_COMMIT();
    load_chunk(1, 1); CP_COMMIT();

    for (int kc = 0; kc < 144; kc++) {
        const int stage = kc % 3;
        if (kc + 2 < 144) { load_chunk(kc+2, (kc+2)%3); CP_COMMIT(); CP_WAIT(2); }
        else if (kc + 1 < 144) { CP_WAIT(1); }
        else { CP_WAIT(0); }
        __syncthreads();

        const uint32_t sA = sbase + stage*C3STAGE;
        const uint32_t sB = sA + C3_B;

        uint32_t A[4][4], B[4][2];
        #pragma unroll
        for (int mf = 0; mf < 4; mf++) {
            uint32_t a_off = (wm*64 + mf*16 + (lane & 15))*48 + (lane >> 4)*16;
            ldsm_x4(A[mf], sA + a_off);
        }
        #pragma unroll
        for (int nf = 0; nf < 4; nf++) {
            uint32_t b_off = (lane & 15)*528 + (wn*32 + nf*8)*2;
            ldsm_x2_t(B[nf], sB + b_off);
        }
        #pragma unroll
        for (int mf = 0; mf < 4; mf++)
            #pragma unroll
            for (int nf = 0; nf < 4; nf++)
                mma_f16(acc[mf][nf], A[mf], B[nf]);
        __syncthreads();
    }

    const int b_ = n >> 2, i2 = (n >> 1) & 1, j2 = n & 1;
    #pragma unroll
    for (int mf = 0; mf < 4; mf++) {
        #pragma unroll
        for (int half = 0; half < 2; half++) {
            int px = pxw + wm*64 + mf*16 + (lane >> 2) + half*8;
            int py = px / 48, pxx = px - py*48;
            bool valid = (py >= 1 && py <= 44) && (pxx >= 1 && pxx <= 44);
            if (!valid) continue;
            size_t ob = ((size_t)(b_*256))*7744 + (size_t)(i2*44 + (py-1))*88 + j2*44 + (pxx-1);
            #pragma unroll
            for (int nf = 0; nf < 4; nf++) {
                int co = wn*32 + nf*8 + (lane & 3)*2;
                out[ob + (size_t)co*7744]     = acc[mf][nf][half*2+0] + biasS[co];
                out[ob + (size_t)(co+1)*7744] = acc[mf][nf][half*2+1] + biasS[co+1];
            }
        }
    }
}

// ---------------- launch ----------------
extern "C" void kernel_launch(void* const* d_in, const int* in_sizes, int n_in,
                              void* d_out, int out_size)
{
    const float* x        = (const float*)d_in[0];
    const float* h_qkv_w  = (const float*)d_in[1];
    const float* h_bn_qkv = (const float*)d_in[2];
    const float* h_bn_sim = (const float*)d_in[3];
    const float* h_bn_out = (const float*)d_in[4];
    const float* h_rel    = (const float*)d_in[5];
    const float* w_qkv_w  = (const float*)d_in[6];
    const float* w_bn_qkv = (const float*)d_in[7];
    const float* w_bn_sim = (const float*)d_in[8];
    const float* w_bn_out = (const float*)d_in[9];
    const float* w_rel    = (const float*)d_in[10];
    const float* conv_w   = (const float*)d_in[11];
    const float* conv_b   = (const float*)d_in[12];
    float* out = (float*)d_out;

    cudaFuncSetAttribute(axial_kernel<0>,  cudaFuncAttributeMaxDynamicSharedMemorySize, AX_SMEM);
    cudaFuncSetAttribute(axial_kernel<1>,  cudaFuncAttributeMaxDynamicSharedMemorySize, AX_SMEM);
    cudaFuncSetAttribute(qkv_gemm_kernel,  cudaFuncAttributeMaxDynamicSharedMemorySize, GEMM_SMEM);
    cudaFuncSetAttribute(conv_mma_kernel,  cudaFuncAttributeMaxDynamicSharedMemorySize, CONV_SMEM);

    prep_kernel<<<(256*256*9 + 255)/256, 256>>>(h_qkv_w, h_bn_qkv, h_bn_sim, h_bn_out,
                                                w_qkv_w, w_bn_qkv, w_bn_sim, w_bn_out,
                                                conv_w, h_rel, w_rel);
    patchify_kernel<<<NPATCH*256, 256>>>(x);
    qkv_gemm_kernel<<<dim3(16,NPATCH), 512, GEMM_SMEM>>>(0);
    axial_kernel<0><<<NB, 1024, AX_SMEM>>>();
    transpose_kernel<<<NPATCH*256, 256>>>();
    qkv_gemm_kernel<<<dim3(16,NPATCH), 512, GEMM_SMEM>>>(1);
    axial_kernel<1><<<NB, 1024, AX_SMEM>>>();
    conv_mma_kernel<<<NPATCH*18, 512, CONV_SMEM>>>(conv_b, out);
}